// round 1
// baseline (speedup 1.0000x reference)
#include <cuda_runtime.h>
#include <math.h>

#define NS   2
#define BSZ  4
#define LSEQ 1024
#define NTOK 4096
#define DM   512
#define DI   1024
#define DS   16
#define CIN  256

// ---------------- scratch (static device globals; no runtime alloc) ----------------
__device__ float d_xt[NS][NTOK * CIN];        // transposed inputs (token-major)
__device__ float d_seq[NS][NTOK * DM];        // post conv_red+bn+relu, (b,l,d)
__device__ float d_pooled[NS][BSZ * DM];
__device__ float d_lam[BSZ * 2];
__device__ float d_xn[NS][NTOK * DM];         // layernormed
__device__ float d_xp[NS][NTOK * 2 * DI];     // in_proj out: [x_ssm | gate]
__device__ float d_y[NS][4][NTOK * DI];       // 4 = variant*2 + dir
__device__ float d_u[NS][NTOK * DI];          // gated, lambda-combined
__device__ float d_outp[NS][NTOK * DM];       // out_proj
__device__ float d_res[NS][NTOK * CIN];       // conv_res

// ---------------- transpose (B,C,HW) -> (B,HW,C) ----------------
__global__ void transpose_in(const float* __restrict__ x0, const float* __restrict__ x1) {
    __shared__ float tile[32][33];
    int s  = blockIdx.z >> 2;
    int b  = blockIdx.z & 3;
    const float* x = s ? x1 : x0;
    int hw0 = blockIdx.x * 32, c0 = blockIdx.y * 32;
    int tx = threadIdx.x, ty = threadIdx.y;
    tile[ty][tx] = x[((size_t)b * CIN + (c0 + ty)) * LSEQ + hw0 + tx];
    __syncthreads();
    d_xt[s][((size_t)b * LSEQ + hw0 + ty) * CIN + c0 + tx] = tile[tx][ty];
}

// ---------------- SGEMM: C[M,N] = A[M,K] * B[N,K]^T, 64x64x16 tiles ----------------
// EPI: 0 = plain store, 1 = per-column BN + ReLU
template <int EPI>
__global__ void sgemm(const float* __restrict__ A, const float* __restrict__ Bm,
                      float* __restrict__ C, int M, int N, int K,
                      const float* __restrict__ eg, const float* __restrict__ eb,
                      const float* __restrict__ em, const float* __restrict__ ev) {
    __shared__ __align__(16) float As[16][68];
    __shared__ __align__(16) float Bs[16][68];
    int tid = threadIdx.x;              // 256 threads
    int tx = tid & 15, ty = tid >> 4;
    int m0 = blockIdx.y * 64, n0 = blockIdx.x * 64;

    int lm = tid >> 2;                  // 0..63
    int lk = (tid & 3) * 4;             // 0,4,8,12
    const float* Aptr = A + (size_t)(m0 + lm) * K + lk;
    const float* Bptr = Bm + (size_t)(n0 + lm) * K + lk;

    float acc[4][4] = {};

    for (int k0 = 0; k0 < K; k0 += 16) {
        float4 av = *(const float4*)(Aptr + k0);
        float4 bv = *(const float4*)(Bptr + k0);
        As[lk + 0][lm] = av.x; As[lk + 1][lm] = av.y;
        As[lk + 2][lm] = av.z; As[lk + 3][lm] = av.w;
        Bs[lk + 0][lm] = bv.x; Bs[lk + 1][lm] = bv.y;
        Bs[lk + 2][lm] = bv.z; Bs[lk + 3][lm] = bv.w;
        __syncthreads();
#pragma unroll
        for (int kk = 0; kk < 16; kk++) {
            float4 a = *(const float4*)&As[kk][ty * 4];
            float4 b = *(const float4*)&Bs[kk][tx * 4];
            acc[0][0] += a.x * b.x; acc[0][1] += a.x * b.y; acc[0][2] += a.x * b.z; acc[0][3] += a.x * b.w;
            acc[1][0] += a.y * b.x; acc[1][1] += a.y * b.y; acc[1][2] += a.y * b.z; acc[1][3] += a.y * b.w;
            acc[2][0] += a.z * b.x; acc[2][1] += a.z * b.y; acc[2][2] += a.z * b.z; acc[2][3] += a.z * b.w;
            acc[3][0] += a.w * b.x; acc[3][1] += a.w * b.y; acc[3][2] += a.w * b.z; acc[3][3] += a.w * b.w;
        }
        __syncthreads();
    }

    int row = m0 + ty * 4;
    int col = n0 + tx * 4;
    if (EPI == 1) {
        float sc[4], sh[4];
#pragma unroll
        for (int j = 0; j < 4; j++) {
            sc[j] = eg[col + j] * rsqrtf(ev[col + j] + 1e-5f);
            sh[j] = eb[col + j] - em[col + j] * sc[j];
        }
#pragma unroll
        for (int i = 0; i < 4; i++)
#pragma unroll
            for (int j = 0; j < 4; j++)
                C[(size_t)(row + i) * N + col + j] = fmaxf(acc[i][j] * sc[j] + sh[j], 0.0f);
    } else {
#pragma unroll
        for (int i = 0; i < 4; i++) {
            float4 o; o.x = acc[i][0]; o.y = acc[i][1]; o.z = acc[i][2]; o.w = acc[i][3];
            *(float4*)&C[(size_t)(row + i) * N + col] = o;
        }
    }
}

// ---------------- global-avg-pool over L per (s,b,d) ----------------
__global__ void pool_kernel() {
    int s = blockIdx.x >> 2;
    int b = blockIdx.x & 3;
    int d = threadIdx.x;                // 512 threads
    const float* p = d_seq[s] + (size_t)b * LSEQ * DM + d;
    float acc = 0.f;
#pragma unroll 4
    for (int l = 0; l < LSEQ; l++) acc += p[(size_t)l * DM];
    d_pooled[s][b * DM + d] = acc * (1.0f / LSEQ);
}

// ---------------- lambda predictor (4 blocks x 128 threads) ----------------
__global__ void lambda_kernel(const float* __restrict__ w1, const float* __restrict__ b1,
                              const float* __restrict__ w2, const float* __restrict__ b2) {
    int b = blockIdx.x, j = threadIdx.x;
    const float* pV = d_pooled[0] + b * DM;
    const float* pI = d_pooled[1] + b * DM;
    const float* w = w1 + (size_t)j * (2 * DM);
    float acc = b1[j];
    for (int c = 0; c < DM; c++) acc += pV[c] * w[c];
    for (int c = 0; c < DM; c++) acc += pI[c] * w[DM + c];
    __shared__ float h1[128];
    h1[j] = fmaxf(acc, 0.f);
    __syncthreads();
    if (j == 0) {
        float l0 = b2[0], l1 = b2[1];
        for (int c = 0; c < 128; c++) { l0 += h1[c] * w2[c]; l1 += h1[c] * w2[128 + c]; }
        float mx = fmaxf(l0, l1);
        float e0 = expf(l0 - mx), e1 = expf(l1 - mx);
        float inv = 1.f / (e0 + e1);
        d_lam[b * 2 + 0] = e0 * inv;
        d_lam[b * 2 + 1] = e1 * inv;
    }
}

// ---------------- LayerNorm over D=512 (block per token, 128 thr x float4) ----------------
__global__ void ln_kernel(int s, const float* __restrict__ g, const float* __restrict__ b) {
    int n = blockIdx.x, t = threadIdx.x;
    float4 v = ((const float4*)(d_seq[s] + (size_t)n * DM))[t];
    float sm = v.x + v.y + v.z + v.w;
    float sq = v.x * v.x + v.y * v.y + v.z * v.z + v.w * v.w;
#pragma unroll
    for (int o = 16; o; o >>= 1) {
        sm += __shfl_xor_sync(0xffffffffu, sm, o);
        sq += __shfl_xor_sync(0xffffffffu, sq, o);
    }
    __shared__ float ss[4], sqs[4];
    int w = t >> 5, ln = t & 31;
    if (ln == 0) { ss[w] = sm; sqs[w] = sq; }
    __syncthreads();
    sm = ss[0] + ss[1] + ss[2] + ss[3];
    sq = sqs[0] + sqs[1] + sqs[2] + sqs[3];
    float mu = sm * (1.f / DM);
    float var = sq * (1.f / DM) - mu * mu;
    float inv = rsqrtf(var + 1e-5f);
    float4 gg = ((const float4*)g)[t];
    float4 bb = ((const float4*)b)[t];
    float4 o4;
    o4.x = (v.x - mu) * inv * gg.x + bb.x;
    o4.y = (v.y - mu) * inv * gg.y + bb.y;
    o4.z = (v.z - mu) * inv * gg.z + bb.z;
    o4.w = (v.w - mu) * inv * gg.w + bb.w;
    ((float4*)(d_xn[s] + (size_t)n * DM))[t] = o4;
}

// ---------------- SSM scan: one thread per (stream,variant,dir,b,i) chain ----------------
__global__ void scan_kernel(const float* __restrict__ VA, const float* __restrict__ VB,
                            const float* __restrict__ VC, const float* __restrict__ IA,
                            const float* __restrict__ IB, const float* __restrict__ IC) {
    int idx = blockIdx.x * 256 + threadIdx.x;   // 32768 total
    int i    = idx & 1023;
    int rest = idx >> 10;
    int b    = rest & 3;
    int dir  = (rest >> 2) & 1;
    int var  = (rest >> 3) & 1;
    int s    = (rest >> 4) & 1;

    const float* Alog = s ? IA : VA;
    const float* Bp   = (s ^ var) ? IB : VB;    // std uses own B, cross uses other's B
    const float* Cp   = s ? IC : VC;

    float A[DS], Bm[DS], Cm[DS], h[DS];
#pragma unroll
    for (int k = 0; k < DS; k++) {
        A[k]  = fminf(fmaxf(-expf(Alog[i * DS + k]), -10.f), -0.01f);
        Bm[k] = Bp[i * DS + k];
        Cm[k] = Cp[i * DS + k];
        h[k]  = 0.f;
    }

    const float* xs = d_xp[s] + (size_t)b * LSEQ * (2 * DI) + i;
    float* yo = d_y[s][var * 2 + dir] + (size_t)b * LSEQ * DI + i;
    int t  = dir ? (LSEQ - 1) : 0;
    int dt = dir ? -1 : 1;

    for (int step = 0; step < LSEQ; step++, t += dt) {
        float x = xs[(size_t)t * (2 * DI)];
        float y = 0.f;
#pragma unroll
        for (int k = 0; k < DS; k++) {
            h[k] = fminf(fmaxf(fmaf(h[k], A[k], x * Bm[k]), -10.f), 10.f);
            y = fmaf(h[k], Cm[k], y);
        }
        yo[(size_t)t * DI] = y;
    }
}

// ---------------- gated lambda-combine: u = silu(gate) * (w0*(y0+y1) + w1*(y2+y3)) ----------------
__global__ void gated_combine() {
    int idx = blockIdx.x * 256 + threadIdx.x;   // 4M per stream
    int s = blockIdx.y;
    int i = idx & 1023;
    int n = idx >> 10;
    int b = n >> 10;
    float w0 = 0.5f * d_lam[b * 2 + 0];
    float w1 = 0.5f * d_lam[b * 2 + 1];
    float g = d_xp[s][(size_t)n * (2 * DI) + DI + i];
    float sig = 1.f / (1.f + expf(-g));
    float y = w0 * (d_y[s][0][idx] + d_y[s][1][idx]) +
              w1 * (d_y[s][2][idx] + d_y[s][3][idx]);
    d_u[s][idx] = y * g * sig;
}

// ---------------- final: transpose + BN + residual + sigmoid(gate) ----------------
__global__ void final_kernel(const float* __restrict__ x0, const float* __restrict__ x1,
                             float* __restrict__ out,
                             const float* __restrict__ g, const float* __restrict__ bb,
                             const float* __restrict__ m, const float* __restrict__ v,
                             const float* __restrict__ gatep) {
    __shared__ float tile[32][33];
    int s = blockIdx.z >> 2;
    int b = blockIdx.z & 3;
    int hw0 = blockIdx.x * 32, o0 = blockIdx.y * 32;
    int tx = threadIdx.x, ty = threadIdx.y;
    tile[ty][tx] = d_res[s][((size_t)b * LSEQ + hw0 + ty) * CIN + o0 + tx];
    __syncthreads();
    int o = o0 + ty, hw = hw0 + tx;
    float sc = g[o] * rsqrtf(v[o] + 1e-5f);
    float sh = bb[o] - m[o] * sc;
    float sg = 1.f / (1.f + expf(-gatep[0]));
    const float* xin = s ? x1 : x0;
    size_t pos = ((size_t)b * CIN + o) * LSEQ + hw;
    float val = tile[tx][ty] * sc + sh;
    out[(size_t)s * BSZ * CIN * LSEQ + pos] = xin[pos] + sg * val;
}

// ---------------- launch ----------------
extern "C" void kernel_launch(void* const* d_in, const int* in_sizes, int n_in,
                              void* d_out, int out_size) {
    const float* x_V        = (const float*)d_in[0];
    const float* x_I        = (const float*)d_in[1];
    const float* conv_red_w = (const float*)d_in[2];
    const float* bn_red_g   = (const float*)d_in[3];
    const float* bn_red_b   = (const float*)d_in[4];
    const float* bn_red_m   = (const float*)d_in[5];
    const float* bn_red_v   = (const float*)d_in[6];
    const float* conv_res_w = (const float*)d_in[7];
    const float* bn_res_g   = (const float*)d_in[8];
    const float* bn_res_b   = (const float*)d_in[9];
    const float* bn_res_m   = (const float*)d_in[10];
    const float* bn_res_v   = (const float*)d_in[11];
    const float* lam_w1     = (const float*)d_in[12];
    const float* lam_b1     = (const float*)d_in[13];
    const float* lam_w2     = (const float*)d_in[14];
    const float* lam_b2     = (const float*)d_in[15];
    const float* in_w[2]    = {(const float*)d_in[16], (const float*)d_in[23]};
    const float* out_w[2]   = {(const float*)d_in[17], (const float*)d_in[24]};
    const float* A_log[2]   = {(const float*)d_in[18], (const float*)d_in[25]};
    const float* Bmat[2]    = {(const float*)d_in[19], (const float*)d_in[26]};
    const float* Cmat[2]    = {(const float*)d_in[20], (const float*)d_in[27]};
    const float* ln_g[2]    = {(const float*)d_in[21], (const float*)d_in[28]};
    const float* ln_b[2]    = {(const float*)d_in[22], (const float*)d_in[29]};
    const float* gate       = (const float*)d_in[30];

    float *XT, *SEQ, *XN, *XP, *U, *OUTP, *RES;
    cudaGetSymbolAddress((void**)&XT,   d_xt);
    cudaGetSymbolAddress((void**)&SEQ,  d_seq);
    cudaGetSymbolAddress((void**)&XN,   d_xn);
    cudaGetSymbolAddress((void**)&XP,   d_xp);
    cudaGetSymbolAddress((void**)&U,    d_u);
    cudaGetSymbolAddress((void**)&OUTP, d_outp);
    cudaGetSymbolAddress((void**)&RES,  d_res);

    dim3 tb32(32, 32);

    // 1. transpose inputs to token-major
    transpose_in<<<dim3(32, 8, 8), tb32>>>(x_V, x_I);

    // 2. conv_red + BN + ReLU -> seq
    for (int s = 0; s < 2; s++)
        sgemm<1><<<dim3(DM / 64, NTOK / 64), 256>>>(
            XT + (size_t)s * NTOK * CIN, conv_red_w, SEQ + (size_t)s * NTOK * DM,
            NTOK, DM, CIN, bn_red_g, bn_red_b, bn_red_m, bn_red_v);

    // 3. pooled means, 4. lambda
    pool_kernel<<<8, 512>>>();
    lambda_kernel<<<4, 128>>>(lam_w1, lam_b1, lam_w2, lam_b2);

    // 5. layernorm, 6. in_proj
    for (int s = 0; s < 2; s++) {
        ln_kernel<<<NTOK, 128>>>(s, ln_g[s], ln_b[s]);
        sgemm<0><<<dim3(2 * DI / 64, NTOK / 64), 256>>>(
            XN + (size_t)s * NTOK * DM, in_w[s], XP + (size_t)s * NTOK * 2 * DI,
            NTOK, 2 * DI, DM, nullptr, nullptr, nullptr, nullptr);
    }

    // 7. all 8 scans in one launch
    scan_kernel<<<128, 256>>>(A_log[0], Bmat[0], Cmat[0], A_log[1], Bmat[1], Cmat[1]);

    // 8. gated lambda combine
    gated_combine<<<dim3(NTOK * DI / 256, 2), 256>>>();

    // 9. out_proj, 10. conv_res
    for (int s = 0; s < 2; s++) {
        sgemm<0><<<dim3(DM / 64, NTOK / 64), 256>>>(
            U + (size_t)s * NTOK * DI, out_w[s], OUTP + (size_t)s * NTOK * DM,
            NTOK, DM, DI, nullptr, nullptr, nullptr, nullptr);
        sgemm<0><<<dim3(CIN / 64, NTOK / 64), 256>>>(
            OUTP + (size_t)s * NTOK * DM, conv_res_w, RES + (size_t)s * NTOK * CIN,
            NTOK, CIN, DM, nullptr, nullptr, nullptr, nullptr);
    }

    // 11. BN + residual + gate -> output (both tensors concatenated)
    final_kernel<<<dim3(32, 8, 8), tb32>>>(x_V, x_I, (float*)d_out,
                                           bn_res_g, bn_res_b, bn_res_m, bn_res_v, gate);
}

// round 2
// speedup vs baseline: 1.2417x; 1.2417x over previous
#include <cuda_runtime.h>
#include <math.h>

#define NS   2
#define BSZ  4
#define LSEQ 1024
#define NTOK 4096
#define DM   512
#define DI   1024
#define DS   16
#define CIN  256

// ---------------- scratch (static device globals; no runtime alloc) ----------------
__device__ float d_seq[NS][NTOK * DM];
__device__ float d_ppart[NS][16][BSZ * DM];
__device__ float d_pooled[NS][BSZ * DM];
__device__ float d_lam[BSZ * 2];
__device__ float d_xn[NS][NTOK * DM];
__device__ float d_xp[NS][NTOK * 2 * DI];
__device__ float d_y2[NS][2][NTOK * DI];
__device__ float d_u[NS][NTOK * DI];
__device__ float d_res[NS][NTOK * CIN];
__device__ float d_wc[NS][CIN * DI];          // per-stream fused weight

// ---------------- packed fp32x2 FMA (FFMA2) ----------------
__device__ __forceinline__ unsigned long long ffma2(unsigned long long a,
                                                    unsigned long long b,
                                                    unsigned long long c) {
    unsigned long long d;
    asm("fma.rn.f32x2 %0, %1, %2, %3;" : "=l"(d) : "l"(a), "l"(b), "l"(c));
    return d;
}
union F2U { unsigned long long u; float2 f; };

// ---------------- GEMM: C[M,N] = A * B^T, 128xTN tiles, double-buffered, FFMA2 ----------------
template <int TN, int EPI, int TRA, int TRB>
__global__ void __launch_bounds__(256, 2)
gemm_kernel(const float* __restrict__ A0, const float* __restrict__ A1,
            const float* __restrict__ B0, const float* __restrict__ B1,
            float* __restrict__ C, int M, int N, int K, long long sCz,
            const float* __restrict__ eg, const float* __restrict__ eb,
            const float* __restrict__ em, const float* __restrict__ ev) {
    __shared__ __align__(16) float As2[2][8][264];
    __shared__ __align__(16) float Bs[2][8][TN + 4];

    const int tid = threadIdx.x;
    const int z = blockIdx.z;
    const float* __restrict__ A = z ? A1 : A0;
    const float* __restrict__ B = z ? B1 : B0;
    float* Cz = C + (size_t)z * sCz;
    const int n0 = blockIdx.x * TN;
    const int m0 = blockIdx.y * 128;

    int amA = 0, akA, amq = 0;
    if (TRA == 0) { amA = tid >> 1; akA = (tid & 1) * 4; }
    else          { akA = tid >> 5; amq = (tid & 31) * 4; }
    int bnB = 0, bkB = 0, bnq = 0;
    if (TRB == 0) { bnB = tid >> 1; bkB = (tid & 1) * 4; }
    else if (TN == 128) { bkB = tid >> 5; bnq = (tid & 31) * 4; }
    else                { bkB = tid >> 4; bnq = (tid & 15) * 4; }
    const bool bact = (TN == 128) || (tid < 128);

    float4 va, vb;
    auto LDG = [&](int t) {
        const int k0 = t * 8;
        if (TRA == 0) {
            va = *(const float4*)(A + (size_t)(m0 + amA) * K + k0 + akA);
        } else {
            int m = m0 + amq;
            va = *(const float4*)(A + ((size_t)(m >> 10) * CIN + k0 + akA) * LSEQ + (m & 1023));
        }
        if (bact) {
            if (TRB == 0) vb = *(const float4*)(B + (size_t)(n0 + bnB) * K + k0 + bkB);
            else          vb = *(const float4*)(B + (size_t)(k0 + bkB) * N + n0 + bnq);
        }
    };
    auto STS = [&](int buf) {
        if (TRA == 0) {
            *(float2*)&As2[buf][akA + 0][2 * amA] = make_float2(va.x, va.x);
            *(float2*)&As2[buf][akA + 1][2 * amA] = make_float2(va.y, va.y);
            *(float2*)&As2[buf][akA + 2][2 * amA] = make_float2(va.z, va.z);
            *(float2*)&As2[buf][akA + 3][2 * amA] = make_float2(va.w, va.w);
        } else {
            *(float4*)&As2[buf][akA][2 * amq]     = make_float4(va.x, va.x, va.y, va.y);
            *(float4*)&As2[buf][akA][2 * amq + 4] = make_float4(va.z, va.z, va.w, va.w);
        }
        if (bact) {
            if (TRB == 0) {
                Bs[buf][bkB + 0][bnB] = vb.x;
                Bs[buf][bkB + 1][bnB] = vb.y;
                Bs[buf][bkB + 2][bnB] = vb.z;
                Bs[buf][bkB + 3][bnB] = vb.w;
            } else {
                *(float4*)&Bs[buf][bkB][bnq] = vb;
            }
        }
    };

    const int ty = tid >> 4, tx = tid & 15;
    const int row0 = ty * 8;
    const int col0 = tx * (TN == 128 ? 8 : 4);
    constexpr int NP = (TN == 128) ? 4 : 2;
    unsigned long long acc[8][NP];
#pragma unroll
    for (int i = 0; i < 8; i++)
#pragma unroll
        for (int j = 0; j < NP; j++) acc[i][j] = 0ull;

    const int T = K >> 3;
    LDG(0); STS(0); __syncthreads();
    for (int t = 0; t < T; t++) {
        if (t + 1 < T) LDG(t + 1);
        const int buf = t & 1;
#pragma unroll
        for (int kk = 0; kk < 8; kk++) {
            const ulonglong2* ap = (const ulonglong2*)&As2[buf][kk][2 * row0];
            ulonglong2 a01 = ap[0], a23 = ap[1], a45 = ap[2], a67 = ap[3];
            unsigned long long a[8] = {a01.x, a01.y, a23.x, a23.y,
                                       a45.x, a45.y, a67.x, a67.y};
            const ulonglong2* bp = (const ulonglong2*)&Bs[buf][kk][col0];
            unsigned long long b[NP];
            { ulonglong2 b01 = bp[0]; b[0] = b01.x; b[1] = b01.y; }
            if constexpr (NP == 4) { ulonglong2 b23 = bp[1]; b[2] = b23.x; b[3] = b23.y; }
#pragma unroll
            for (int i = 0; i < 8; i++)
#pragma unroll
                for (int j = 0; j < NP; j++)
                    acc[i][j] = ffma2(a[i], b[j], acc[i][j]);
        }
        if (t + 1 < T) { STS((t + 1) & 1); __syncthreads(); }
    }

    float sc[2 * NP], sh[2 * NP];
    if (EPI == 1) {
#pragma unroll
        for (int j = 0; j < 2 * NP; j++) {
            int cn = n0 + col0 + j;
            float s = eg[cn] * rsqrtf(ev[cn] + 1e-5f);
            sc[j] = s;
            sh[j] = eb[cn] - em[cn] * s;
        }
    }
#pragma unroll
    for (int i = 0; i < 8; i++) {
        float o[2 * NP];
#pragma unroll
        for (int j = 0; j < NP; j++) {
            F2U u2; u2.u = acc[i][j];
            o[2 * j] = u2.f.x;
            o[2 * j + 1] = u2.f.y;
        }
        if (EPI == 1) {
#pragma unroll
            for (int j = 0; j < 2 * NP; j++) o[j] = fmaxf(o[j] * sc[j] + sh[j], 0.f);
        }
        float* cp = Cz + (size_t)(m0 + row0 + i) * N + n0 + col0;
        *(float4*)cp = make_float4(o[0], o[1], o[2], o[3]);
        if constexpr (NP == 4)
            *(float4*)(cp + 4) = make_float4(o[4], o[5], o[6], o[7]);
    }
}

// ---------------- pool: two-stage over L ----------------
__global__ void pool1_kernel() {
    int s = blockIdx.y >> 2, b = blockIdx.y & 3, chunk = blockIdx.x;
    int d = threadIdx.x;
    const float* p = d_seq[s] + ((size_t)b * LSEQ + chunk * 64) * DM + d;
    float acc = 0.f;
#pragma unroll 8
    for (int l = 0; l < 64; l++) acc += p[(size_t)l * DM];
    d_ppart[s][chunk][b * DM + d] = acc;
}
__global__ void pool2_kernel() {
    int s = blockIdx.x >> 2, b = blockIdx.x & 3;
    int d = threadIdx.x;
    float acc = 0.f;
#pragma unroll
    for (int c = 0; c < 16; c++) acc += d_ppart[s][c][b * DM + d];
    d_pooled[s][b * DM + d] = acc * (1.0f / LSEQ);
}

// ---------------- lambda predictor ----------------
__global__ void lambda_kernel(const float* __restrict__ w1, const float* __restrict__ b1,
                              const float* __restrict__ w2, const float* __restrict__ b2) {
    int b = blockIdx.x, j = threadIdx.x;
    const float* pV = d_pooled[0] + b * DM;
    const float* pI = d_pooled[1] + b * DM;
    const float* w = w1 + (size_t)j * (2 * DM);
    float acc = b1[j];
    for (int c = 0; c < DM; c++) acc += pV[c] * w[c];
    for (int c = 0; c < DM; c++) acc += pI[c] * w[DM + c];
    __shared__ float h1[128];
    h1[j] = fmaxf(acc, 0.f);
    __syncthreads();
    if (j == 0) {
        float l0 = b2[0], l1 = b2[1];
        for (int c = 0; c < 128; c++) { l0 += h1[c] * w2[c]; l1 += h1[c] * w2[128 + c]; }
        float mx = fmaxf(l0, l1);
        float e0 = expf(l0 - mx), e1 = expf(l1 - mx);
        float inv = 1.f / (e0 + e1);
        d_lam[b * 2 + 0] = e0 * inv;
        d_lam[b * 2 + 1] = e1 * inv;
    }
}

// ---------------- LayerNorm over D=512, streams batched via grid.y ----------------
__global__ void ln_kernel(const float* __restrict__ g0, const float* __restrict__ b0,
                          const float* __restrict__ g1, const float* __restrict__ b1) {
    int s = blockIdx.y;
    const float* g = s ? g1 : g0;
    const float* b = s ? b1 : b0;
    int n = blockIdx.x, t = threadIdx.x;
    float4 v = ((const float4*)(d_seq[s] + (size_t)n * DM))[t];
    float sm = v.x + v.y + v.z + v.w;
    float sq = v.x * v.x + v.y * v.y + v.z * v.z + v.w * v.w;
#pragma unroll
    for (int o = 16; o; o >>= 1) {
        sm += __shfl_xor_sync(0xffffffffu, sm, o);
        sq += __shfl_xor_sync(0xffffffffu, sq, o);
    }
    __shared__ float ss[4], sqs[4];
    int w = t >> 5, ln = t & 31;
    if (ln == 0) { ss[w] = sm; sqs[w] = sq; }
    __syncthreads();
    sm = ss[0] + ss[1] + ss[2] + ss[3];
    sq = sqs[0] + sqs[1] + sqs[2] + sqs[3];
    float mu = sm * (1.f / DM);
    float var = sq * (1.f / DM) - mu * mu;
    float inv = rsqrtf(var + 1e-5f);
    float4 gg = ((const float4*)g)[t];
    float4 bb = ((const float4*)b)[t];
    float4 o4;
    o4.x = (v.x - mu) * inv * gg.x + bb.x;
    o4.y = (v.y - mu) * inv * gg.y + bb.y;
    o4.z = (v.z - mu) * inv * gg.z + bb.z;
    o4.w = (v.w - mu) * inv * gg.w + bb.w;
    ((float4*)(d_xn[s] + (size_t)n * DM))[t] = o4;
}

// ---------------- SSM scan: both variants per thread, lambda-weighted ----------------
__global__ void __launch_bounds__(128)
scan_kernel(const float* __restrict__ VA, const float* __restrict__ VB,
            const float* __restrict__ VC, const float* __restrict__ IA,
            const float* __restrict__ IB, const float* __restrict__ IC) {
    int idx = blockIdx.x * 128 + threadIdx.x;
    int i    = idx & 1023;
    int rest = idx >> 10;
    int b    = rest & 3;
    int dir  = (rest >> 2) & 1;
    int s    = (rest >> 3) & 1;

    const float* Alog = s ? IA : VA;
    const float* Bown = s ? IB : VB;
    const float* Both = s ? VB : IB;
    const float* Cp   = s ? IC : VC;
    float w0 = 0.5f * d_lam[b * 2 + 0];
    float w1 = 0.5f * d_lam[b * 2 + 1];

    float A[DS], B0r[DS], B1r[DS], Cr[DS], h0[DS], h1[DS];
#pragma unroll
    for (int k = 0; k < DS; k++) {
        A[k]   = fminf(fmaxf(-expf(Alog[i * DS + k]), -10.f), -0.01f);
        B0r[k] = Bown[i * DS + k];
        B1r[k] = Both[i * DS + k];
        Cr[k]  = Cp[i * DS + k];
        h0[k] = 0.f; h1[k] = 0.f;
    }

    const float* xs = d_xp[s] + (size_t)b * LSEQ * (2 * DI) + i;
    float* yo = d_y2[s][dir] + (size_t)b * LSEQ * DI + i;
    int t  = dir ? (LSEQ - 1) : 0;
    int dt = dir ? -1 : 1;
    float x = xs[(size_t)t * (2 * DI)];

    for (int step = 0; step < LSEQ; step++) {
        int tn = t + dt;
        float xn = (step + 1 < LSEQ) ? xs[(size_t)tn * (2 * DI)] : 0.f;
        float y0 = 0.f, y1 = 0.f;
#pragma unroll
        for (int k = 0; k < DS; k++) {
            h0[k] = fminf(fmaxf(fmaf(h0[k], A[k], x * B0r[k]), -10.f), 10.f);
            y0 = fmaf(h0[k], Cr[k], y0);
            h1[k] = fminf(fmaxf(fmaf(h1[k], A[k], x * B1r[k]), -10.f), 10.f);
            y1 = fmaf(h1[k], Cr[k], y1);
        }
        yo[(size_t)t * DI] = fmaf(w0, y0, w1 * y1);
        t = tn; x = xn;
    }
}

// ---------------- gated combine ----------------
__global__ void gated_combine() {
    int s = blockIdx.y;
    int idx = blockIdx.x * 256 + threadIdx.x;
    int i = idx & 1023;
    int n = idx >> 10;
    float g = d_xp[s][(size_t)n * (2 * DI) + DI + i];
    float sig = 1.f / (1.f + expf(-g));
    d_u[s][idx] = (d_y2[s][0][idx] + d_y2[s][1][idx]) * g * sig;
}

// ---------------- final: transpose + BN + residual + gate ----------------
__global__ void final_kernel(const float* __restrict__ x0, const float* __restrict__ x1,
                             float* __restrict__ out,
                             const float* __restrict__ g, const float* __restrict__ bb,
                             const float* __restrict__ m, const float* __restrict__ v,
                             const float* __restrict__ gatep) {
    __shared__ float tile[32][33];
    int s = blockIdx.z >> 2;
    int b = blockIdx.z & 3;
    int hw0 = blockIdx.x * 32, o0 = blockIdx.y * 32;
    int tx = threadIdx.x, ty = threadIdx.y;
    tile[ty][tx] = d_res[s][((size_t)b * LSEQ + hw0 + ty) * CIN + o0 + tx];
    __syncthreads();
    int o = o0 + ty, hw = hw0 + tx;
    float sc = g[o] * rsqrtf(v[o] + 1e-5f);
    float sh = bb[o] - m[o] * sc;
    float sg = 1.f / (1.f + expf(-gatep[0]));
    const float* xin = s ? x1 : x0;
    size_t pos = ((size_t)b * CIN + o) * LSEQ + hw;
    float val = tile[tx][ty] * sc + sh;
    out[(size_t)s * BSZ * CIN * LSEQ + pos] = xin[pos] + sg * val;
}

// ---------------- launch ----------------
extern "C" void kernel_launch(void* const* d_in, const int* in_sizes, int n_in,
                              void* d_out, int out_size) {
    const float* x_V        = (const float*)d_in[0];
    const float* x_I        = (const float*)d_in[1];
    const float* conv_red_w = (const float*)d_in[2];
    const float* bn_red_g   = (const float*)d_in[3];
    const float* bn_red_b   = (const float*)d_in[4];
    const float* bn_red_m   = (const float*)d_in[5];
    const float* bn_red_v   = (const float*)d_in[6];
    const float* conv_res_w = (const float*)d_in[7];
    const float* bn_res_g   = (const float*)d_in[8];
    const float* bn_res_b   = (const float*)d_in[9];
    const float* bn_res_m   = (const float*)d_in[10];
    const float* bn_res_v   = (const float*)d_in[11];
    const float* lam_w1     = (const float*)d_in[12];
    const float* lam_b1     = (const float*)d_in[13];
    const float* lam_w2     = (const float*)d_in[14];
    const float* lam_b2     = (const float*)d_in[15];
    const float* in_w[2]    = {(const float*)d_in[16], (const float*)d_in[23]};
    const float* out_w[2]   = {(const float*)d_in[17], (const float*)d_in[24]};
    const float* A_log[2]   = {(const float*)d_in[18], (const float*)d_in[25]};
    const float* Bmat[2]    = {(const float*)d_in[19], (const float*)d_in[26]};
    const float* Cmat[2]    = {(const float*)d_in[20], (const float*)d_in[27]};
    const float* ln_g[2]    = {(const float*)d_in[21], (const float*)d_in[28]};
    const float* ln_b[2]    = {(const float*)d_in[22], (const float*)d_in[29]};
    const float* gate       = (const float*)d_in[30];

    float *SEQ, *XN, *XP, *U, *RES, *WC;
    cudaGetSymbolAddress((void**)&SEQ, d_seq);
    cudaGetSymbolAddress((void**)&XN,  d_xn);
    cudaGetSymbolAddress((void**)&XP,  d_xp);
    cudaGetSymbolAddress((void**)&U,   d_u);
    cudaGetSymbolAddress((void**)&RES, d_res);
    cudaGetSymbolAddress((void**)&WC,  d_wc);

    // 0. Wc[z] = conv_res_w @ out_w[z]   (collapses out_proj+conv_res into one GEMM)
    gemm_kernel<128, 0, 0, 1><<<dim3(DI / 128, CIN / 128, 2), 256>>>(
        conv_res_w, conv_res_w, out_w[0], out_w[1], WC, CIN, DI, DM,
        (long long)CIN * DI, nullptr, nullptr, nullptr, nullptr);

    // 1. conv_red + BN + ReLU (reads x_V/x_I directly with transposed A access)
    gemm_kernel<128, 1, 1, 0><<<dim3(DM / 128, NTOK / 128, 2), 256>>>(
        x_V, x_I, conv_red_w, conv_red_w, SEQ, NTOK, DM, CIN, (long long)NTOK * DM,
        bn_red_g, bn_red_b, bn_red_m, bn_red_v);

    // 2. pool + lambda
    pool1_kernel<<<dim3(16, 8), 512>>>();
    pool2_kernel<<<8, 512>>>();
    lambda_kernel<<<4, 128>>>(lam_w1, lam_b1, lam_w2, lam_b2);

    // 3. layernorm + in_proj
    ln_kernel<<<dim3(NTOK, 2), 128>>>(ln_g[0], ln_b[0], ln_g[1], ln_b[1]);
    gemm_kernel<128, 0, 0, 0><<<dim3(2 * DI / 128, NTOK / 128, 2), 256>>>(
        XN, XN + (size_t)NTOK * DM, in_w[0], in_w[1], XP, NTOK, 2 * DI, DM,
        (long long)NTOK * 2 * DI, nullptr, nullptr, nullptr, nullptr);

    // 4. scans (both variants fused, lambda-weighted)
    scan_kernel<<<128, 128>>>(A_log[0], Bmat[0], Cmat[0], A_log[1], Bmat[1], Cmat[1]);

    // 5. gated combine
    gated_combine<<<dim3(NTOK * DI / 256, 2), 256>>>();

    // 6. fused out_proj + conv_res
    gemm_kernel<64, 0, 0, 0><<<dim3(CIN / 64, NTOK / 128, 2), 256>>>(
        U, U + (size_t)NTOK * DI, WC, WC + (size_t)CIN * DI, RES, NTOK, CIN, DI,
        (long long)NTOK * CIN, nullptr, nullptr, nullptr, nullptr);

    // 7. BN + residual + gate -> output
    final_kernel<<<dim3(32, 8, 8), dim3(32, 32)>>>(x_V, x_I, (float*)d_out,
                                                   bn_res_g, bn_res_b, bn_res_m,
                                                   bn_res_v, gate);
}

// round 4
// speedup vs baseline: 2.1644x; 1.7431x over previous
#include <cuda_runtime.h>
#include <math.h>
#include <stdint.h>

#define NS   2
#define BSZ  4
#define LSEQ 1024
#define NTOK 4096
#define DM   512
#define DI   1024
#define DS   16
#define CIN  256

// ---------------- scratch (static device globals; no runtime alloc) ----------------
__device__ float d_xt[NS][NTOK * CIN];        // token-major inputs
__device__ float d_seq[NS][NTOK * DM];
__device__ float d_ppart[NS][16][BSZ * DM];
__device__ float d_pooled[NS][BSZ * DM];
__device__ float d_lam[BSZ * 2];
__device__ float d_xn[NS][NTOK * DM];
__device__ float d_xp[NS][NTOK * 2 * DI];
__device__ float d_y2[NS][2][NTOK * DI];
__device__ float d_u[NS][NTOK * DI];
__device__ float d_res[NS][NTOK * CIN];
__device__ float d_wt[NS][DI * DM];           // out_w transposed [DI, DM]
__device__ float d_wc[NS][CIN * DI];          // Wc = conv_res_w @ out_w

// ---------------- PTX helpers (all baseline sm_80+, no 'a' features) ----------------
__device__ __forceinline__ uint32_t smem_u32(const void* p) {
    uint32_t a;
    asm("{ .reg .u64 t; cvta.to.shared.u64 t, %1; cvt.u32.u64 %0, t; }" : "=r"(a) : "l"(p));
    return a;
}
#define CP_ASYNC16(sp, gp) \
    asm volatile("cp.async.cg.shared.global [%0], [%1], 16;" :: "r"(sp), "l"(gp) : "memory")
#define CP_COMMIT() asm volatile("cp.async.commit_group;" ::: "memory")
#define CP_WAIT1()  asm volatile("cp.async.wait_group 1;" ::: "memory")
#define CP_WAIT0()  asm volatile("cp.async.wait_group 0;" ::: "memory")

#define LDSM_X4(r0, r1, r2, r3, addr) \
    asm volatile("ldmatrix.sync.aligned.m8n8.x4.shared.b16 {%0,%1,%2,%3}, [%4];" \
                 : "=r"(r0), "=r"(r1), "=r"(r2), "=r"(r3) : "r"(addr))

#define MMA_TF32(d, a, b) \
    asm volatile("mma.sync.aligned.m16n8k8.row.col.f32.tf32.tf32.f32 " \
                 "{%0,%1,%2,%3}, {%4,%5,%6,%7}, {%8,%9}, {%0,%1,%2,%3};" \
                 : "+f"((d)[0]), "+f"((d)[1]), "+f"((d)[2]), "+f"((d)[3]) \
                 : "r"((a)[0]), "r"((a)[1]), "r"((a)[2]), "r"((a)[3]), \
                   "r"((b)[0]), "r"((b)[1]))

__device__ __forceinline__ uint32_t cvt_tf32(uint32_t bits) {
    uint32_t r;
    asm("cvt.rna.tf32.f32 %0, %1;" : "=r"(r) : "f"(__uint_as_float(bits)));
    return r;
}

// ---------------- tensor-core tf32 GEMM via mma.sync: C[M,N] = A[M,K] * B[N,K]^T ----------------
// 128x128 CTA tile, 8 warps (2x4), warp tile 64x32, k-chunk 32, double-buffered cp.async.
// Smem rows padded to 144B (36 floats) -> conflict-free ldmatrix + 16B-aligned cp.async.
#define TG_STAGE_B 36864              // bytes per stage (A 18432 + B 18432)
#define TG_SMEM    (2 * TG_STAGE_B)

template <int EPI>
__global__ void __launch_bounds__(256, 2)
tgemm(const float* __restrict__ A0, const float* __restrict__ A1,
      const float* __restrict__ B0, const float* __restrict__ B1,
      float* __restrict__ C, int M, int N, int K, long long sCz,
      const float* __restrict__ eg, const float* __restrict__ eb,
      const float* __restrict__ em, const float* __restrict__ ev) {
    extern __shared__ float smf[];
    const uint32_t sbase = smem_u32(smf);

    const int tid  = threadIdx.x;
    const int lane = tid & 31;
    const int wid  = tid >> 5;
    const int z = blockIdx.z;
    const float* __restrict__ A = z ? A1 : A0;
    const float* __restrict__ B = z ? B1 : B0;
    float* Cz = C + (size_t)z * sCz;
    const int m0 = blockIdx.y * 128, n0 = blockIdx.x * 128;
    const int wm = (wid >> 2) * 64;   // warp M offset
    const int wn = (wid & 3) * 32;    // warp N offset

    // cp.async loader indices: 256 threads, 32 rows x 8 chunks of 16B per pass
    const int lr = tid >> 3;
    const int lc = tid & 7;

    auto load_stage = [&](int t) {
        const int k0 = t * 32;
        uint32_t dst = sbase + (t & 1) * TG_STAGE_B;
#pragma unroll
        for (int i = 0; i < 4; i++) {
            int m = lr + i * 32;
            CP_ASYNC16(dst + m * 144 + lc * 16, A + (size_t)(m0 + m) * K + k0 + lc * 4);
        }
        dst += 18432;
#pragma unroll
        for (int i = 0; i < 4; i++) {
            int n = lr + i * 32;
            CP_ASYNC16(dst + n * 144 + lc * 16, B + (size_t)(n0 + n) * K + k0 + lc * 4);
        }
        CP_COMMIT();
    };

    float c[4][4][4];
#pragma unroll
    for (int mt = 0; mt < 4; mt++)
#pragma unroll
        for (int nt = 0; nt < 4; nt++)
#pragma unroll
            for (int q = 0; q < 4; q++) c[mt][nt][q] = 0.f;

    const int T = K / 32;
    load_stage(0);
    load_stage(1);

    // ldmatrix lane addressing
    const int l15   = lane & 15;
    const int lhiA  = (lane >> 4) * 16;                 // a2/a3 k-half (+16B)
    const int bnrow = (lane & 7) + ((lane >> 4) << 3);  // B row (n) add
    const int bkoff = ((lane >> 3) & 1) * 16;           // b1 k-half (+16B)

    for (int t = 0; t < T; t++) {
        if (t + 1 < T) { CP_WAIT1(); } else { CP_WAIT0(); }
        __syncthreads();
        const uint32_t aB = sbase + (t & 1) * TG_STAGE_B;
        const uint32_t bB = aB + 18432;
#pragma unroll
        for (int kk = 0; kk < 4; kk++) {
            uint32_t a[4][4], b[4][2];
#pragma unroll
            for (int mt = 0; mt < 4; mt++) {
                uint32_t addr = aB + (wm + mt * 16 + l15) * 144 + kk * 32 + lhiA;
                LDSM_X4(a[mt][0], a[mt][1], a[mt][2], a[mt][3], addr);
            }
#pragma unroll
            for (int nh = 0; nh < 2; nh++) {
                uint32_t addr = bB + (wn + nh * 16 + bnrow) * 144 + kk * 32 + bkoff;
                uint32_t r0, r1, r2, r3;
                LDSM_X4(r0, r1, r2, r3, addr);
                b[nh * 2][0] = r0; b[nh * 2][1] = r1;
                b[nh * 2 + 1][0] = r2; b[nh * 2 + 1][1] = r3;
            }
            // round fp32 -> tf32 (zero-mean error; raw truncation would bias ~-1e-3)
#pragma unroll
            for (int mt = 0; mt < 4; mt++)
#pragma unroll
                for (int q = 0; q < 4; q++) a[mt][q] = cvt_tf32(a[mt][q]);
#pragma unroll
            for (int nt = 0; nt < 4; nt++) {
                b[nt][0] = cvt_tf32(b[nt][0]);
                b[nt][1] = cvt_tf32(b[nt][1]);
            }
#pragma unroll
            for (int mt = 0; mt < 4; mt++)
#pragma unroll
                for (int nt = 0; nt < 4; nt++)
                    MMA_TF32(c[mt][nt], a[mt], b[nt]);
        }
        __syncthreads();
        if (t + 2 < T) load_stage(t + 2);
    }

    // epilogue: fragments are already (row, col) addressed -> direct float2 stores
    const int gid = lane >> 2;
    const int tig = lane & 3;
#pragma unroll
    for (int mt = 0; mt < 4; mt++) {
        const int r0 = m0 + wm + mt * 16 + gid;
#pragma unroll
        for (int nt = 0; nt < 4; nt++) {
            const int col = n0 + wn + nt * 8 + tig * 2;
            float v0 = c[mt][nt][0], v1 = c[mt][nt][1];
            float v2 = c[mt][nt][2], v3 = c[mt][nt][3];
            if (EPI == 1) {
                float s0 = eg[col] * rsqrtf(ev[col] + 1e-5f);
                float h0 = eb[col] - em[col] * s0;
                float s1 = eg[col + 1] * rsqrtf(ev[col + 1] + 1e-5f);
                float h1 = eb[col + 1] - em[col + 1] * s1;
                v0 = fmaxf(v0 * s0 + h0, 0.f);
                v1 = fmaxf(v1 * s1 + h1, 0.f);
                v2 = fmaxf(v2 * s0 + h0, 0.f);
                v3 = fmaxf(v3 * s1 + h1, 0.f);
            }
            *(float2*)&Cz[(size_t)r0 * N + col]       = make_float2(v0, v1);
            *(float2*)&Cz[(size_t)(r0 + 8) * N + col] = make_float2(v2, v3);
        }
    }
}

// ---------------- transpose x: (B,C,HW) -> (B*HW, C) ----------------
__global__ void transpose_in(const float* __restrict__ x0, const float* __restrict__ x1) {
    __shared__ float tile[32][33];
    int s = blockIdx.z >> 2, b = blockIdx.z & 3;
    const float* x = s ? x1 : x0;
    int hw0 = blockIdx.x * 32, c0 = blockIdx.y * 32;
    int tx = threadIdx.x, ty = threadIdx.y;
    tile[ty][tx] = x[((size_t)b * CIN + (c0 + ty)) * LSEQ + hw0 + tx];
    __syncthreads();
    d_xt[s][((size_t)b * LSEQ + hw0 + ty) * CIN + c0 + tx] = tile[tx][ty];
}

// ---------------- transpose out_w: [DM, DI] -> [DI, DM] ----------------
__global__ void transpose_w(const float* __restrict__ w0, const float* __restrict__ w1) {
    __shared__ float tile[32][33];
    int s = blockIdx.z;
    const float* w = s ? w1 : w0;
    int c0 = blockIdx.x * 32, r0 = blockIdx.y * 32;
    int tx = threadIdx.x, ty = threadIdx.y;
    tile[ty][tx] = w[(size_t)(r0 + ty) * DI + c0 + tx];
    __syncthreads();
    d_wt[s][(size_t)(c0 + ty) * DM + r0 + tx] = tile[tx][ty];
}

// ---------------- pool: two-stage over L ----------------
__global__ void pool1_kernel() {
    int s = blockIdx.y >> 2, b = blockIdx.y & 3, chunk = blockIdx.x;
    int d = threadIdx.x;
    const float* p = d_seq[s] + ((size_t)b * LSEQ + chunk * 64) * DM + d;
    float acc = 0.f;
#pragma unroll 8
    for (int l = 0; l < 64; l++) acc += p[(size_t)l * DM];
    d_ppart[s][chunk][b * DM + d] = acc;
}
__global__ void pool2_kernel() {
    int s = blockIdx.x >> 2, b = blockIdx.x & 3;
    int d = threadIdx.x;
    float acc = 0.f;
#pragma unroll
    for (int c = 0; c < 16; c++) acc += d_ppart[s][c][b * DM + d];
    d_pooled[s][b * DM + d] = acc * (1.0f / LSEQ);
}

// ---------------- lambda predictor ----------------
__global__ void lambda_kernel(const float* __restrict__ w1, const float* __restrict__ b1,
                              const float* __restrict__ w2, const float* __restrict__ b2) {
    int b = blockIdx.x, j = threadIdx.x;
    const float* pV = d_pooled[0] + b * DM;
    const float* pI = d_pooled[1] + b * DM;
    const float* w = w1 + (size_t)j * (2 * DM);
    float acc = b1[j];
    for (int c = 0; c < DM; c++) acc += pV[c] * w[c];
    for (int c = 0; c < DM; c++) acc += pI[c] * w[DM + c];
    __shared__ float h1[128];
    h1[j] = fmaxf(acc, 0.f);
    __syncthreads();
    if (j == 0) {
        float l0 = b2[0], l1 = b2[1];
        for (int c = 0; c < 128; c++) { l0 += h1[c] * w2[c]; l1 += h1[c] * w2[128 + c]; }
        float mx = fmaxf(l0, l1);
        float e0 = expf(l0 - mx), e1 = expf(l1 - mx);
        float inv = 1.f / (e0 + e1);
        d_lam[b * 2 + 0] = e0 * inv;
        d_lam[b * 2 + 1] = e1 * inv;
    }
}

// ---------------- LayerNorm over D=512 ----------------
__global__ void ln_kernel(const float* __restrict__ g0, const float* __restrict__ b0,
                          const float* __restrict__ g1, const float* __restrict__ b1) {
    int s = blockIdx.y;
    const float* g = s ? g1 : g0;
    const float* b = s ? b1 : b0;
    int n = blockIdx.x, t = threadIdx.x;
    float4 v = ((const float4*)(d_seq[s] + (size_t)n * DM))[t];
    float sm = v.x + v.y + v.z + v.w;
    float sq = v.x * v.x + v.y * v.y + v.z * v.z + v.w * v.w;
#pragma unroll
    for (int o = 16; o; o >>= 1) {
        sm += __shfl_xor_sync(0xffffffffu, sm, o);
        sq += __shfl_xor_sync(0xffffffffu, sq, o);
    }
    __shared__ float ss[4], sqs[4];
    int w = t >> 5, ln = t & 31;
    if (ln == 0) { ss[w] = sm; sqs[w] = sq; }
    __syncthreads();
    sm = ss[0] + ss[1] + ss[2] + ss[3];
    sq = sqs[0] + sqs[1] + sqs[2] + sqs[3];
    float mu = sm * (1.f / DM);
    float var = sq * (1.f / DM) - mu * mu;
    float inv = rsqrtf(var + 1e-5f);
    float4 gg = ((const float4*)g)[t];
    float4 bb = ((const float4*)b)[t];
    float4 o4;
    o4.x = (v.x - mu) * inv * gg.x + bb.x;
    o4.y = (v.y - mu) * inv * gg.y + bb.y;
    o4.z = (v.z - mu) * inv * gg.z + bb.z;
    o4.w = (v.w - mu) * inv * gg.w + bb.w;
    ((float4*)(d_xn[s] + (size_t)n * DM))[t] = o4;
}

// ---------------- SSM scan ----------------
__global__ void __launch_bounds__(128)
scan_kernel(const float* __restrict__ VA, const float* __restrict__ VB,
            const float* __restrict__ VC, const float* __restrict__ IA,
            const float* __restrict__ IB, const float* __restrict__ IC) {
    int idx = blockIdx.x * 128 + threadIdx.x;
    int i    = idx & 1023;
    int rest = idx >> 10;
    int b    = rest & 3;
    int dir  = (rest >> 2) & 1;
    int s    = (rest >> 3) & 1;

    const float* Alog = s ? IA : VA;
    const float* Bown = s ? IB : VB;
    const float* Both = s ? VB : IB;
    const float* Cp   = s ? IC : VC;
    float w0 = 0.5f * d_lam[b * 2 + 0];
    float w1 = 0.5f * d_lam[b * 2 + 1];

    float A[DS], B0r[DS], B1r[DS], Cr[DS], h0[DS], h1[DS];
#pragma unroll
    for (int k = 0; k < DS; k++) {
        A[k]   = fminf(fmaxf(-expf(Alog[i * DS + k]), -10.f), -0.01f);
        B0r[k] = Bown[i * DS + k];
        B1r[k] = Both[i * DS + k];
        Cr[k]  = Cp[i * DS + k];
        h0[k] = 0.f; h1[k] = 0.f;
    }

    const float* xs = d_xp[s] + (size_t)b * LSEQ * (2 * DI) + i;
    float* yo = d_y2[s][dir] + (size_t)b * LSEQ * DI + i;
    int t  = dir ? (LSEQ - 1) : 0;
    int dt = dir ? -1 : 1;
    float x = xs[(size_t)t * (2 * DI)];

    for (int step = 0; step < LSEQ; step++) {
        int tn = t + dt;
        float xn = (step + 1 < LSEQ) ? xs[(size_t)tn * (2 * DI)] : 0.f;
        float y0 = 0.f, y1 = 0.f;
#pragma unroll
        for (int k = 0; k < DS; k++) {
            h0[k] = fminf(fmaxf(fmaf(h0[k], A[k], x * B0r[k]), -10.f), 10.f);
            y0 = fmaf(h0[k], Cr[k], y0);
            h1[k] = fminf(fmaxf(fmaf(h1[k], A[k], x * B1r[k]), -10.f), 10.f);
            y1 = fmaf(h1[k], Cr[k], y1);
        }
        yo[(size_t)t * DI] = fmaf(w0, y0, w1 * y1);
        t = tn; x = xn;
    }
}

// ---------------- gated combine ----------------
__global__ void gated_combine() {
    int s = blockIdx.y;
    int idx = blockIdx.x * 256 + threadIdx.x;
    int i = idx & 1023;
    int n = idx >> 10;
    float g = d_xp[s][(size_t)n * (2 * DI) + DI + i];
    float sig = 1.f / (1.f + expf(-g));
    d_u[s][idx] = (d_y2[s][0][idx] + d_y2[s][1][idx]) * g * sig;
}

// ---------------- final: transpose + BN + residual + gate ----------------
__global__ void final_kernel(const float* __restrict__ x0, const float* __restrict__ x1,
                             float* __restrict__ out,
                             const float* __restrict__ g, const float* __restrict__ bb,
                             const float* __restrict__ m, const float* __restrict__ v,
                             const float* __restrict__ gatep) {
    __shared__ float tile[32][33];
    int s = blockIdx.z >> 2;
    int b = blockIdx.z & 3;
    int hw0 = blockIdx.x * 32, o0 = blockIdx.y * 32;
    int tx = threadIdx.x, ty = threadIdx.y;
    tile[ty][tx] = d_res[s][((size_t)b * LSEQ + hw0 + ty) * CIN + o0 + tx];
    __syncthreads();
    int o = o0 + ty, hw = hw0 + tx;
    float sc = g[o] * rsqrtf(v[o] + 1e-5f);
    float sh = bb[o] - m[o] * sc;
    float sg = 1.f / (1.f + expf(-gatep[0]));
    const float* xin = s ? x1 : x0;
    size_t pos = ((size_t)b * CIN + o) * LSEQ + hw;
    float val = tile[tx][ty] * sc + sh;
    out[(size_t)s * BSZ * CIN * LSEQ + pos] = xin[pos] + sg * val;
}

// ---------------- launch ----------------
extern "C" void kernel_launch(void* const* d_in, const int* in_sizes, int n_in,
                              void* d_out, int out_size) {
    const float* x_V        = (const float*)d_in[0];
    const float* x_I        = (const float*)d_in[1];
    const float* conv_red_w = (const float*)d_in[2];
    const float* bn_red_g   = (const float*)d_in[3];
    const float* bn_red_b   = (const float*)d_in[4];
    const float* bn_red_m   = (const float*)d_in[5];
    const float* bn_red_v   = (const float*)d_in[6];
    const float* conv_res_w = (const float*)d_in[7];
    const float* bn_res_g   = (const float*)d_in[8];
    const float* bn_res_b   = (const float*)d_in[9];
    const float* bn_res_m   = (const float*)d_in[10];
    const float* bn_res_v   = (const float*)d_in[11];
    const float* lam_w1     = (const float*)d_in[12];
    const float* lam_b1     = (const float*)d_in[13];
    const float* lam_w2     = (const float*)d_in[14];
    const float* lam_b2     = (const float*)d_in[15];
    const float* in_w[2]    = {(const float*)d_in[16], (const float*)d_in[23]};
    const float* out_w[2]   = {(const float*)d_in[17], (const float*)d_in[24]};
    const float* A_log[2]   = {(const float*)d_in[18], (const float*)d_in[25]};
    const float* Bmat[2]    = {(const float*)d_in[19], (const float*)d_in[26]};
    const float* Cmat[2]    = {(const float*)d_in[20], (const float*)d_in[27]};
    const float* ln_g[2]    = {(const float*)d_in[21], (const float*)d_in[28]};
    const float* ln_b[2]    = {(const float*)d_in[22], (const float*)d_in[29]};
    const float* gate       = (const float*)d_in[30];

    float *XT, *SEQ, *XN, *XP, *U, *RES, *WT, *WC;
    cudaGetSymbolAddress((void**)&XT,  d_xt);
    cudaGetSymbolAddress((void**)&SEQ, d_seq);
    cudaGetSymbolAddress((void**)&XN,  d_xn);
    cudaGetSymbolAddress((void**)&XP,  d_xp);
    cudaGetSymbolAddress((void**)&U,   d_u);
    cudaGetSymbolAddress((void**)&RES, d_res);
    cudaGetSymbolAddress((void**)&WT,  d_wt);
    cudaGetSymbolAddress((void**)&WC,  d_wc);

    cudaFuncSetAttribute(tgemm<0>, cudaFuncAttributeMaxDynamicSharedMemorySize, TG_SMEM);
    cudaFuncSetAttribute(tgemm<1>, cudaFuncAttributeMaxDynamicSharedMemorySize, TG_SMEM);

    // 0. transposes
    transpose_in<<<dim3(32, 8, 8), dim3(32, 32)>>>(x_V, x_I);
    transpose_w<<<dim3(DI / 32, DM / 32, 2), dim3(32, 32)>>>(out_w[0], out_w[1]);

    // 1. Wc[z] = conv_res_w @ out_w[z]  (M=256, N=1024, K=512)
    tgemm<0><<<dim3(DI / 128, CIN / 128, 2), 256, TG_SMEM>>>(
        conv_res_w, conv_res_w, WT, WT + (size_t)DI * DM, WC, CIN, DI, DM,
        (long long)CIN * DI, nullptr, nullptr, nullptr, nullptr);

    // 2. conv_red + BN + ReLU  (M=4096, N=512, K=256)
    tgemm<1><<<dim3(DM / 128, NTOK / 128, 2), 256, TG_SMEM>>>(
        XT, XT + (size_t)NTOK * CIN, conv_red_w, conv_red_w, SEQ, NTOK, DM, CIN,
        (long long)NTOK * DM, bn_red_g, bn_red_b, bn_red_m, bn_red_v);

    // 3. pool + lambda
    pool1_kernel<<<dim3(16, 8), 512>>>();
    pool2_kernel<<<8, 512>>>();
    lambda_kernel<<<4, 128>>>(lam_w1, lam_b1, lam_w2, lam_b2);

    // 4. layernorm + in_proj (M=4096, N=2048, K=512)
    ln_kernel<<<dim3(NTOK, 2), 128>>>(ln_g[0], ln_b[0], ln_g[1], ln_b[1]);
    tgemm<0><<<dim3(2 * DI / 128, NTOK / 128, 2), 256, TG_SMEM>>>(
        XN, XN + (size_t)NTOK * DM, in_w[0], in_w[1], XP, NTOK, 2 * DI, DM,
        (long long)NTOK * 2 * DI, nullptr, nullptr, nullptr, nullptr);

    // 5. scans
    scan_kernel<<<128, 128>>>(A_log[0], Bmat[0], Cmat[0], A_log[1], Bmat[1], Cmat[1]);

    // 6. gated combine
    gated_combine<<<dim3(NTOK * DI / 256, 2), 256>>>();

    // 7. fused out_proj + conv_res  (M=4096, N=256, K=1024)
    tgemm<0><<<dim3(CIN / 128, NTOK / 128, 2), 256, TG_SMEM>>>(
        U, U + (size_t)NTOK * DI, WC, WC + (size_t)CIN * DI, RES, NTOK, CIN, DI,
        (long long)NTOK * CIN, nullptr, nullptr, nullptr, nullptr);

    // 8. BN + residual + gate -> output
    final_kernel<<<dim3(32, 8, 8), dim3(32, 32)>>>(x_V, x_I, (float*)d_out,
                                                   bn_res_g, bn_res_b, bn_res_m,
                                                   bn_res_v, gate);
}

// round 5
// speedup vs baseline: 2.3842x; 1.1015x over previous
#include <cuda_runtime.h>
#include <math.h>
#include <stdint.h>

#define NS   2
#define BSZ  4
#define LSEQ 1024
#define NTOK 4096
#define DM   512
#define DI   1024
#define DS   16
#define CIN  256
#define NCH  8           // scan chunks
#define CHL  128         // chunk length

// ---------------- scratch (static device globals; no runtime alloc) ----------------
__device__ float d_xt[NS][NTOK * CIN];        // token-major inputs (tf32-rounded)
__device__ float d_seq[NS][NTOK * DM];
__device__ float d_ppart[NS][16][BSZ * DM];
__device__ float d_pooled[NS][BSZ * DM];
__device__ float d_lam[BSZ * 2];
__device__ float d_xn[NS][NTOK * DM];         // layernormed (tf32-rounded)
__device__ float d_xp[NS][NTOK * 2 * DI];
__device__ float d_y2[NS][2][NTOK * DI];
__device__ float d_u[NS][NTOK * DI];          // gated (tf32-rounded)
__device__ float d_res[NS][NTOK * CIN];
__device__ float d_wt[NS][DI * DM];           // out_w^T (tf32-rounded)
__device__ float d_wc[NS][CIN * DI];          // Wc = conv_res_w @ out_w (tf32-rounded)
__device__ float d_crw[DM * CIN];             // conv_red_w rounded
__device__ float d_crsw[CIN * DM];            // conv_res_w rounded
__device__ float d_inw[NS][2 * DI * DM];      // in_w rounded
// scan intermediates: [s][dir][b][chunk][var][k][i]
__device__ float d_hfin[NS * 2 * BSZ * NCH * 2 * DS * 1024];

// ---------------- PTX helpers (baseline sm_80+, no 'a' features) ----------------
__device__ __forceinline__ uint32_t smem_u32(const void* p) {
    uint32_t a;
    asm("{ .reg .u64 t; cvta.to.shared.u64 t, %1; cvt.u32.u64 %0, t; }" : "=r"(a) : "l"(p));
    return a;
}
__device__ __forceinline__ float rnd_tf32(float x) {
    uint32_t u;
    asm("cvt.rna.tf32.f32 %0, %1;" : "=r"(u) : "f"(x));
    return __uint_as_float(u);
}
#define CP_ASYNC16(sp, gp) \
    asm volatile("cp.async.cg.shared.global [%0], [%1], 16;" :: "r"(sp), "l"(gp) : "memory")
#define CP_COMMIT() asm volatile("cp.async.commit_group;" ::: "memory")
#define CP_WAIT1()  asm volatile("cp.async.wait_group 1;" ::: "memory")
#define CP_WAIT0()  asm volatile("cp.async.wait_group 0;" ::: "memory")

#define LDSM_X4(r0, r1, r2, r3, addr) \
    asm volatile("ldmatrix.sync.aligned.m8n8.x4.shared.b16 {%0,%1,%2,%3}, [%4];" \
                 : "=r"(r0), "=r"(r1), "=r"(r2), "=r"(r3) : "r"(addr))

#define MMA_TF32(d, a, b) \
    asm volatile("mma.sync.aligned.m16n8k8.row.col.f32.tf32.tf32.f32 " \
                 "{%0,%1,%2,%3}, {%4,%5,%6,%7}, {%8,%9}, {%0,%1,%2,%3};" \
                 : "+f"((d)[0]), "+f"((d)[1]), "+f"((d)[2]), "+f"((d)[3]) \
                 : "r"((a)[0]), "r"((a)[1]), "r"((a)[2]), "r"((a)[3]), \
                   "r"((b)[0]), "r"((b)[1]))

// ---------------- mma.sync tf32 GEMM: C[M,N] = A[M,K] * B[N,K]^T ----------------
// Operands are pre-rounded to tf32 by producers -> no cvt in inner loop.
// 128x128 CTA tile, 8 warps (2x4), warp tile 64x32, k-chunk 32, double-buffered cp.async.
#define TG_STAGE_B 36864
#define TG_SMEM    (2 * TG_STAGE_B)

template <int EPI>   // 0 plain, 1 BN+ReLU, 2 tf32-round output
__global__ void __launch_bounds__(256, 2)
tgemm(const float* __restrict__ A0, const float* __restrict__ A1,
      const float* __restrict__ B0, const float* __restrict__ B1,
      float* __restrict__ C, int M, int N, int K, long long sCz,
      const float* __restrict__ eg, const float* __restrict__ eb,
      const float* __restrict__ em, const float* __restrict__ ev) {
    extern __shared__ float smf[];
    const uint32_t sbase = smem_u32(smf);

    const int tid  = threadIdx.x;
    const int lane = tid & 31;
    const int wid  = tid >> 5;
    const int z = blockIdx.z;
    const float* __restrict__ A = z ? A1 : A0;
    const float* __restrict__ B = z ? B1 : B0;
    float* Cz = C + (size_t)z * sCz;
    const int m0 = blockIdx.y * 128, n0 = blockIdx.x * 128;
    const int wm = (wid >> 2) * 64;
    const int wn = (wid & 3) * 32;

    const int lr = tid >> 3;
    const int lc = tid & 7;

    auto load_stage = [&](int t) {
        const int k0 = t * 32;
        uint32_t dst = sbase + (t & 1) * TG_STAGE_B;
#pragma unroll
        for (int i = 0; i < 4; i++) {
            int m = lr + i * 32;
            CP_ASYNC16(dst + m * 144 + lc * 16, A + (size_t)(m0 + m) * K + k0 + lc * 4);
        }
        dst += 18432;
#pragma unroll
        for (int i = 0; i < 4; i++) {
            int n = lr + i * 32;
            CP_ASYNC16(dst + n * 144 + lc * 16, B + (size_t)(n0 + n) * K + k0 + lc * 4);
        }
        CP_COMMIT();
    };

    float c[4][4][4];
#pragma unroll
    for (int mt = 0; mt < 4; mt++)
#pragma unroll
        for (int nt = 0; nt < 4; nt++)
#pragma unroll
            for (int q = 0; q < 4; q++) c[mt][nt][q] = 0.f;

    const int T = K / 32;
    load_stage(0);
    load_stage(1);

    const int l15   = lane & 15;
    const int lhiA  = (lane >> 4) * 16;
    const int bnrow = (lane & 7) + ((lane >> 4) << 3);
    const int bkoff = ((lane >> 3) & 1) * 16;

    for (int t = 0; t < T; t++) {
        if (t + 1 < T) { CP_WAIT1(); } else { CP_WAIT0(); }
        __syncthreads();
        const uint32_t aB = sbase + (t & 1) * TG_STAGE_B;
        const uint32_t bB = aB + 18432;
#pragma unroll
        for (int kk = 0; kk < 4; kk++) {
            uint32_t a[4][4], b[4][2];
#pragma unroll
            for (int mt = 0; mt < 4; mt++) {
                uint32_t addr = aB + (wm + mt * 16 + l15) * 144 + kk * 32 + lhiA;
                LDSM_X4(a[mt][0], a[mt][1], a[mt][2], a[mt][3], addr);
            }
#pragma unroll
            for (int nh = 0; nh < 2; nh++) {
                uint32_t addr = bB + (wn + nh * 16 + bnrow) * 144 + kk * 32 + bkoff;
                uint32_t r0, r1, r2, r3;
                LDSM_X4(r0, r1, r2, r3, addr);
                b[nh * 2][0] = r0; b[nh * 2][1] = r1;
                b[nh * 2 + 1][0] = r2; b[nh * 2 + 1][1] = r3;
            }
#pragma unroll
            for (int mt = 0; mt < 4; mt++)
#pragma unroll
                for (int nt = 0; nt < 4; nt++)
                    MMA_TF32(c[mt][nt], a[mt], b[nt]);
        }
        __syncthreads();
        if (t + 2 < T) load_stage(t + 2);
    }

    const int gid = lane >> 2;
    const int tig = lane & 3;
#pragma unroll
    for (int mt = 0; mt < 4; mt++) {
        const int r0 = m0 + wm + mt * 16 + gid;
#pragma unroll
        for (int nt = 0; nt < 4; nt++) {
            const int col = n0 + wn + nt * 8 + tig * 2;
            float v0 = c[mt][nt][0], v1 = c[mt][nt][1];
            float v2 = c[mt][nt][2], v3 = c[mt][nt][3];
            if (EPI == 1) {
                float s0 = eg[col] * rsqrtf(ev[col] + 1e-5f);
                float h0 = eb[col] - em[col] * s0;
                float s1 = eg[col + 1] * rsqrtf(ev[col + 1] + 1e-5f);
                float h1 = eb[col + 1] - em[col + 1] * s1;
                v0 = fmaxf(v0 * s0 + h0, 0.f);
                v1 = fmaxf(v1 * s1 + h1, 0.f);
                v2 = fmaxf(v2 * s0 + h0, 0.f);
                v3 = fmaxf(v3 * s1 + h1, 0.f);
            } else if (EPI == 2) {
                v0 = rnd_tf32(v0); v1 = rnd_tf32(v1);
                v2 = rnd_tf32(v2); v3 = rnd_tf32(v3);
            }
            *(float2*)&Cz[(size_t)r0 * N + col]       = make_float2(v0, v1);
            *(float2*)&Cz[(size_t)(r0 + 8) * N + col] = make_float2(v2, v3);
        }
    }
}

// ---------------- weight rounding prep ----------------
__global__ void prep_round(const float* __restrict__ src, float* __restrict__ dst, int n) {
    int i = blockIdx.x * 256 + threadIdx.x;
    if (i < n) dst[i] = rnd_tf32(src[i]);
}

// ---------------- transpose x: (B,C,HW) -> (B*HW, C), tf32-rounded ----------------
__global__ void transpose_in(const float* __restrict__ x0, const float* __restrict__ x1) {
    __shared__ float tile[32][33];
    int s = blockIdx.z >> 2, b = blockIdx.z & 3;
    const float* x = s ? x1 : x0;
    int hw0 = blockIdx.x * 32, c0 = blockIdx.y * 32;
    int tx = threadIdx.x, ty = threadIdx.y;
    tile[ty][tx] = x[((size_t)b * CIN + (c0 + ty)) * LSEQ + hw0 + tx];
    __syncthreads();
    d_xt[s][((size_t)b * LSEQ + hw0 + ty) * CIN + c0 + tx] = rnd_tf32(tile[tx][ty]);
}

// ---------------- transpose out_w: [DM, DI] -> [DI, DM], tf32-rounded ----------------
__global__ void transpose_w(const float* __restrict__ w0, const float* __restrict__ w1) {
    __shared__ float tile[32][33];
    int s = blockIdx.z;
    const float* w = s ? w1 : w0;
    int c0 = blockIdx.x * 32, r0 = blockIdx.y * 32;
    int tx = threadIdx.x, ty = threadIdx.y;
    tile[ty][tx] = w[(size_t)(r0 + ty) * DI + c0 + tx];
    __syncthreads();
    d_wt[s][(size_t)(c0 + ty) * DM + r0 + tx] = rnd_tf32(tile[tx][ty]);
}

// ---------------- pool: two-stage over L ----------------
__global__ void pool1_kernel() {
    int s = blockIdx.y >> 2, b = blockIdx.y & 3, chunk = blockIdx.x;
    int d = threadIdx.x;
    const float* p = d_seq[s] + ((size_t)b * LSEQ + chunk * 64) * DM + d;
    float acc = 0.f;
#pragma unroll 8
    for (int l = 0; l < 64; l++) acc += p[(size_t)l * DM];
    d_ppart[s][chunk][b * DM + d] = acc;
}
__global__ void pool2_kernel() {
    int s = blockIdx.x >> 2, b = blockIdx.x & 3;
    int d = threadIdx.x;
    float acc = 0.f;
#pragma unroll
    for (int c = 0; c < 16; c++) acc += d_ppart[s][c][b * DM + d];
    d_pooled[s][b * DM + d] = acc * (1.0f / LSEQ);
}

// ---------------- lambda predictor ----------------
__global__ void lambda_kernel(const float* __restrict__ w1, const float* __restrict__ b1,
                              const float* __restrict__ w2, const float* __restrict__ b2) {
    int b = blockIdx.x, j = threadIdx.x;
    const float* pV = d_pooled[0] + b * DM;
    const float* pI = d_pooled[1] + b * DM;
    const float* w = w1 + (size_t)j * (2 * DM);
    float acc = b1[j];
    for (int c = 0; c < DM; c++) acc += pV[c] * w[c];
    for (int c = 0; c < DM; c++) acc += pI[c] * w[DM + c];
    __shared__ float h1[128];
    h1[j] = fmaxf(acc, 0.f);
    __syncthreads();
    if (j == 0) {
        float l0 = b2[0], l1 = b2[1];
        for (int c = 0; c < 128; c++) { l0 += h1[c] * w2[c]; l1 += h1[c] * w2[128 + c]; }
        float mx = fmaxf(l0, l1);
        float e0 = expf(l0 - mx), e1 = expf(l1 - mx);
        float inv = 1.f / (e0 + e1);
        d_lam[b * 2 + 0] = e0 * inv;
        d_lam[b * 2 + 1] = e1 * inv;
    }
}

// ---------------- LayerNorm over D=512, tf32-rounded output ----------------
__global__ void ln_kernel(const float* __restrict__ g0, const float* __restrict__ b0,
                          const float* __restrict__ g1, const float* __restrict__ b1) {
    int s = blockIdx.y;
    const float* g = s ? g1 : g0;
    const float* b = s ? b1 : b0;
    int n = blockIdx.x, t = threadIdx.x;
    float4 v = ((const float4*)(d_seq[s] + (size_t)n * DM))[t];
    float sm = v.x + v.y + v.z + v.w;
    float sq = v.x * v.x + v.y * v.y + v.z * v.z + v.w * v.w;
#pragma unroll
    for (int o = 16; o; o >>= 1) {
        sm += __shfl_xor_sync(0xffffffffu, sm, o);
        sq += __shfl_xor_sync(0xffffffffu, sq, o);
    }
    __shared__ float ss[4], sqs[4];
    int w = t >> 5, ln = t & 31;
    if (ln == 0) { ss[w] = sm; sqs[w] = sq; }
    __syncthreads();
    sm = ss[0] + ss[1] + ss[2] + ss[3];
    sq = sqs[0] + sqs[1] + sqs[2] + sqs[3];
    float mu = sm * (1.f / DM);
    float var = sq * (1.f / DM) - mu * mu;
    float inv = rsqrtf(var + 1e-5f);
    float4 gg = ((const float4*)g)[t];
    float4 bb = ((const float4*)b)[t];
    float4 o4;
    o4.x = rnd_tf32((v.x - mu) * inv * gg.x + bb.x);
    o4.y = rnd_tf32((v.y - mu) * inv * gg.y + bb.y);
    o4.z = rnd_tf32((v.z - mu) * inv * gg.z + bb.z);
    o4.w = rnd_tf32((v.w - mu) * inv * gg.w + bb.w);
    ((float4*)(d_xn[s] + (size_t)n * DM))[t] = o4;
}

// ================= chunked parallel scan (linear regime; clip kept in-chunk) =================
// layout helper: d_hfin[s][dir][b][chunk][var][k][i], i fastest
__device__ __forceinline__ size_t hf_off(int s, int dir, int b, int c, int var, int i) {
    return ((((((size_t)s * 2 + dir) * 4 + b) * NCH + c) * 2 + var) * DS) * 1024 + i;
}

// pass 1: per (chain, chunk) compute chunk-final h from h=0 (no y)
__global__ void __launch_bounds__(256)
scan_pass1(const float* __restrict__ VA, const float* __restrict__ VB,
           const float* __restrict__ IA, const float* __restrict__ IB) {
    int idx = blockIdx.x * 256 + threadIdx.x;       // 131072
    int i   = idx & 1023;
    int c   = (idx >> 10) & 7;
    int b   = (idx >> 13) & 3;
    int dir = (idx >> 15) & 1;
    int s   = (idx >> 16) & 1;

    const float* Alog = s ? IA : VA;
    const float* Bown = s ? IB : VB;
    const float* Both = s ? VB : IB;

    float A[DS], B0r[DS], B1r[DS], h0[DS], h1[DS];
#pragma unroll
    for (int k = 0; k < DS; k++) {
        A[k]   = fminf(fmaxf(-expf(Alog[i * DS + k]), -10.f), -0.01f);
        B0r[k] = Bown[i * DS + k];
        B1r[k] = Both[i * DS + k];
        h0[k] = 0.f; h1[k] = 0.f;
    }

    const float* xs = d_xp[s] + (size_t)b * LSEQ * (2 * DI) + i;
    int t  = dir ? (LSEQ - 1 - c * CHL) : c * CHL;
    int dt = dir ? -1 : 1;

    for (int step = 0; step < CHL; step++, t += dt) {
        float x = xs[(size_t)t * (2 * DI)];
#pragma unroll
        for (int k = 0; k < DS; k++) {
            h0[k] = fminf(fmaxf(fmaf(h0[k], A[k], x * B0r[k]), -10.f), 10.f);
            h1[k] = fminf(fmaxf(fmaf(h1[k], A[k], x * B1r[k]), -10.f), 10.f);
        }
    }

    size_t o0 = hf_off(s, dir, b, c, 0, i);
    size_t o1 = hf_off(s, dir, b, c, 1, i);
#pragma unroll
    for (int k = 0; k < DS; k++) {
        d_hfin[o0 + (size_t)k * 1024] = h0[k];
        d_hfin[o1 + (size_t)k * 1024] = h1[k];
    }
}

// pass 2: per chain, prefix across chunks: h_in[c] = A^128 * h_in[c-1] + hfin[c-1]
// overwrites d_hfin slots in place with h_in values
__global__ void __launch_bounds__(256)
scan_pass2(const float* __restrict__ VA, const float* __restrict__ IA) {
    int idx = blockIdx.x * 256 + threadIdx.x;       // 16384
    int i   = idx & 1023;
    int b   = (idx >> 10) & 3;
    int dir = (idx >> 12) & 1;
    int s   = (idx >> 13) & 1;

    const float* Alog = s ? IA : VA;
    float a128[DS];
#pragma unroll
    for (int k = 0; k < DS; k++) {
        float a = fminf(fmaxf(-expf(Alog[i * DS + k]), -10.f), -0.01f);
#pragma unroll
        for (int q = 0; q < 7; q++) a = a * a;      // A^128
        a128[k] = a;
    }

    const size_t cstride = (size_t)2 * DS * 1024;   // chunk stride in d_hfin
#pragma unroll
    for (int var = 0; var < 2; var++) {
        size_t base = hf_off(s, dir, b, 0, var, i);
        float hin[DS];
#pragma unroll
        for (int k = 0; k < DS; k++) hin[k] = 0.f;
        for (int c = 0; c < NCH; c++) {
            size_t o = base + c * cstride;
#pragma unroll
            for (int k = 0; k < DS; k++) {
                float fin = d_hfin[o + (size_t)k * 1024];
                d_hfin[o + (size_t)k * 1024] = hin[k];
                hin[k] = fmaf(a128[k], hin[k], fin);
            }
        }
    }
}

// pass 3: per (chain, chunk) re-scan from true h_in, write lambda-weighted y
__global__ void __launch_bounds__(256)
scan_pass3(const float* __restrict__ VA, const float* __restrict__ VB,
           const float* __restrict__ VC, const float* __restrict__ IA,
           const float* __restrict__ IB, const float* __restrict__ IC) {
    int idx = blockIdx.x * 256 + threadIdx.x;       // 131072
    int i   = idx & 1023;
    int c   = (idx >> 10) & 7;
    int b   = (idx >> 13) & 3;
    int dir = (idx >> 15) & 1;
    int s   = (idx >> 16) & 1;

    const float* Alog = s ? IA : VA;
    const float* Bown = s ? IB : VB;
    const float* Both = s ? VB : IB;
    const float* Cp   = s ? IC : VC;
    float w0 = 0.5f * d_lam[b * 2 + 0];
    float w1 = 0.5f * d_lam[b * 2 + 1];

    float A[DS], B0r[DS], B1r[DS], Cr[DS], h0[DS], h1[DS];
    size_t o0 = hf_off(s, dir, b, c, 0, i);
    size_t o1 = hf_off(s, dir, b, c, 1, i);
#pragma unroll
    for (int k = 0; k < DS; k++) {
        A[k]   = fminf(fmaxf(-expf(Alog[i * DS + k]), -10.f), -0.01f);
        B0r[k] = Bown[i * DS + k];
        B1r[k] = Both[i * DS + k];
        Cr[k]  = Cp[i * DS + k];
        h0[k]  = d_hfin[o0 + (size_t)k * 1024];
        h1[k]  = d_hfin[o1 + (size_t)k * 1024];
    }

    const float* xs = d_xp[s] + (size_t)b * LSEQ * (2 * DI) + i;
    float* yo = d_y2[s][dir] + (size_t)b * LSEQ * DI + i;
    int t  = dir ? (LSEQ - 1 - c * CHL) : c * CHL;
    int dt = dir ? -1 : 1;

    for (int step = 0; step < CHL; step++, t += dt) {
        float x = xs[(size_t)t * (2 * DI)];
        float y0 = 0.f, y1 = 0.f;
#pragma unroll
        for (int k = 0; k < DS; k++) {
            h0[k] = fminf(fmaxf(fmaf(h0[k], A[k], x * B0r[k]), -10.f), 10.f);
            y0 = fmaf(h0[k], Cr[k], y0);
            h1[k] = fminf(fmaxf(fmaf(h1[k], A[k], x * B1r[k]), -10.f), 10.f);
            y1 = fmaf(h1[k], Cr[k], y1);
        }
        yo[(size_t)t * DI] = fmaf(w0, y0, w1 * y1);
    }
}

// ---------------- gated combine, tf32-rounded output ----------------
__global__ void gated_combine() {
    int s = blockIdx.y;
    int idx = blockIdx.x * 256 + threadIdx.x;
    int i = idx & 1023;
    int n = idx >> 10;
    float g = d_xp[s][(size_t)n * (2 * DI) + DI + i];
    float sig = 1.f / (1.f + expf(-g));
    d_u[s][idx] = rnd_tf32((d_y2[s][0][idx] + d_y2[s][1][idx]) * g * sig);
}

// ---------------- final: transpose + BN + residual + gate ----------------
__global__ void final_kernel(const float* __restrict__ x0, const float* __restrict__ x1,
                             float* __restrict__ out,
                             const float* __restrict__ g, const float* __restrict__ bb,
                             const float* __restrict__ m, const float* __restrict__ v,
                             const float* __restrict__ gatep) {
    __shared__ float tile[32][33];
    int s = blockIdx.z >> 2;
    int b = blockIdx.z & 3;
    int hw0 = blockIdx.x * 32, o0 = blockIdx.y * 32;
    int tx = threadIdx.x, ty = threadIdx.y;
    tile[ty][tx] = d_res[s][((size_t)b * LSEQ + hw0 + ty) * CIN + o0 + tx];
    __syncthreads();
    int o = o0 + ty, hw = hw0 + tx;
    float sc = g[o] * rsqrtf(v[o] + 1e-5f);
    float sh = bb[o] - m[o] * sc;
    float sg = 1.f / (1.f + expf(-gatep[0]));
    const float* xin = s ? x1 : x0;
    size_t pos = ((size_t)b * CIN + o) * LSEQ + hw;
    float val = tile[tx][ty] * sc + sh;
    out[(size_t)s * BSZ * CIN * LSEQ + pos] = xin[pos] + sg * val;
}

// ---------------- launch ----------------
extern "C" void kernel_launch(void* const* d_in, const int* in_sizes, int n_in,
                              void* d_out, int out_size) {
    const float* x_V        = (const float*)d_in[0];
    const float* x_I        = (const float*)d_in[1];
    const float* conv_red_w = (const float*)d_in[2];
    const float* bn_red_g   = (const float*)d_in[3];
    const float* bn_red_b   = (const float*)d_in[4];
    const float* bn_red_m   = (const float*)d_in[5];
    const float* bn_red_v   = (const float*)d_in[6];
    const float* conv_res_w = (const float*)d_in[7];
    const float* bn_res_g   = (const float*)d_in[8];
    const float* bn_res_b   = (const float*)d_in[9];
    const float* bn_res_m   = (const float*)d_in[10];
    const float* bn_res_v   = (const float*)d_in[11];
    const float* lam_w1     = (const float*)d_in[12];
    const float* lam_b1     = (const float*)d_in[13];
    const float* lam_w2     = (const float*)d_in[14];
    const float* lam_b2     = (const float*)d_in[15];
    const float* in_w[2]    = {(const float*)d_in[16], (const float*)d_in[23]};
    const float* out_w[2]   = {(const float*)d_in[17], (const float*)d_in[24]};
    const float* A_log[2]   = {(const float*)d_in[18], (const float*)d_in[25]};
    const float* Bmat[2]    = {(const float*)d_in[19], (const float*)d_in[26]};
    const float* Cmat[2]    = {(const float*)d_in[20], (const float*)d_in[27]};
    const float* ln_g[2]    = {(const float*)d_in[21], (const float*)d_in[28]};
    const float* ln_b[2]    = {(const float*)d_in[22], (const float*)d_in[29]};
    const float* gate       = (const float*)d_in[30];

    float *XT, *SEQ, *XN, *XP, *U, *RES, *WT, *WC, *CRW, *CRSW, *INW;
    cudaGetSymbolAddress((void**)&XT,   d_xt);
    cudaGetSymbolAddress((void**)&SEQ,  d_seq);
    cudaGetSymbolAddress((void**)&XN,   d_xn);
    cudaGetSymbolAddress((void**)&XP,   d_xp);
    cudaGetSymbolAddress((void**)&U,    d_u);
    cudaGetSymbolAddress((void**)&RES,  d_res);
    cudaGetSymbolAddress((void**)&WT,   d_wt);
    cudaGetSymbolAddress((void**)&WC,   d_wc);
    cudaGetSymbolAddress((void**)&CRW,  d_crw);
    cudaGetSymbolAddress((void**)&CRSW, d_crsw);
    cudaGetSymbolAddress((void**)&INW,  d_inw);

    cudaFuncSetAttribute(tgemm<0>, cudaFuncAttributeMaxDynamicSharedMemorySize, TG_SMEM);
    cudaFuncSetAttribute(tgemm<1>, cudaFuncAttributeMaxDynamicSharedMemorySize, TG_SMEM);
    cudaFuncSetAttribute(tgemm<2>, cudaFuncAttributeMaxDynamicSharedMemorySize, TG_SMEM);

    // 0. weight rounding + transposes
    prep_round<<<DM * CIN / 256, 256>>>(conv_red_w, CRW, DM * CIN);
    prep_round<<<CIN * DM / 256, 256>>>(conv_res_w, CRSW, CIN * DM);
    prep_round<<<2 * DI * DM / 256, 256>>>(in_w[0], INW, 2 * DI * DM);
    prep_round<<<2 * DI * DM / 256, 256>>>(in_w[1], INW + (size_t)2 * DI * DM, 2 * DI * DM);
    transpose_in<<<dim3(32, 8, 8), dim3(32, 32)>>>(x_V, x_I);
    transpose_w<<<dim3(DI / 32, DM / 32, 2), dim3(32, 32)>>>(out_w[0], out_w[1]);

    // 1. Wc[z] = conv_res_w @ out_w[z]  (M=256, N=1024, K=512), round output
    tgemm<2><<<dim3(DI / 128, CIN / 128, 2), 256, TG_SMEM>>>(
        CRSW, CRSW, WT, WT + (size_t)DI * DM, WC, CIN, DI, DM,
        (long long)CIN * DI, nullptr, nullptr, nullptr, nullptr);

    // 2. conv_red + BN + ReLU  (M=4096, N=512, K=256)
    tgemm<1><<<dim3(DM / 128, NTOK / 128, 2), 256, TG_SMEM>>>(
        XT, XT + (size_t)NTOK * CIN, CRW, CRW, SEQ, NTOK, DM, CIN,
        (long long)NTOK * DM, bn_red_g, bn_red_b, bn_red_m, bn_red_v);

    // 3. pool + lambda
    pool1_kernel<<<dim3(16, 8), 512>>>();
    pool2_kernel<<<8, 512>>>();
    lambda_kernel<<<4, 128>>>(lam_w1, lam_b1, lam_w2, lam_b2);

    // 4. layernorm + in_proj (M=4096, N=2048, K=512)
    ln_kernel<<<dim3(NTOK, 2), 128>>>(ln_g[0], ln_b[0], ln_g[1], ln_b[1]);
    tgemm<0><<<dim3(2 * DI / 128, NTOK / 128, 2), 256, TG_SMEM>>>(
        XN, XN + (size_t)NTOK * DM, INW, INW + (size_t)2 * DI * DM, XP, NTOK, 2 * DI, DM,
        (long long)NTOK * 2 * DI, nullptr, nullptr, nullptr, nullptr);

    // 5. chunked parallel scan (3 passes)
    scan_pass1<<<512, 256>>>(A_log[0], Bmat[0], A_log[1], Bmat[1]);
    scan_pass2<<<64, 256>>>(A_log[0], A_log[1]);
    scan_pass3<<<512, 256>>>(A_log[0], Bmat[0], Cmat[0], A_log[1], Bmat[1], Cmat[1]);

    // 6. gated combine
    gated_combine<<<dim3(NTOK * DI / 256, 2), 256>>>();

    // 7. fused out_proj + conv_res  (M=4096, N=256, K=1024)
    tgemm<0><<<dim3(CIN / 128, NTOK / 128, 2), 256, TG_SMEM>>>(
        U, U + (size_t)NTOK * DI, WC, WC + (size_t)CIN * DI, RES, NTOK, CIN, DI,
        (long long)NTOK * CIN, nullptr, nullptr, nullptr, nullptr);

    // 8. BN + residual + gate -> output
    final_kernel<<<dim3(32, 8, 8), dim3(32, 32)>>>(x_V, x_I, (float*)d_out,
                                                   bn_res_g, bn_res_b, bn_res_m,
                                                   bn_res_v, gate);
}

// round 6
// speedup vs baseline: 2.6371x; 1.1061x over previous
#include <cuda_runtime.h>
#include <cuda_bf16.h>
#include <math.h>
#include <stdint.h>

#define NS   2
#define BSZ  4
#define LSEQ 1024
#define NTOK 4096
#define DM   512
#define DI   1024
#define DS   16
#define CIN  256
#define NCH  8
#define CHL  128

typedef __nv_bfloat16 bf16;

// ---------------- scratch (static device globals; no runtime alloc) ----------------
__device__ bf16  d_xt[NS][NTOK * CIN];        // token-major inputs, bf16
__device__ float d_seq[NS][NTOK * DM];
__device__ float d_ppart[NS][16][BSZ * DM];
__device__ float d_pooled[NS][BSZ * DM];
__device__ float d_lam[BSZ * 2];
__device__ bf16  d_xn[NS][NTOK * DM];         // layernormed, bf16
__device__ float d_xp[NS][NTOK * 2 * DI];
__device__ float d_y2[NS][2][NTOK * DI];
__device__ bf16  d_u[NS][NTOK * DI];          // gated, bf16
__device__ float d_res[NS][NTOK * CIN];
__device__ bf16  d_wt[NS][DI * DM];           // out_w^T, bf16
__device__ bf16  d_wc[NS][CIN * DI];          // Wc = conv_res_w @ out_w, bf16
__device__ bf16  d_crw[DM * CIN];
__device__ bf16  d_crsw[CIN * DM];
__device__ bf16  d_inw[NS][2 * DI * DM];
__device__ float d_hfin[NS * 2 * BSZ * NCH * 2 * DS * 1024];

// ---------------- PTX helpers (baseline sm_80+) ----------------
__device__ __forceinline__ uint32_t smem_u32(const void* p) {
    uint32_t a;
    asm("{ .reg .u64 t; cvta.to.shared.u64 t, %1; cvt.u32.u64 %0, t; }" : "=r"(a) : "l"(p));
    return a;
}
#define CP_ASYNC16(sp, gp) \
    asm volatile("cp.async.cg.shared.global [%0], [%1], 16;" :: "r"(sp), "l"(gp) : "memory")
#define CP_COMMIT() asm volatile("cp.async.commit_group;" ::: "memory")
#define CP_WAIT1()  asm volatile("cp.async.wait_group 1;" ::: "memory")
#define CP_WAIT0()  asm volatile("cp.async.wait_group 0;" ::: "memory")

#define LDSM_X4(r0, r1, r2, r3, addr) \
    asm volatile("ldmatrix.sync.aligned.m8n8.x4.shared.b16 {%0,%1,%2,%3}, [%4];" \
                 : "=r"(r0), "=r"(r1), "=r"(r2), "=r"(r3) : "r"(addr))

#define MMA_BF16(d, a, b) \
    asm volatile("mma.sync.aligned.m16n8k16.row.col.f32.bf16.bf16.f32 " \
                 "{%0,%1,%2,%3}, {%4,%5,%6,%7}, {%8,%9}, {%0,%1,%2,%3};" \
                 : "+f"((d)[0]), "+f"((d)[1]), "+f"((d)[2]), "+f"((d)[3]) \
                 : "r"((a)[0]), "r"((a)[1]), "r"((a)[2]), "r"((a)[3]), \
                   "r"((b)[0]), "r"((b)[1]))

// ---------------- bf16 mma.sync GEMM: C[M,N] = A[M,K] * B[N,K]^T ----------------
// 128x128 CTA tile, 8 warps (2x4), warp tile 64x32, k-chunk 32 (64B bf16 rows,
// padded to 80B: conflict-free ldmatrix, 16B-aligned cp.async), double-buffered.
#define TG_PITCH   80
#define TG_MATB    (128 * TG_PITCH)      // 10240 B per matrix per stage
#define TG_STAGE_B (2 * TG_MATB)         // 20480
#define TG_SMEM    (2 * TG_STAGE_B)      // 40960

template <int EPI>   // 0 plain fp32, 1 BN+ReLU fp32, 2 bf16 output
__global__ void __launch_bounds__(256, 2)
tgemm(const bf16* __restrict__ A0, const bf16* __restrict__ A1,
      const bf16* __restrict__ B0, const bf16* __restrict__ B1,
      void* __restrict__ Cv, int M, int N, int K, long long sCz,
      const float* __restrict__ eg, const float* __restrict__ eb,
      const float* __restrict__ em, const float* __restrict__ ev) {
    extern __shared__ float smf[];
    const uint32_t sbase = smem_u32(smf);

    const int tid  = threadIdx.x;
    const int lane = tid & 31;
    const int wid  = tid >> 5;
    const int z = blockIdx.z;
    const bf16* __restrict__ A = z ? A1 : A0;
    const bf16* __restrict__ B = z ? B1 : B0;
    const int m0 = blockIdx.y * 128, n0 = blockIdx.x * 128;
    const int wm = (wid >> 2) * 64;
    const int wn = (wid & 3) * 32;

    // loader: 128 rows x 4 segs of 16B per matrix; 256 threads -> 2 rows each
    const int lr = tid >> 2;     // 0..63
    const int lc = tid & 3;      // seg

    auto load_stage = [&](int t) {
        const int k0 = t * 32;   // elements
        uint32_t dst = sbase + (t & 1) * TG_STAGE_B;
#pragma unroll
        for (int i = 0; i < 2; i++) {
            int m = lr + i * 64;
            CP_ASYNC16(dst + m * TG_PITCH + lc * 16, A + (size_t)(m0 + m) * K + k0 + lc * 8);
        }
        dst += TG_MATB;
#pragma unroll
        for (int i = 0; i < 2; i++) {
            int n = lr + i * 64;
            CP_ASYNC16(dst + n * TG_PITCH + lc * 16, B + (size_t)(n0 + n) * K + k0 + lc * 8);
        }
        CP_COMMIT();
    };

    float c[4][4][4];
#pragma unroll
    for (int mt = 0; mt < 4; mt++)
#pragma unroll
        for (int nt = 0; nt < 4; nt++)
#pragma unroll
            for (int q = 0; q < 4; q++) c[mt][nt][q] = 0.f;

    const int T = K / 32;
    load_stage(0);
    load_stage(1);

    const int l15   = lane & 15;
    const int lhiA  = (lane >> 4) * 16;                 // k8-15 half (+16B)
    const int bnrow = (lane & 7) + ((lane >> 4) << 3);  // B n-row
    const int bkoff = ((lane >> 3) & 1) * 16;           // B k-half

    for (int t = 0; t < T; t++) {
        if (t + 1 < T) { CP_WAIT1(); } else { CP_WAIT0(); }
        __syncthreads();
        const uint32_t aB = sbase + (t & 1) * TG_STAGE_B;
        const uint32_t bB = aB + TG_MATB;
#pragma unroll
        for (int kk = 0; kk < 2; kk++) {                // 2 x k16
            uint32_t a[4][4], b[4][2];
#pragma unroll
            for (int mt = 0; mt < 4; mt++) {
                uint32_t addr = aB + (wm + mt * 16 + l15) * TG_PITCH + kk * 32 + lhiA;
                LDSM_X4(a[mt][0], a[mt][1], a[mt][2], a[mt][3], addr);
            }
#pragma unroll
            for (int nh = 0; nh < 2; nh++) {
                uint32_t addr = bB + (wn + nh * 16 + bnrow) * TG_PITCH + kk * 32 + bkoff;
                uint32_t r0, r1, r2, r3;
                LDSM_X4(r0, r1, r2, r3, addr);
                b[nh * 2][0] = r0; b[nh * 2][1] = r1;
                b[nh * 2 + 1][0] = r2; b[nh * 2 + 1][1] = r3;
            }
#pragma unroll
            for (int mt = 0; mt < 4; mt++)
#pragma unroll
                for (int nt = 0; nt < 4; nt++)
                    MMA_BF16(c[mt][nt], a[mt], b[nt]);
        }
        __syncthreads();
        if (t + 2 < T) load_stage(t + 2);
    }

    const int gid = lane >> 2;
    const int tig = lane & 3;
#pragma unroll
    for (int mt = 0; mt < 4; mt++) {
        const int r0 = m0 + wm + mt * 16 + gid;
#pragma unroll
        for (int nt = 0; nt < 4; nt++) {
            const int col = n0 + wn + nt * 8 + tig * 2;
            float v0 = c[mt][nt][0], v1 = c[mt][nt][1];
            float v2 = c[mt][nt][2], v3 = c[mt][nt][3];
            if (EPI == 1) {
                float s0 = eg[col] * rsqrtf(ev[col] + 1e-5f);
                float h0 = eb[col] - em[col] * s0;
                float s1 = eg[col + 1] * rsqrtf(ev[col + 1] + 1e-5f);
                float h1 = eb[col + 1] - em[col + 1] * s1;
                v0 = fmaxf(v0 * s0 + h0, 0.f);
                v1 = fmaxf(v1 * s1 + h1, 0.f);
                v2 = fmaxf(v2 * s0 + h0, 0.f);
                v3 = fmaxf(v3 * s1 + h1, 0.f);
            }
            if (EPI == 2) {
                bf16* Cb = (bf16*)Cv + (size_t)z * sCz;
                *(__nv_bfloat162*)&Cb[(size_t)r0 * N + col] =
                    __floats2bfloat162_rn(v0, v1);
                *(__nv_bfloat162*)&Cb[(size_t)(r0 + 8) * N + col] =
                    __floats2bfloat162_rn(v2, v3);
            } else {
                float* Cf = (float*)Cv + (size_t)z * sCz;
                *(float2*)&Cf[(size_t)r0 * N + col]       = make_float2(v0, v1);
                *(float2*)&Cf[(size_t)(r0 + 8) * N + col] = make_float2(v2, v3);
            }
        }
    }
}

// ---------------- merged weight conversion fp32 -> bf16 ----------------
#define PREP_N (DM * CIN + CIN * DM + 2 * (2 * DI * DM))
__global__ void prep_all(const float* __restrict__ crw, const float* __restrict__ crsw,
                         const float* __restrict__ iw0, const float* __restrict__ iw1) {
    int i = blockIdx.x * 256 + threadIdx.x;
    const int n1 = DM * CIN, n2 = n1 + CIN * DM, n3 = n2 + 2 * DI * DM;
    if (i < n1)       d_crw[i]          = __float2bfloat16(crw[i]);
    else if (i < n2)  d_crsw[i - n1]    = __float2bfloat16(crsw[i - n1]);
    else if (i < n3)  d_inw[0][i - n2]  = __float2bfloat16(iw0[i - n2]);
    else if (i < PREP_N) d_inw[1][i - n3] = __float2bfloat16(iw1[i - n3]);
}

// ---------------- transpose x: (B,C,HW) -> (B*HW, C), bf16 ----------------
__global__ void transpose_in(const float* __restrict__ x0, const float* __restrict__ x1) {
    __shared__ float tile[32][33];
    int s = blockIdx.z >> 2, b = blockIdx.z & 3;
    const float* x = s ? x1 : x0;
    int hw0 = blockIdx.x * 32, c0 = blockIdx.y * 32;
    int tx = threadIdx.x, ty = threadIdx.y;
    tile[ty][tx] = x[((size_t)b * CIN + (c0 + ty)) * LSEQ + hw0 + tx];
    __syncthreads();
    d_xt[s][((size_t)b * LSEQ + hw0 + ty) * CIN + c0 + tx] = __float2bfloat16(tile[tx][ty]);
}

// ---------------- transpose out_w: [DM, DI] -> [DI, DM], bf16 ----------------
__global__ void transpose_w(const float* __restrict__ w0, const float* __restrict__ w1) {
    __shared__ float tile[32][33];
    int s = blockIdx.z;
    const float* w = s ? w1 : w0;
    int c0 = blockIdx.x * 32, r0 = blockIdx.y * 32;
    int tx = threadIdx.x, ty = threadIdx.y;
    tile[ty][tx] = w[(size_t)(r0 + ty) * DI + c0 + tx];
    __syncthreads();
    d_wt[s][(size_t)(c0 + ty) * DM + r0 + tx] = __float2bfloat16(tile[tx][ty]);
}

// ---------------- pool: two-stage over L ----------------
__global__ void pool1_kernel() {
    int s = blockIdx.y >> 2, b = blockIdx.y & 3, chunk = blockIdx.x;
    int d = threadIdx.x;
    const float* p = d_seq[s] + ((size_t)b * LSEQ + chunk * 64) * DM + d;
    float acc = 0.f;
#pragma unroll 8
    for (int l = 0; l < 64; l++) acc += p[(size_t)l * DM];
    d_ppart[s][chunk][b * DM + d] = acc;
}
__global__ void pool2_kernel() {
    int s = blockIdx.x >> 2, b = blockIdx.x & 3;
    int d = threadIdx.x;
    float acc = 0.f;
#pragma unroll
    for (int c = 0; c < 16; c++) acc += d_ppart[s][c][b * DM + d];
    d_pooled[s][b * DM + d] = acc * (1.0f / LSEQ);
}

// ---------------- lambda predictor ----------------
__global__ void lambda_kernel(const float* __restrict__ w1, const float* __restrict__ b1,
                              const float* __restrict__ w2, const float* __restrict__ b2) {
    int b = blockIdx.x, j = threadIdx.x;
    const float* pV = d_pooled[0] + b * DM;
    const float* pI = d_pooled[1] + b * DM;
    const float* w = w1 + (size_t)j * (2 * DM);
    float acc = b1[j];
    for (int c = 0; c < DM; c++) acc += pV[c] * w[c];
    for (int c = 0; c < DM; c++) acc += pI[c] * w[DM + c];
    __shared__ float h1[128];
    h1[j] = fmaxf(acc, 0.f);
    __syncthreads();
    if (j == 0) {
        float l0 = b2[0], l1 = b2[1];
        for (int c = 0; c < 128; c++) { l0 += h1[c] * w2[c]; l1 += h1[c] * w2[128 + c]; }
        float mx = fmaxf(l0, l1);
        float e0 = expf(l0 - mx), e1 = expf(l1 - mx);
        float inv = 1.f / (e0 + e1);
        d_lam[b * 2 + 0] = e0 * inv;
        d_lam[b * 2 + 1] = e1 * inv;
    }
}

// ---------------- LayerNorm over D=512, bf16 output ----------------
__global__ void ln_kernel(const float* __restrict__ g0, const float* __restrict__ b0,
                          const float* __restrict__ g1, const float* __restrict__ b1) {
    int s = blockIdx.y;
    const float* g = s ? g1 : g0;
    const float* b = s ? b1 : b0;
    int n = blockIdx.x, t = threadIdx.x;
    float4 v = ((const float4*)(d_seq[s] + (size_t)n * DM))[t];
    float sm = v.x + v.y + v.z + v.w;
    float sq = v.x * v.x + v.y * v.y + v.z * v.z + v.w * v.w;
#pragma unroll
    for (int o = 16; o; o >>= 1) {
        sm += __shfl_xor_sync(0xffffffffu, sm, o);
        sq += __shfl_xor_sync(0xffffffffu, sq, o);
    }
    __shared__ float ss[4], sqs[4];
    int w = t >> 5, ln = t & 31;
    if (ln == 0) { ss[w] = sm; sqs[w] = sq; }
    __syncthreads();
    sm = ss[0] + ss[1] + ss[2] + ss[3];
    sq = sqs[0] + sqs[1] + sqs[2] + sqs[3];
    float mu = sm * (1.f / DM);
    float var = sq * (1.f / DM) - mu * mu;
    float inv = rsqrtf(var + 1e-5f);
    float4 gg = ((const float4*)g)[t];
    float4 bb = ((const float4*)b)[t];
    __nv_bfloat162* dst = (__nv_bfloat162*)(d_xn[s] + (size_t)n * DM);
    dst[2 * t]     = __floats2bfloat162_rn((v.x - mu) * inv * gg.x + bb.x,
                                           (v.y - mu) * inv * gg.y + bb.y);
    dst[2 * t + 1] = __floats2bfloat162_rn((v.z - mu) * inv * gg.z + bb.z,
                                           (v.w - mu) * inv * gg.w + bb.w);
}

// ================= chunked parallel scan =================
__device__ __forceinline__ size_t hf_off(int s, int dir, int b, int c, int var, int i) {
    return ((((((size_t)s * 2 + dir) * 4 + b) * NCH + c) * 2 + var) * DS) * 1024 + i;
}

__global__ void __launch_bounds__(256)
scan_pass1(const float* __restrict__ VA, const float* __restrict__ VB,
           const float* __restrict__ IA, const float* __restrict__ IB) {
    int idx = blockIdx.x * 256 + threadIdx.x;
    int i   = idx & 1023;
    int c   = (idx >> 10) & 7;
    int b   = (idx >> 13) & 3;
    int dir = (idx >> 15) & 1;
    int s   = (idx >> 16) & 1;

    const float* Alog = s ? IA : VA;
    const float* Bown = s ? IB : VB;
    const float* Both = s ? VB : IB;

    float A[DS], B0r[DS], B1r[DS], h0[DS], h1[DS];
#pragma unroll
    for (int k = 0; k < DS; k++) {
        A[k]   = fminf(fmaxf(-expf(Alog[i * DS + k]), -10.f), -0.01f);
        B0r[k] = Bown[i * DS + k];
        B1r[k] = Both[i * DS + k];
        h0[k] = 0.f; h1[k] = 0.f;
    }

    const float* xs = d_xp[s] + (size_t)b * LSEQ * (2 * DI) + i;
    int t  = dir ? (LSEQ - 1 - c * CHL) : c * CHL;
    int dt = dir ? -1 : 1;

    for (int step = 0; step < CHL; step++, t += dt) {
        float x = xs[(size_t)t * (2 * DI)];
#pragma unroll
        for (int k = 0; k < DS; k++) {
            h0[k] = fminf(fmaxf(fmaf(h0[k], A[k], x * B0r[k]), -10.f), 10.f);
            h1[k] = fminf(fmaxf(fmaf(h1[k], A[k], x * B1r[k]), -10.f), 10.f);
        }
    }

    size_t o0 = hf_off(s, dir, b, c, 0, i);
    size_t o1 = hf_off(s, dir, b, c, 1, i);
#pragma unroll
    for (int k = 0; k < DS; k++) {
        d_hfin[o0 + (size_t)k * 1024] = h0[k];
        d_hfin[o1 + (size_t)k * 1024] = h1[k];
    }
}

__global__ void __launch_bounds__(256)
scan_pass2(const float* __restrict__ VA, const float* __restrict__ IA) {
    int idx = blockIdx.x * 256 + threadIdx.x;
    int i   = idx & 1023;
    int b   = (idx >> 10) & 3;
    int dir = (idx >> 12) & 1;
    int s   = (idx >> 13) & 1;

    const float* Alog = s ? IA : VA;
    float a128[DS];
#pragma unroll
    for (int k = 0; k < DS; k++) {
        float a = fminf(fmaxf(-expf(Alog[i * DS + k]), -10.f), -0.01f);
#pragma unroll
        for (int q = 0; q < 7; q++) a = a * a;
        a128[k] = a;
    }

    const size_t cstride = (size_t)2 * DS * 1024;
#pragma unroll
    for (int var = 0; var < 2; var++) {
        size_t base = hf_off(s, dir, b, 0, var, i);
        float hin[DS];
#pragma unroll
        for (int k = 0; k < DS; k++) hin[k] = 0.f;
        for (int c = 0; c < NCH; c++) {
            size_t o = base + c * cstride;
#pragma unroll
            for (int k = 0; k < DS; k++) {
                float fin = d_hfin[o + (size_t)k * 1024];
                d_hfin[o + (size_t)k * 1024] = hin[k];
                hin[k] = fmaf(a128[k], hin[k], fin);
            }
        }
    }
}

__global__ void __launch_bounds__(256)
scan_pass3(const float* __restrict__ VA, const float* __restrict__ VB,
           const float* __restrict__ VC, const float* __restrict__ IA,
           const float* __restrict__ IB, const float* __restrict__ IC) {
    int idx = blockIdx.x * 256 + threadIdx.x;
    int i   = idx & 1023;
    int c   = (idx >> 10) & 7;
    int b   = (idx >> 13) & 3;
    int dir = (idx >> 15) & 1;
    int s   = (idx >> 16) & 1;

    const float* Alog = s ? IA : VA;
    const float* Bown = s ? IB : VB;
    const float* Both = s ? VB : IB;
    const float* Cp   = s ? IC : VC;
    float w0 = 0.5f * d_lam[b * 2 + 0];
    float w1 = 0.5f * d_lam[b * 2 + 1];

    float A[DS], B0r[DS], B1r[DS], Cr[DS], h0[DS], h1[DS];
    size_t o0 = hf_off(s, dir, b, c, 0, i);
    size_t o1 = hf_off(s, dir, b, c, 1, i);
#pragma unroll
    for (int k = 0; k < DS; k++) {
        A[k]   = fminf(fmaxf(-expf(Alog[i * DS + k]), -10.f), -0.01f);
        B0r[k] = Bown[i * DS + k];
        B1r[k] = Both[i * DS + k];
        Cr[k]  = Cp[i * DS + k];
        h0[k]  = d_hfin[o0 + (size_t)k * 1024];
        h1[k]  = d_hfin[o1 + (size_t)k * 1024];
    }

    const float* xs = d_xp[s] + (size_t)b * LSEQ * (2 * DI) + i;
    float* yo = d_y2[s][dir] + (size_t)b * LSEQ * DI + i;
    int t  = dir ? (LSEQ - 1 - c * CHL) : c * CHL;
    int dt = dir ? -1 : 1;

    for (int step = 0; step < CHL; step++, t += dt) {
        float x = xs[(size_t)t * (2 * DI)];
        float y0 = 0.f, y1 = 0.f;
#pragma unroll
        for (int k = 0; k < DS; k++) {
            h0[k] = fminf(fmaxf(fmaf(h0[k], A[k], x * B0r[k]), -10.f), 10.f);
            y0 = fmaf(h0[k], Cr[k], y0);
            h1[k] = fminf(fmaxf(fmaf(h1[k], A[k], x * B1r[k]), -10.f), 10.f);
            y1 = fmaf(h1[k], Cr[k], y1);
        }
        yo[(size_t)t * DI] = fmaf(w0, y0, w1 * y1);
    }
}

// ---------------- gated combine, bf16 output ----------------
__global__ void gated_combine() {
    int s = blockIdx.y;
    int idx = blockIdx.x * 256 + threadIdx.x;
    int i = idx & 1023;
    int n = idx >> 10;
    float g = d_xp[s][(size_t)n * (2 * DI) + DI + i];
    float sig = 1.f / (1.f + expf(-g));
    d_u[s][idx] = __float2bfloat16((d_y2[s][0][idx] + d_y2[s][1][idx]) * g * sig);
}

// ---------------- final: transpose + BN + residual + gate ----------------
__global__ void final_kernel(const float* __restrict__ x0, const float* __restrict__ x1,
                             float* __restrict__ out,
                             const float* __restrict__ g, const float* __restrict__ bb,
                             const float* __restrict__ m, const float* __restrict__ v,
                             const float* __restrict__ gatep) {
    __shared__ float tile[32][33];
    int s = blockIdx.z >> 2;
    int b = blockIdx.z & 3;
    int hw0 = blockIdx.x * 32, o0 = blockIdx.y * 32;
    int tx = threadIdx.x, ty = threadIdx.y;
    tile[ty][tx] = d_res[s][((size_t)b * LSEQ + hw0 + ty) * CIN + o0 + tx];
    __syncthreads();
    int o = o0 + ty, hw = hw0 + tx;
    float sc = g[o] * rsqrtf(v[o] + 1e-5f);
    float sh = bb[o] - m[o] * sc;
    float sg = 1.f / (1.f + expf(-gatep[0]));
    const float* xin = s ? x1 : x0;
    size_t pos = ((size_t)b * CIN + o) * LSEQ + hw;
    float val = tile[tx][ty] * sc + sh;
    out[(size_t)s * BSZ * CIN * LSEQ + pos] = xin[pos] + sg * val;
}

// ---------------- launch ----------------
extern "C" void kernel_launch(void* const* d_in, const int* in_sizes, int n_in,
                              void* d_out, int out_size) {
    const float* x_V        = (const float*)d_in[0];
    const float* x_I        = (const float*)d_in[1];
    const float* conv_red_w = (const float*)d_in[2];
    const float* bn_red_g   = (const float*)d_in[3];
    const float* bn_red_b   = (const float*)d_in[4];
    const float* bn_red_m   = (const float*)d_in[5];
    const float* bn_red_v   = (const float*)d_in[6];
    const float* conv_res_w = (const float*)d_in[7];
    const float* bn_res_g   = (const float*)d_in[8];
    const float* bn_res_b   = (const float*)d_in[9];
    const float* bn_res_m   = (const float*)d_in[10];
    const float* bn_res_v   = (const float*)d_in[11];
    const float* lam_w1     = (const float*)d_in[12];
    const float* lam_b1     = (const float*)d_in[13];
    const float* lam_w2     = (const float*)d_in[14];
    const float* lam_b2     = (const float*)d_in[15];
    const float* in_w[2]    = {(const float*)d_in[16], (const float*)d_in[23]};
    const float* out_w[2]   = {(const float*)d_in[17], (const float*)d_in[24]};
    const float* A_log[2]   = {(const float*)d_in[18], (const float*)d_in[25]};
    const float* Bmat[2]    = {(const float*)d_in[19], (const float*)d_in[26]};
    const float* Cmat[2]    = {(const float*)d_in[20], (const float*)d_in[27]};
    const float* ln_g[2]    = {(const float*)d_in[21], (const float*)d_in[28]};
    const float* ln_b[2]    = {(const float*)d_in[22], (const float*)d_in[29]};
    const float* gate       = (const float*)d_in[30];

    bf16 *XT, *XN, *U, *WT, *WC, *CRW, *CRSW, *INW;
    float *SEQ, *XP, *RES;
    cudaGetSymbolAddress((void**)&XT,   d_xt);
    cudaGetSymbolAddress((void**)&SEQ,  d_seq);
    cudaGetSymbolAddress((void**)&XN,   d_xn);
    cudaGetSymbolAddress((void**)&XP,   d_xp);
    cudaGetSymbolAddress((void**)&U,    d_u);
    cudaGetSymbolAddress((void**)&RES,  d_res);
    cudaGetSymbolAddress((void**)&WT,   d_wt);
    cudaGetSymbolAddress((void**)&WC,   d_wc);
    cudaGetSymbolAddress((void**)&CRW,  d_crw);
    cudaGetSymbolAddress((void**)&CRSW, d_crsw);
    cudaGetSymbolAddress((void**)&INW,  d_inw);

    cudaFuncSetAttribute(tgemm<0>, cudaFuncAttributeMaxDynamicSharedMemorySize, TG_SMEM);
    cudaFuncSetAttribute(tgemm<1>, cudaFuncAttributeMaxDynamicSharedMemorySize, TG_SMEM);
    cudaFuncSetAttribute(tgemm<2>, cudaFuncAttributeMaxDynamicSharedMemorySize, TG_SMEM);

    // 0. weight conversion + transposes
    prep_all<<<(PREP_N + 255) / 256, 256>>>(conv_red_w, conv_res_w, in_w[0], in_w[1]);
    transpose_in<<<dim3(32, 8, 8), dim3(32, 32)>>>(x_V, x_I);
    transpose_w<<<dim3(DI / 32, DM / 32, 2), dim3(32, 32)>>>(out_w[0], out_w[1]);

    // 1. Wc[z] = conv_res_w @ out_w[z]  (M=256, N=1024, K=512) -> bf16
    tgemm<2><<<dim3(DI / 128, CIN / 128, 2), 256, TG_SMEM>>>(
        CRSW, CRSW, WT, WT + (size_t)DI * DM, WC, CIN, DI, DM,
        (long long)CIN * DI, nullptr, nullptr, nullptr, nullptr);

    // 2. conv_red + BN + ReLU  (M=4096, N=512, K=256)
    tgemm<1><<<dim3(DM / 128, NTOK / 128, 2), 256, TG_SMEM>>>(
        XT, XT + (size_t)NTOK * CIN, CRW, CRW, SEQ, NTOK, DM, CIN,
        (long long)NTOK * DM, bn_red_g, bn_red_b, bn_red_m, bn_red_v);

    // 3. pool + lambda
    pool1_kernel<<<dim3(16, 8), 512>>>();
    pool2_kernel<<<8, 512>>>();
    lambda_kernel<<<4, 128>>>(lam_w1, lam_b1, lam_w2, lam_b2);

    // 4. layernorm + in_proj (M=4096, N=2048, K=512)
    ln_kernel<<<dim3(NTOK, 2), 128>>>(ln_g[0], ln_b[0], ln_g[1], ln_b[1]);
    tgemm<0><<<dim3(2 * DI / 128, NTOK / 128, 2), 256, TG_SMEM>>>(
        XN, XN + (size_t)NTOK * DM, INW, INW + (size_t)2 * DI * DM, XP, NTOK, 2 * DI, DM,
        (long long)NTOK * 2 * DI, nullptr, nullptr, nullptr, nullptr);

    // 5. chunked parallel scan
    scan_pass1<<<512, 256>>>(A_log[0], Bmat[0], A_log[1], Bmat[1]);
    scan_pass2<<<64, 256>>>(A_log[0], A_log[1]);
    scan_pass3<<<512, 256>>>(A_log[0], Bmat[0], Cmat[0], A_log[1], Bmat[1], Cmat[1]);

    // 6. gated combine
    gated_combine<<<dim3(NTOK * DI / 256, 2), 256>>>();

    // 7. fused out_proj + conv_res  (M=4096, N=256, K=1024)
    tgemm<0><<<dim3(CIN / 128, NTOK / 128, 2), 256, TG_SMEM>>>(
        U, U + (size_t)NTOK * DI, WC, WC + (size_t)CIN * DI, RES, NTOK, CIN, DI,
        (long long)NTOK * CIN, nullptr, nullptr, nullptr, nullptr);

    // 8. BN + residual + gate -> output
    final_kernel<<<dim3(32, 8, 8), dim3(32, 32)>>>(x_V, x_I, (float*)d_out,
                                                   bn_res_g, bn_res_b, bn_res_m,
                                                   bn_res_v, gate);
}

// round 7
// speedup vs baseline: 2.7726x; 1.0514x over previous
#include <cuda_runtime.h>
#include <cuda_bf16.h>
#include <math.h>
#include <stdint.h>

#define NS   2
#define BSZ  4
#define LSEQ 1024
#define NTOK 4096
#define DM   512
#define DI   1024
#define DS   16
#define CIN  256
#define NCH  8
#define CHL  128

typedef __nv_bfloat16 bf16;

// ---------------- scratch (static device globals; no runtime alloc) ----------------
__device__ bf16  d_xt[NS][NTOK * CIN];
__device__ float d_seq[NS][NTOK * DM];
__device__ float d_ppart[NS][16][BSZ * DM];
__device__ float d_pooled[NS][BSZ * DM];
__device__ float d_lam[BSZ * 2];
__device__ bf16  d_xn[NS][NTOK * DM];
__device__ float d_xp[NS][NTOK * 2 * DI];
__device__ float d_y2[NS][2][NTOK * DI];
__device__ bf16  d_u[NS][NTOK * DI];
__device__ float d_res[NS][NTOK * CIN];
__device__ bf16  d_wt[NS][DI * DM];
__device__ bf16  d_wc[NS][CIN * DI];
__device__ bf16  d_crw[DM * CIN];
__device__ bf16  d_crsw[CIN * DM];
__device__ bf16  d_inw[NS][2 * DI * DM];
__device__ float d_hfin[NS * 2 * BSZ * NCH * 2 * DS * 1024];

// ---------------- PTX helpers (baseline sm_80+) ----------------
__device__ __forceinline__ uint32_t smem_u32(const void* p) {
    uint32_t a;
    asm("{ .reg .u64 t; cvta.to.shared.u64 t, %1; cvt.u32.u64 %0, t; }" : "=r"(a) : "l"(p));
    return a;
}
#define CP_ASYNC16(sp, gp) \
    asm volatile("cp.async.cg.shared.global [%0], [%1], 16;" :: "r"(sp), "l"(gp) : "memory")
#define CP_COMMIT() asm volatile("cp.async.commit_group;" ::: "memory")
#define CP_WAIT1()  asm volatile("cp.async.wait_group 1;" ::: "memory")
#define CP_WAIT0()  asm volatile("cp.async.wait_group 0;" ::: "memory")

#define LDSM_X4(r0, r1, r2, r3, addr) \
    asm volatile("ldmatrix.sync.aligned.m8n8.x4.shared.b16 {%0,%1,%2,%3}, [%4];" \
                 : "=r"(r0), "=r"(r1), "=r"(r2), "=r"(r3) : "r"(addr))

#define MMA_BF16(d, a, b) \
    asm volatile("mma.sync.aligned.m16n8k16.row.col.f32.bf16.bf16.f32 " \
                 "{%0,%1,%2,%3}, {%4,%5,%6,%7}, {%8,%9}, {%0,%1,%2,%3};" \
                 : "+f"((d)[0]), "+f"((d)[1]), "+f"((d)[2]), "+f"((d)[3]) \
                 : "r"((a)[0]), "r"((a)[1]), "r"((a)[2]), "r"((a)[3]), \
                   "r"((b)[0]), "r"((b)[1]))

// ---------------- bf16 mma.sync GEMM: C[M,N] = A[M,K] * B[N,K]^T ----------------
// CTA tile 256x128, 8 warps (4 M x 2 N), warp tile 64x64, k-chunk 32,
// pitch 80B (conflict-free ldmatrix, aligned cp.async), double-buffered.
#define TG_PITCH   80
#define TG_MATA    (256 * TG_PITCH)      // 20480
#define TG_MATB    (128 * TG_PITCH)      // 10240
#define TG_STAGE_B (TG_MATA + TG_MATB)   // 30720
#define TG_SMEM    (2 * TG_STAGE_B)      // 61440

template <int EPI>   // 0 plain fp32, 1 BN+ReLU fp32, 2 bf16 output
__global__ void __launch_bounds__(256, 1)
tgemm(const bf16* __restrict__ A0, const bf16* __restrict__ A1,
      const bf16* __restrict__ B0, const bf16* __restrict__ B1,
      void* __restrict__ Cv, int M, int N, int K, long long sCz,
      const float* __restrict__ eg, const float* __restrict__ eb,
      const float* __restrict__ em, const float* __restrict__ ev) {
    extern __shared__ float smf[];
    const uint32_t sbase = smem_u32(smf);

    const int tid  = threadIdx.x;
    const int lane = tid & 31;
    const int wid  = tid >> 5;
    const int z = blockIdx.z;
    const bf16* __restrict__ A = z ? A1 : A0;
    const bf16* __restrict__ B = z ? B1 : B0;
    const int m0 = blockIdx.y * 256, n0 = blockIdx.x * 128;
    const int wm = (wid >> 1) * 64;
    const int wn = (wid & 1) * 64;

    const int lr = tid >> 2;     // 0..63
    const int lc = tid & 3;      // 16B seg

    auto load_stage = [&](int t) {
        const int k0 = t * 32;
        uint32_t dst = sbase + (t & 1) * TG_STAGE_B;
#pragma unroll
        for (int i = 0; i < 4; i++) {
            int m = lr + i * 64;
            CP_ASYNC16(dst + m * TG_PITCH + lc * 16, A + (size_t)(m0 + m) * K + k0 + lc * 8);
        }
        dst += TG_MATA;
#pragma unroll
        for (int i = 0; i < 2; i++) {
            int n = lr + i * 64;
            CP_ASYNC16(dst + n * TG_PITCH + lc * 16, B + (size_t)(n0 + n) * K + k0 + lc * 8);
        }
        CP_COMMIT();
    };

    float c[4][8][4];
#pragma unroll
    for (int mt = 0; mt < 4; mt++)
#pragma unroll
        for (int nt = 0; nt < 8; nt++)
#pragma unroll
            for (int q = 0; q < 4; q++) c[mt][nt][q] = 0.f;

    const int T = K / 32;
    load_stage(0);
    load_stage(1);

    const int l15   = lane & 15;
    const int lhiA  = (lane >> 4) * 16;
    const int bnrow = (lane & 7) + ((lane >> 4) << 3);
    const int bkoff = ((lane >> 3) & 1) * 16;

    for (int t = 0; t < T; t++) {
        if (t + 1 < T) { CP_WAIT1(); } else { CP_WAIT0(); }
        __syncthreads();
        const uint32_t aB = sbase + (t & 1) * TG_STAGE_B;
        const uint32_t bB = aB + TG_MATA;
#pragma unroll
        for (int kk = 0; kk < 2; kk++) {
            uint32_t a[4][4], b[8][2];
#pragma unroll
            for (int mt = 0; mt < 4; mt++) {
                uint32_t addr = aB + (wm + mt * 16 + l15) * TG_PITCH + kk * 32 + lhiA;
                LDSM_X4(a[mt][0], a[mt][1], a[mt][2], a[mt][3], addr);
            }
#pragma unroll
            for (int nh = 0; nh < 4; nh++) {
                uint32_t addr = bB + (wn + nh * 16 + bnrow) * TG_PITCH + kk * 32 + bkoff;
                uint32_t r0, r1, r2, r3;
                LDSM_X4(r0, r1, r2, r3, addr);
                b[nh * 2][0] = r0; b[nh * 2][1] = r1;
                b[nh * 2 + 1][0] = r2; b[nh * 2 + 1][1] = r3;
            }
#pragma unroll
            for (int mt = 0; mt < 4; mt++)
#pragma unroll
                for (int nt = 0; nt < 8; nt++)
                    MMA_BF16(c[mt][nt], a[mt], b[nt]);
        }
        __syncthreads();
        if (t + 2 < T) load_stage(t + 2);
    }

    const int gid = lane >> 2;
    const int tig = lane & 3;
#pragma unroll
    for (int mt = 0; mt < 4; mt++) {
        const int r0 = m0 + wm + mt * 16 + gid;
#pragma unroll
        for (int nt = 0; nt < 8; nt++) {
            const int col = n0 + wn + nt * 8 + tig * 2;
            float v0 = c[mt][nt][0], v1 = c[mt][nt][1];
            float v2 = c[mt][nt][2], v3 = c[mt][nt][3];
            if (EPI == 1) {
                float s0 = eg[col] * rsqrtf(ev[col] + 1e-5f);
                float h0 = eb[col] - em[col] * s0;
                float s1 = eg[col + 1] * rsqrtf(ev[col + 1] + 1e-5f);
                float h1 = eb[col + 1] - em[col + 1] * s1;
                v0 = fmaxf(v0 * s0 + h0, 0.f);
                v1 = fmaxf(v1 * s1 + h1, 0.f);
                v2 = fmaxf(v2 * s0 + h0, 0.f);
                v3 = fmaxf(v3 * s1 + h1, 0.f);
            }
            if (EPI == 2) {
                bf16* Cb = (bf16*)Cv + (size_t)z * sCz;
                *(__nv_bfloat162*)&Cb[(size_t)r0 * N + col] =
                    __floats2bfloat162_rn(v0, v1);
                *(__nv_bfloat162*)&Cb[(size_t)(r0 + 8) * N + col] =
                    __floats2bfloat162_rn(v2, v3);
            } else {
                float* Cf = (float*)Cv + (size_t)z * sCz;
                *(float2*)&Cf[(size_t)r0 * N + col]       = make_float2(v0, v1);
                *(float2*)&Cf[(size_t)(r0 + 8) * N + col] = make_float2(v2, v3);
            }
        }
    }
}

// ---------------- merged weight conversion fp32 -> bf16 ----------------
#define PREP_N (DM * CIN + CIN * DM + 2 * (2 * DI * DM))
__global__ void prep_all(const float* __restrict__ crw, const float* __restrict__ crsw,
                         const float* __restrict__ iw0, const float* __restrict__ iw1) {
    int i = blockIdx.x * 256 + threadIdx.x;
    const int n1 = DM * CIN, n2 = n1 + CIN * DM, n3 = n2 + 2 * DI * DM;
    if (i < n1)       d_crw[i]          = __float2bfloat16(crw[i]);
    else if (i < n2)  d_crsw[i - n1]    = __float2bfloat16(crsw[i - n1]);
    else if (i < n3)  d_inw[0][i - n2]  = __float2bfloat16(iw0[i - n2]);
    else if (i < PREP_N) d_inw[1][i - n3] = __float2bfloat16(iw1[i - n3]);
}

// ---------------- transpose x: (B,C,HW) -> (B*HW, C), bf16 ----------------
__global__ void transpose_in(const float* __restrict__ x0, const float* __restrict__ x1) {
    __shared__ float tile[32][33];
    int s = blockIdx.z >> 2, b = blockIdx.z & 3;
    const float* x = s ? x1 : x0;
    int hw0 = blockIdx.x * 32, c0 = blockIdx.y * 32;
    int tx = threadIdx.x, ty = threadIdx.y;
    tile[ty][tx] = x[((size_t)b * CIN + (c0 + ty)) * LSEQ + hw0 + tx];
    __syncthreads();
    d_xt[s][((size_t)b * LSEQ + hw0 + ty) * CIN + c0 + tx] = __float2bfloat16(tile[tx][ty]);
}

// ---------------- transpose out_w: [DM, DI] -> [DI, DM], bf16 ----------------
__global__ void transpose_w(const float* __restrict__ w0, const float* __restrict__ w1) {
    __shared__ float tile[32][33];
    int s = blockIdx.z;
    const float* w = s ? w1 : w0;
    int c0 = blockIdx.x * 32, r0 = blockIdx.y * 32;
    int tx = threadIdx.x, ty = threadIdx.y;
    tile[ty][tx] = w[(size_t)(r0 + ty) * DI + c0 + tx];
    __syncthreads();
    d_wt[s][(size_t)(c0 + ty) * DM + r0 + tx] = __float2bfloat16(tile[tx][ty]);
}

// ---------------- pool: two-stage over L ----------------
__global__ void pool1_kernel() {
    int s = blockIdx.y >> 2, b = blockIdx.y & 3, chunk = blockIdx.x;
    int d = threadIdx.x;
    const float* p = d_seq[s] + ((size_t)b * LSEQ + chunk * 64) * DM + d;
    float acc = 0.f;
#pragma unroll 8
    for (int l = 0; l < 64; l++) acc += p[(size_t)l * DM];
    d_ppart[s][chunk][b * DM + d] = acc;
}
__global__ void pool2_kernel() {
    int s = blockIdx.x >> 2, b = blockIdx.x & 3;
    int d = threadIdx.x;
    float acc = 0.f;
#pragma unroll
    for (int c = 0; c < 16; c++) acc += d_ppart[s][c][b * DM + d];
    d_pooled[s][b * DM + d] = acc * (1.0f / LSEQ);
}

// ---------------- lambda predictor ----------------
__global__ void lambda_kernel(const float* __restrict__ w1, const float* __restrict__ b1,
                              const float* __restrict__ w2, const float* __restrict__ b2) {
    int b = blockIdx.x, j = threadIdx.x;
    const float* pV = d_pooled[0] + b * DM;
    const float* pI = d_pooled[1] + b * DM;
    const float* w = w1 + (size_t)j * (2 * DM);
    float acc = b1[j];
    for (int c = 0; c < DM; c++) acc += pV[c] * w[c];
    for (int c = 0; c < DM; c++) acc += pI[c] * w[DM + c];
    __shared__ float h1[128];
    h1[j] = fmaxf(acc, 0.f);
    __syncthreads();
    if (j == 0) {
        float l0 = b2[0], l1 = b2[1];
        for (int c = 0; c < 128; c++) { l0 += h1[c] * w2[c]; l1 += h1[c] * w2[128 + c]; }
        float mx = fmaxf(l0, l1);
        float e0 = expf(l0 - mx), e1 = expf(l1 - mx);
        float inv = 1.f / (e0 + e1);
        d_lam[b * 2 + 0] = e0 * inv;
        d_lam[b * 2 + 1] = e1 * inv;
    }
}

// ---------------- LayerNorm over D=512, bf16 output ----------------
__global__ void ln_kernel(const float* __restrict__ g0, const float* __restrict__ b0,
                          const float* __restrict__ g1, const float* __restrict__ b1) {
    int s = blockIdx.y;
    const float* g = s ? g1 : g0;
    const float* b = s ? b1 : b0;
    int n = blockIdx.x, t = threadIdx.x;
    float4 v = ((const float4*)(d_seq[s] + (size_t)n * DM))[t];
    float sm = v.x + v.y + v.z + v.w;
    float sq = v.x * v.x + v.y * v.y + v.z * v.z + v.w * v.w;
#pragma unroll
    for (int o = 16; o; o >>= 1) {
        sm += __shfl_xor_sync(0xffffffffu, sm, o);
        sq += __shfl_xor_sync(0xffffffffu, sq, o);
    }
    __shared__ float ss[4], sqs[4];
    int w = t >> 5, ln = t & 31;
    if (ln == 0) { ss[w] = sm; sqs[w] = sq; }
    __syncthreads();
    sm = ss[0] + ss[1] + ss[2] + ss[3];
    sq = sqs[0] + sqs[1] + sqs[2] + sqs[3];
    float mu = sm * (1.f / DM);
    float var = sq * (1.f / DM) - mu * mu;
    float inv = rsqrtf(var + 1e-5f);
    float4 gg = ((const float4*)g)[t];
    float4 bb = ((const float4*)b)[t];
    __nv_bfloat162* dst = (__nv_bfloat162*)(d_xn[s] + (size_t)n * DM);
    dst[2 * t]     = __floats2bfloat162_rn((v.x - mu) * inv * gg.x + bb.x,
                                           (v.y - mu) * inv * gg.y + bb.y);
    dst[2 * t + 1] = __floats2bfloat162_rn((v.z - mu) * inv * gg.z + bb.z,
                                           (v.w - mu) * inv * gg.w + bb.w);
}

// ================= chunked parallel scan (clip provably non-binding -> dropped) =================
__device__ __forceinline__ size_t hf_off(int s, int dir, int b, int c, int var, int i) {
    return ((((((size_t)s * 2 + dir) * 4 + b) * NCH + c) * 2 + var) * DS) * 1024 + i;
}

__global__ void __launch_bounds__(256)
scan_pass1(const float* __restrict__ VA, const float* __restrict__ VB,
           const float* __restrict__ IA, const float* __restrict__ IB) {
    int idx = blockIdx.x * 256 + threadIdx.x;
    int i   = idx & 1023;
    int c   = (idx >> 10) & 7;
    int b   = (idx >> 13) & 3;
    int dir = (idx >> 15) & 1;
    int s   = (idx >> 16) & 1;

    const float* Alog = s ? IA : VA;
    const float* Bown = s ? IB : VB;
    const float* Both = s ? VB : IB;

    float A[DS], B0r[DS], B1r[DS], h0[DS], h1[DS];
#pragma unroll
    for (int k = 0; k < DS; k++) {
        A[k]   = fminf(fmaxf(-expf(Alog[i * DS + k]), -10.f), -0.01f);
        B0r[k] = Bown[i * DS + k];
        B1r[k] = Both[i * DS + k];
        h0[k] = 0.f; h1[k] = 0.f;
    }

    const float* xs = d_xp[s] + (size_t)b * LSEQ * (2 * DI) + i;
    int t  = dir ? (LSEQ - 1 - c * CHL) : c * CHL;
    int dt = dir ? -1 : 1;

    for (int step = 0; step < CHL; step++, t += dt) {
        float x = xs[(size_t)t * (2 * DI)];
#pragma unroll
        for (int k = 0; k < DS; k++) {
            h0[k] = fmaf(h0[k], A[k], x * B0r[k]);
            h1[k] = fmaf(h1[k], A[k], x * B1r[k]);
        }
    }

    size_t o0 = hf_off(s, dir, b, c, 0, i);
    size_t o1 = hf_off(s, dir, b, c, 1, i);
#pragma unroll
    for (int k = 0; k < DS; k++) {
        d_hfin[o0 + (size_t)k * 1024] = h0[k];
        d_hfin[o1 + (size_t)k * 1024] = h1[k];
    }
}

__global__ void __launch_bounds__(256)
scan_pass2(const float* __restrict__ VA, const float* __restrict__ IA) {
    int idx = blockIdx.x * 256 + threadIdx.x;
    int i   = idx & 1023;
    int b   = (idx >> 10) & 3;
    int dir = (idx >> 12) & 1;
    int s   = (idx >> 13) & 1;

    const float* Alog = s ? IA : VA;
    float a128[DS];
#pragma unroll
    for (int k = 0; k < DS; k++) {
        float a = fminf(fmaxf(-expf(Alog[i * DS + k]), -10.f), -0.01f);
#pragma unroll
        for (int q = 0; q < 7; q++) a = a * a;
        a128[k] = a;
    }

    const size_t cstride = (size_t)2 * DS * 1024;
#pragma unroll
    for (int var = 0; var < 2; var++) {
        size_t base = hf_off(s, dir, b, 0, var, i);
        float hin[DS];
#pragma unroll
        for (int k = 0; k < DS; k++) hin[k] = 0.f;
        for (int c = 0; c < NCH; c++) {
            size_t o = base + c * cstride;
#pragma unroll
            for (int k = 0; k < DS; k++) {
                float fin = d_hfin[o + (size_t)k * 1024];
                d_hfin[o + (size_t)k * 1024] = hin[k];
                hin[k] = fmaf(a128[k], hin[k], fin);
            }
        }
    }
}

__global__ void __launch_bounds__(256)
scan_pass3(const float* __restrict__ VA, const float* __restrict__ VB,
           const float* __restrict__ VC, const float* __restrict__ IA,
           const float* __restrict__ IB, const float* __restrict__ IC) {
    int idx = blockIdx.x * 256 + threadIdx.x;
    int i   = idx & 1023;
    int c   = (idx >> 10) & 7;
    int b   = (idx >> 13) & 3;
    int dir = (idx >> 15) & 1;
    int s   = (idx >> 16) & 1;

    const float* Alog = s ? IA : VA;
    const float* Bown = s ? IB : VB;
    const float* Both = s ? VB : IB;
    const float* Cp   = s ? IC : VC;
    float w0 = 0.5f * d_lam[b * 2 + 0];
    float w1 = 0.5f * d_lam[b * 2 + 1];

    float A[DS], B0r[DS], B1r[DS], Cr[DS], h0[DS], h1[DS];
    size_t o0 = hf_off(s, dir, b, c, 0, i);
    size_t o1 = hf_off(s, dir, b, c, 1, i);
#pragma unroll
    for (int k = 0; k < DS; k++) {
        A[k]   = fminf(fmaxf(-expf(Alog[i * DS + k]), -10.f), -0.01f);
        B0r[k] = Bown[i * DS + k];
        B1r[k] = Both[i * DS + k];
        Cr[k]  = Cp[i * DS + k];
        h0[k]  = d_hfin[o0 + (size_t)k * 1024];
        h1[k]  = d_hfin[o1 + (size_t)k * 1024];
    }

    const float* xs = d_xp[s] + (size_t)b * LSEQ * (2 * DI) + i;
    float* yo = d_y2[s][dir] + (size_t)b * LSEQ * DI + i;
    int t  = dir ? (LSEQ - 1 - c * CHL) : c * CHL;
    int dt = dir ? -1 : 1;

    for (int step = 0; step < CHL; step++, t += dt) {
        float x = xs[(size_t)t * (2 * DI)];
        float y0 = 0.f, y1 = 0.f;
#pragma unroll
        for (int k = 0; k < DS; k++) {
            h0[k] = fmaf(h0[k], A[k], x * B0r[k]);
            y0 = fmaf(h0[k], Cr[k], y0);
            h1[k] = fmaf(h1[k], A[k], x * B1r[k]);
            y1 = fmaf(h1[k], Cr[k], y1);
        }
        yo[(size_t)t * DI] = fmaf(w0, y0, w1 * y1);
    }
}

// ---------------- gated combine, bf16 output ----------------
__global__ void gated_combine() {
    int s = blockIdx.y;
    int idx = blockIdx.x * 256 + threadIdx.x;
    int i = idx & 1023;
    int n = idx >> 10;
    float g = d_xp[s][(size_t)n * (2 * DI) + DI + i];
    float sig = 1.f / (1.f + expf(-g));
    d_u[s][idx] = __float2bfloat16((d_y2[s][0][idx] + d_y2[s][1][idx]) * g * sig);
}

// ---------------- final: transpose + BN + residual + gate ----------------
__global__ void final_kernel(const float* __restrict__ x0, const float* __restrict__ x1,
                             float* __restrict__ out,
                             const float* __restrict__ g, const float* __restrict__ bb,
                             const float* __restrict__ m, const float* __restrict__ v,
                             const float* __restrict__ gatep) {
    __shared__ float tile[32][33];
    int s = blockIdx.z >> 2;
    int b = blockIdx.z & 3;
    int hw0 = blockIdx.x * 32, o0 = blockIdx.y * 32;
    int tx = threadIdx.x, ty = threadIdx.y;
    tile[ty][tx] = d_res[s][((size_t)b * LSEQ + hw0 + ty) * CIN + o0 + tx];
    __syncthreads();
    int o = o0 + ty, hw = hw0 + tx;
    float sc = g[o] * rsqrtf(v[o] + 1e-5f);
    float sh = bb[o] - m[o] * sc;
    float sg = 1.f / (1.f + expf(-gatep[0]));
    const float* xin = s ? x1 : x0;
    size_t pos = ((size_t)b * CIN + o) * LSEQ + hw;
    float val = tile[tx][ty] * sc + sh;
    out[(size_t)s * BSZ * CIN * LSEQ + pos] = xin[pos] + sg * val;
}

// ---------------- launch ----------------
extern "C" void kernel_launch(void* const* d_in, const int* in_sizes, int n_in,
                              void* d_out, int out_size) {
    const float* x_V        = (const float*)d_in[0];
    const float* x_I        = (const float*)d_in[1];
    const float* conv_red_w = (const float*)d_in[2];
    const float* bn_red_g   = (const float*)d_in[3];
    const float* bn_red_b   = (const float*)d_in[4];
    const float* bn_red_m   = (const float*)d_in[5];
    const float* bn_red_v   = (const float*)d_in[6];
    const float* conv_res_w = (const float*)d_in[7];
    const float* bn_res_g   = (const float*)d_in[8];
    const float* bn_res_b   = (const float*)d_in[9];
    const float* bn_res_m   = (const float*)d_in[10];
    const float* bn_res_v   = (const float*)d_in[11];
    const float* lam_w1     = (const float*)d_in[12];
    const float* lam_b1     = (const float*)d_in[13];
    const float* lam_w2     = (const float*)d_in[14];
    const float* lam_b2     = (const float*)d_in[15];
    const float* in_w[2]    = {(const float*)d_in[16], (const float*)d_in[23]};
    const float* out_w[2]   = {(const float*)d_in[17], (const float*)d_in[24]};
    const float* A_log[2]   = {(const float*)d_in[18], (const float*)d_in[25]};
    const float* Bmat[2]    = {(const float*)d_in[19], (const float*)d_in[26]};
    const float* Cmat[2]    = {(const float*)d_in[20], (const float*)d_in[27]};
    const float* ln_g[2]    = {(const float*)d_in[21], (const float*)d_in[28]};
    const float* ln_b[2]    = {(const float*)d_in[22], (const float*)d_in[29]};
    const float* gate       = (const float*)d_in[30];

    bf16 *XT, *XN, *U, *WT, *WC, *CRW, *CRSW, *INW;
    float *SEQ, *XP, *RES;
    cudaGetSymbolAddress((void**)&XT,   d_xt);
    cudaGetSymbolAddress((void**)&SEQ,  d_seq);
    cudaGetSymbolAddress((void**)&XN,   d_xn);
    cudaGetSymbolAddress((void**)&XP,   d_xp);
    cudaGetSymbolAddress((void**)&U,    d_u);
    cudaGetSymbolAddress((void**)&RES,  d_res);
    cudaGetSymbolAddress((void**)&WT,   d_wt);
    cudaGetSymbolAddress((void**)&WC,   d_wc);
    cudaGetSymbolAddress((void**)&CRW,  d_crw);
    cudaGetSymbolAddress((void**)&CRSW, d_crsw);
    cudaGetSymbolAddress((void**)&INW,  d_inw);

    cudaFuncSetAttribute(tgemm<0>, cudaFuncAttributeMaxDynamicSharedMemorySize, TG_SMEM);
    cudaFuncSetAttribute(tgemm<1>, cudaFuncAttributeMaxDynamicSharedMemorySize, TG_SMEM);
    cudaFuncSetAttribute(tgemm<2>, cudaFuncAttributeMaxDynamicSharedMemorySize, TG_SMEM);

    // 0. weight conversion + transposes
    prep_all<<<(PREP_N + 255) / 256, 256>>>(conv_red_w, conv_res_w, in_w[0], in_w[1]);
    transpose_in<<<dim3(32, 8, 8), dim3(32, 32)>>>(x_V, x_I);
    transpose_w<<<dim3(DI / 32, DM / 32, 2), dim3(32, 32)>>>(out_w[0], out_w[1]);

    // 1. Wc[z] = conv_res_w @ out_w[z]  (M=256, N=1024, K=512) -> bf16
    tgemm<2><<<dim3(DI / 128, CIN / 256, 2), 256, TG_SMEM>>>(
        CRSW, CRSW, WT, WT + (size_t)DI * DM, WC, CIN, DI, DM,
        (long long)CIN * DI, nullptr, nullptr, nullptr, nullptr);

    // 2. conv_red + BN + ReLU  (M=4096, N=512, K=256)
    tgemm<1><<<dim3(DM / 128, NTOK / 256, 2), 256, TG_SMEM>>>(
        XT, XT + (size_t)NTOK * CIN, CRW, CRW, SEQ, NTOK, DM, CIN,
        (long long)NTOK * DM, bn_red_g, bn_red_b, bn_red_m, bn_red_v);

    // 3. pool + lambda
    pool1_kernel<<<dim3(16, 8), 512>>>();
    pool2_kernel<<<8, 512>>>();
    lambda_kernel<<<4, 128>>>(lam_w1, lam_b1, lam_w2, lam_b2);

    // 4. layernorm + in_proj (M=4096, N=2048, K=512)
    ln_kernel<<<dim3(NTOK, 2), 128>>>(ln_g[0], ln_b[0], ln_g[1], ln_b[1]);
    tgemm<0><<<dim3(2 * DI / 128, NTOK / 256, 2), 256, TG_SMEM>>>(
        XN, XN + (size_t)NTOK * DM, INW, INW + (size_t)2 * DI * DM, XP, NTOK, 2 * DI, DM,
        (long long)NTOK * 2 * DI, nullptr, nullptr, nullptr, nullptr);

    // 5. chunked parallel scan
    scan_pass1<<<512, 256>>>(A_log[0], Bmat[0], A_log[1], Bmat[1]);
    scan_pass2<<<64, 256>>>(A_log[0], A_log[1]);
    scan_pass3<<<512, 256>>>(A_log[0], Bmat[0], Cmat[0], A_log[1], Bmat[1], Cmat[1]);

    // 6. gated combine
    gated_combine<<<dim3(NTOK * DI / 256, 2), 256>>>();

    // 7. fused out_proj + conv_res  (M=4096, N=256, K=1024)
    tgemm<0><<<dim3(CIN / 128, NTOK / 256, 2), 256, TG_SMEM>>>(
        U, U + (size_t)NTOK * DI, WC, WC + (size_t)CIN * DI, RES, NTOK, CIN, DI,
        (long long)NTOK * CIN, nullptr, nullptr, nullptr, nullptr);

    // 8. BN + residual + gate -> output
    final_kernel<<<dim3(32, 8, 8), dim3(32, 32)>>>(x_V, x_I, (float*)d_out,
                                                   bn_res_g, bn_res_b, bn_res_m,
                                                   bn_res_v, gate);
}

// round 8
// speedup vs baseline: 3.2425x; 1.1695x over previous
#include <cuda_runtime.h>
#include <cuda_bf16.h>
#include <math.h>
#include <stdint.h>

#define NS   2
#define BSZ  4
#define LSEQ 1024
#define NTOK 4096
#define DM   512
#define DI   1024
#define DS   16
#define CIN  256
#define NCH  8
#define CHL  128

typedef __nv_bfloat16 bf16;
typedef unsigned long long u64;

// ---------------- scratch (static device globals; no runtime alloc) ----------------
__device__ bf16  d_xt[NS][NTOK * CIN];
__device__ float d_seq[NS][NTOK * DM];
__device__ float d_ppart[NS][16][BSZ * DM];
__device__ float d_lam[BSZ * 2];
__device__ bf16  d_xn[NS][NTOK * DM];
__device__ bf16  d_xp[NS][NTOK * 2 * DI];     // in_proj out, bf16
__device__ bf16  d_y2[NS][2][NTOK * DI];      // scan out, bf16
__device__ bf16  d_u[NS][NTOK * DI];
__device__ float d_res[NS][NTOK * CIN];
__device__ bf16  d_wt[NS][DI * DM];
__device__ bf16  d_wc[NS][CIN * DI];
__device__ bf16  d_crw[DM * CIN];
__device__ bf16  d_crsw[CIN * DM];
__device__ bf16  d_inw[NS][2 * DI * DM];
__device__ float d_hfin[NS * 2 * BSZ * NCH * 2 * DS * 1024];

// ---------------- PTX helpers ----------------
__device__ __forceinline__ uint32_t smem_u32(const void* p) {
    uint32_t a;
    asm("{ .reg .u64 t; cvta.to.shared.u64 t, %1; cvt.u32.u64 %0, t; }" : "=r"(a) : "l"(p));
    return a;
}
#define CP_ASYNC16(sp, gp) \
    asm volatile("cp.async.cg.shared.global [%0], [%1], 16;" :: "r"(sp), "l"(gp) : "memory")
#define CP_COMMIT() asm volatile("cp.async.commit_group;" ::: "memory")
#define CP_WAIT1()  asm volatile("cp.async.wait_group 1;" ::: "memory")
#define CP_WAIT0()  asm volatile("cp.async.wait_group 0;" ::: "memory")

#define LDSM_X4(r0, r1, r2, r3, addr) \
    asm volatile("ldmatrix.sync.aligned.m8n8.x4.shared.b16 {%0,%1,%2,%3}, [%4];" \
                 : "=r"(r0), "=r"(r1), "=r"(r2), "=r"(r3) : "r"(addr))

#define MMA_BF16(d, a, b) \
    asm volatile("mma.sync.aligned.m16n8k16.row.col.f32.bf16.bf16.f32 " \
                 "{%0,%1,%2,%3}, {%4,%5,%6,%7}, {%8,%9}, {%0,%1,%2,%3};" \
                 : "+f"((d)[0]), "+f"((d)[1]), "+f"((d)[2]), "+f"((d)[3]) \
                 : "r"((a)[0]), "r"((a)[1]), "r"((a)[2]), "r"((a)[3]), \
                   "r"((b)[0]), "r"((b)[1]))

// packed fp32x2 (proven to compile for this target in round 2)
__device__ __forceinline__ u64 fma2_(u64 a, u64 b, u64 c) {
    u64 d;
    asm("fma.rn.f32x2 %0, %1, %2, %3;" : "=l"(d) : "l"(a), "l"(b), "l"(c));
    return d;
}
__device__ __forceinline__ u64 pack2(float lo, float hi) {
    u64 r;
    asm("mov.b64 %0, {%1, %2};" : "=l"(r) : "f"(lo), "f"(hi));
    return r;
}
__device__ __forceinline__ float2 unpack2(u64 v) {
    float2 f;
    asm("mov.b64 {%0, %1}, %2;" : "=f"(f.x), "=f"(f.y) : "l"(v));
    return f;
}

// ---------------- bf16 mma.sync GEMM: C[M,N] = A[M,K] * B[N,K]^T ----------------
// CTA 256x128, 8 warps (4Mx2N), warp tile 64x64, k-chunk 32, pitch 80B, dbl-buffered.
#define TG_PITCH   80
#define TG_MATA    (256 * TG_PITCH)
#define TG_MATB    (128 * TG_PITCH)
#define TG_STAGE_B (TG_MATA + TG_MATB)
#define TG_SMEM    (2 * TG_STAGE_B)

template <int EPI>   // 0 plain fp32, 1 BN+ReLU fp32, 2 bf16 output
__global__ void __launch_bounds__(256, 1)
tgemm(const bf16* __restrict__ A0, const bf16* __restrict__ A1,
      const bf16* __restrict__ B0, const bf16* __restrict__ B1,
      void* __restrict__ Cv, int M, int N, int K, long long sCz,
      const float* __restrict__ eg, const float* __restrict__ eb,
      const float* __restrict__ em, const float* __restrict__ ev) {
    extern __shared__ float smf[];
    const uint32_t sbase = smem_u32(smf);

    const int tid  = threadIdx.x;
    const int lane = tid & 31;
    const int wid  = tid >> 5;
    const int z = blockIdx.z;
    const bf16* __restrict__ A = z ? A1 : A0;
    const bf16* __restrict__ B = z ? B1 : B0;
    const int m0 = blockIdx.y * 256, n0 = blockIdx.x * 128;
    const int wm = (wid >> 1) * 64;
    const int wn = (wid & 1) * 64;

    const int lr = tid >> 2;
    const int lc = tid & 3;

    auto load_stage = [&](int t) {
        const int k0 = t * 32;
        uint32_t dst = sbase + (t & 1) * TG_STAGE_B;
#pragma unroll
        for (int i = 0; i < 4; i++) {
            int m = lr + i * 64;
            CP_ASYNC16(dst + m * TG_PITCH + lc * 16, A + (size_t)(m0 + m) * K + k0 + lc * 8);
        }
        dst += TG_MATA;
#pragma unroll
        for (int i = 0; i < 2; i++) {
            int n = lr + i * 64;
            CP_ASYNC16(dst + n * TG_PITCH + lc * 16, B + (size_t)(n0 + n) * K + k0 + lc * 8);
        }
        CP_COMMIT();
    };

    float c[4][8][4];
#pragma unroll
    for (int mt = 0; mt < 4; mt++)
#pragma unroll
        for (int nt = 0; nt < 8; nt++)
#pragma unroll
            for (int q = 0; q < 4; q++) c[mt][nt][q] = 0.f;

    const int T = K / 32;
    load_stage(0);
    load_stage(1);

    const int l15   = lane & 15;
    const int lhiA  = (lane >> 4) * 16;
    const int bnrow = (lane & 7) + ((lane >> 4) << 3);
    const int bkoff = ((lane >> 3) & 1) * 16;

    for (int t = 0; t < T; t++) {
        if (t + 1 < T) { CP_WAIT1(); } else { CP_WAIT0(); }
        __syncthreads();
        const uint32_t aB = sbase + (t & 1) * TG_STAGE_B;
        const uint32_t bB = aB + TG_MATA;
#pragma unroll
        for (int kk = 0; kk < 2; kk++) {
            uint32_t a[4][4], b[8][2];
#pragma unroll
            for (int mt = 0; mt < 4; mt++) {
                uint32_t addr = aB + (wm + mt * 16 + l15) * TG_PITCH + kk * 32 + lhiA;
                LDSM_X4(a[mt][0], a[mt][1], a[mt][2], a[mt][3], addr);
            }
#pragma unroll
            for (int nh = 0; nh < 4; nh++) {
                uint32_t addr = bB + (wn + nh * 16 + bnrow) * TG_PITCH + kk * 32 + bkoff;
                uint32_t r0, r1, r2, r3;
                LDSM_X4(r0, r1, r2, r3, addr);
                b[nh * 2][0] = r0; b[nh * 2][1] = r1;
                b[nh * 2 + 1][0] = r2; b[nh * 2 + 1][1] = r3;
            }
#pragma unroll
            for (int mt = 0; mt < 4; mt++)
#pragma unroll
                for (int nt = 0; nt < 8; nt++)
                    MMA_BF16(c[mt][nt], a[mt], b[nt]);
        }
        __syncthreads();
        if (t + 2 < T) load_stage(t + 2);
    }

    const int gid = lane >> 2;
    const int tig = lane & 3;
#pragma unroll
    for (int mt = 0; mt < 4; mt++) {
        const int r0 = m0 + wm + mt * 16 + gid;
#pragma unroll
        for (int nt = 0; nt < 8; nt++) {
            const int col = n0 + wn + nt * 8 + tig * 2;
            float v0 = c[mt][nt][0], v1 = c[mt][nt][1];
            float v2 = c[mt][nt][2], v3 = c[mt][nt][3];
            if (EPI == 1) {
                float s0 = eg[col] * rsqrtf(ev[col] + 1e-5f);
                float h0 = eb[col] - em[col] * s0;
                float s1 = eg[col + 1] * rsqrtf(ev[col + 1] + 1e-5f);
                float h1 = eb[col + 1] - em[col + 1] * s1;
                v0 = fmaxf(v0 * s0 + h0, 0.f);
                v1 = fmaxf(v1 * s1 + h1, 0.f);
                v2 = fmaxf(v2 * s0 + h0, 0.f);
                v3 = fmaxf(v3 * s1 + h1, 0.f);
            }
            if (EPI == 2) {
                bf16* Cb = (bf16*)Cv + (size_t)z * sCz;
                *(__nv_bfloat162*)&Cb[(size_t)r0 * N + col] =
                    __floats2bfloat162_rn(v0, v1);
                *(__nv_bfloat162*)&Cb[(size_t)(r0 + 8) * N + col] =
                    __floats2bfloat162_rn(v2, v3);
            } else {
                float* Cf = (float*)Cv + (size_t)z * sCz;
                *(float2*)&Cf[(size_t)r0 * N + col]       = make_float2(v0, v1);
                *(float2*)&Cf[(size_t)(r0 + 8) * N + col] = make_float2(v2, v3);
            }
        }
    }
}

// ---------------- merged weight conversion fp32 -> bf16 ----------------
#define PREP_N (DM * CIN + CIN * DM + 2 * (2 * DI * DM))
__global__ void prep_all(const float* __restrict__ crw, const float* __restrict__ crsw,
                         const float* __restrict__ iw0, const float* __restrict__ iw1) {
    int i = blockIdx.x * 256 + threadIdx.x;
    const int n1 = DM * CIN, n2 = n1 + CIN * DM, n3 = n2 + 2 * DI * DM;
    if (i < n1)       d_crw[i]          = __float2bfloat16(crw[i]);
    else if (i < n2)  d_crsw[i - n1]    = __float2bfloat16(crsw[i - n1]);
    else if (i < n3)  d_inw[0][i - n2]  = __float2bfloat16(iw0[i - n2]);
    else if (i < PREP_N) d_inw[1][i - n3] = __float2bfloat16(iw1[i - n3]);
}

// ---------------- transpose x: (B,C,HW) -> (B*HW, C), bf16 ----------------
__global__ void transpose_in(const float* __restrict__ x0, const float* __restrict__ x1) {
    __shared__ float tile[32][33];
    int s = blockIdx.z >> 2, b = blockIdx.z & 3;
    const float* x = s ? x1 : x0;
    int hw0 = blockIdx.x * 32, c0 = blockIdx.y * 32;
    int tx = threadIdx.x, ty = threadIdx.y;
    tile[ty][tx] = x[((size_t)b * CIN + (c0 + ty)) * LSEQ + hw0 + tx];
    __syncthreads();
    d_xt[s][((size_t)b * LSEQ + hw0 + ty) * CIN + c0 + tx] = __float2bfloat16(tile[tx][ty]);
}

// ---------------- transpose out_w: [DM, DI] -> [DI, DM], bf16 ----------------
__global__ void transpose_w(const float* __restrict__ w0, const float* __restrict__ w1) {
    __shared__ float tile[32][33];
    int s = blockIdx.z;
    const float* w = s ? w1 : w0;
    int c0 = blockIdx.x * 32, r0 = blockIdx.y * 32;
    int tx = threadIdx.x, ty = threadIdx.y;
    tile[ty][tx] = w[(size_t)(r0 + ty) * DI + c0 + tx];
    __syncthreads();
    d_wt[s][(size_t)(c0 + ty) * DM + r0 + tx] = __float2bfloat16(tile[tx][ty]);
}

// ---------------- pool stage 1 ----------------
__global__ void pool1_kernel() {
    int s = blockIdx.y >> 2, b = blockIdx.y & 3, chunk = blockIdx.x;
    int d = threadIdx.x;
    const float* p = d_seq[s] + ((size_t)b * LSEQ + chunk * 64) * DM + d;
    float acc = 0.f;
#pragma unroll 8
    for (int l = 0; l < 64; l++) acc += p[(size_t)l * DM];
    d_ppart[s][chunk][b * DM + d] = acc;
}

// ---------------- lambda predictor (pool stage 2 merged in) ----------------
__global__ void lambda_kernel(const float* __restrict__ w1, const float* __restrict__ b1,
                              const float* __restrict__ w2, const float* __restrict__ b2) {
    int b = blockIdx.x, j = threadIdx.x;
    __shared__ float pooled[2 * DM];
    for (int idx = j; idx < 2 * DM; idx += 128) {
        int s = idx >> 9, d = idx & (DM - 1);
        float acc = 0.f;
#pragma unroll
        for (int c = 0; c < 16; c++) acc += d_ppart[s][c][b * DM + d];
        pooled[idx] = acc * (1.0f / LSEQ);
    }
    __syncthreads();
    const float* w = w1 + (size_t)j * (2 * DM);
    float acc = b1[j];
    for (int c = 0; c < DM; c++) acc += pooled[c] * w[c];
    for (int c = 0; c < DM; c++) acc += pooled[DM + c] * w[DM + c];
    __shared__ float h1[128];
    h1[j] = fmaxf(acc, 0.f);
    __syncthreads();
    if (j == 0) {
        float l0 = b2[0], l1 = b2[1];
        for (int c = 0; c < 128; c++) { l0 += h1[c] * w2[c]; l1 += h1[c] * w2[128 + c]; }
        float mx = fmaxf(l0, l1);
        float e0 = expf(l0 - mx), e1 = expf(l1 - mx);
        float inv = 1.f / (e0 + e1);
        d_lam[b * 2 + 0] = e0 * inv;
        d_lam[b * 2 + 1] = e1 * inv;
    }
}

// ---------------- LayerNorm over D=512, bf16 output ----------------
__global__ void ln_kernel(const float* __restrict__ g0, const float* __restrict__ b0,
                          const float* __restrict__ g1, const float* __restrict__ b1) {
    int s = blockIdx.y;
    const float* g = s ? g1 : g0;
    const float* b = s ? b1 : b0;
    int n = blockIdx.x, t = threadIdx.x;
    float4 v = ((const float4*)(d_seq[s] + (size_t)n * DM))[t];
    float sm = v.x + v.y + v.z + v.w;
    float sq = v.x * v.x + v.y * v.y + v.z * v.z + v.w * v.w;
#pragma unroll
    for (int o = 16; o; o >>= 1) {
        sm += __shfl_xor_sync(0xffffffffu, sm, o);
        sq += __shfl_xor_sync(0xffffffffu, sq, o);
    }
    __shared__ float ss[4], sqs[4];
    int w = t >> 5, ln = t & 31;
    if (ln == 0) { ss[w] = sm; sqs[w] = sq; }
    __syncthreads();
    sm = ss[0] + ss[1] + ss[2] + ss[3];
    sq = sqs[0] + sqs[1] + sqs[2] + sqs[3];
    float mu = sm * (1.f / DM);
    float var = sq * (1.f / DM) - mu * mu;
    float inv = rsqrtf(var + 1e-5f);
    float4 gg = ((const float4*)g)[t];
    float4 bb = ((const float4*)b)[t];
    __nv_bfloat162* dst = (__nv_bfloat162*)(d_xn[s] + (size_t)n * DM);
    dst[2 * t]     = __floats2bfloat162_rn((v.x - mu) * inv * gg.x + bb.x,
                                           (v.y - mu) * inv * gg.y + bb.y);
    dst[2 * t + 1] = __floats2bfloat162_rn((v.z - mu) * inv * gg.z + bb.z,
                                           (v.w - mu) * inv * gg.w + bb.w);
}

// ================= chunked parallel scan, packed f32x2 =================
__device__ __forceinline__ size_t hf_off(int s, int dir, int b, int c, int var, int i) {
    return ((((((size_t)s * 2 + dir) * 4 + b) * NCH + c) * 2 + var) * DS) * 1024 + i;
}

__global__ void __launch_bounds__(256)
scan_pass1(const float* __restrict__ VA, const float* __restrict__ VB,
           const float* __restrict__ IA, const float* __restrict__ IB) {
    int idx = blockIdx.x * 256 + threadIdx.x;
    int i   = idx & 1023;
    int c   = (idx >> 10) & 7;
    int b   = (idx >> 13) & 3;
    int dir = (idx >> 15) & 1;
    int s   = (idx >> 16) & 1;

    const float* Alog = s ? IA : VA;
    const float* Bown = s ? IB : VB;
    const float* Both = s ? VB : IB;

    u64 A2[8], B02[8], B12[8], h02[8], h12[8];
#pragma unroll
    for (int k = 0; k < 8; k++) {
        float a0 = fminf(fmaxf(-expf(Alog[i * DS + 2 * k]),     -10.f), -0.01f);
        float a1 = fminf(fmaxf(-expf(Alog[i * DS + 2 * k + 1]), -10.f), -0.01f);
        A2[k]  = pack2(a0, a1);
        B02[k] = pack2(Bown[i * DS + 2 * k], Bown[i * DS + 2 * k + 1]);
        B12[k] = pack2(Both[i * DS + 2 * k], Both[i * DS + 2 * k + 1]);
        h02[k] = 0ull; h12[k] = 0ull;
    }

    const bf16* xs = d_xp[s] + (size_t)b * LSEQ * (2 * DI) + i;
    int t  = dir ? (LSEQ - 1 - c * CHL) : c * CHL;
    int dt = dir ? -1 : 1;

    for (int step = 0; step < CHL; step++, t += dt) {
        float x = __bfloat162float(xs[(size_t)t * (2 * DI)]);
        u64 xd = pack2(x, x);
#pragma unroll
        for (int k = 0; k < 8; k++) {
            h02[k] = fma2_(h02[k], A2[k], fma2_(B02[k], xd, 0ull));
            h12[k] = fma2_(h12[k], A2[k], fma2_(B12[k], xd, 0ull));
        }
    }

    size_t o0 = hf_off(s, dir, b, c, 0, i);
    size_t o1 = hf_off(s, dir, b, c, 1, i);
#pragma unroll
    for (int k = 0; k < 8; k++) {
        float2 f0 = unpack2(h02[k]), f1 = unpack2(h12[k]);
        d_hfin[o0 + (size_t)(2 * k) * 1024]     = f0.x;
        d_hfin[o0 + (size_t)(2 * k + 1) * 1024] = f0.y;
        d_hfin[o1 + (size_t)(2 * k) * 1024]     = f1.x;
        d_hfin[o1 + (size_t)(2 * k + 1) * 1024] = f1.y;
    }
}

__global__ void __launch_bounds__(256)
scan_pass2(const float* __restrict__ VA, const float* __restrict__ IA) {
    int idx = blockIdx.x * 256 + threadIdx.x;
    int i   = idx & 1023;
    int b   = (idx >> 10) & 3;
    int dir = (idx >> 12) & 1;
    int s   = (idx >> 13) & 1;

    const float* Alog = s ? IA : VA;
    float a128[DS];
#pragma unroll
    for (int k = 0; k < DS; k++) {
        float a = fminf(fmaxf(-expf(Alog[i * DS + k]), -10.f), -0.01f);
#pragma unroll
        for (int q = 0; q < 7; q++) a = a * a;
        a128[k] = a;
    }

    const size_t cstride = (size_t)2 * DS * 1024;
#pragma unroll
    for (int var = 0; var < 2; var++) {
        size_t base = hf_off(s, dir, b, 0, var, i);
        float hin[DS];
#pragma unroll
        for (int k = 0; k < DS; k++) hin[k] = 0.f;
        for (int c = 0; c < NCH; c++) {
            size_t o = base + c * cstride;
#pragma unroll
            for (int k = 0; k < DS; k++) {
                float fin = d_hfin[o + (size_t)k * 1024];
                d_hfin[o + (size_t)k * 1024] = hin[k];
                hin[k] = fmaf(a128[k], hin[k], fin);
            }
        }
    }
}

__global__ void __launch_bounds__(256)
scan_pass3(const float* __restrict__ VA, const float* __restrict__ VB,
           const float* __restrict__ VC, const float* __restrict__ IA,
           const float* __restrict__ IB, const float* __restrict__ IC) {
    int idx = blockIdx.x * 256 + threadIdx.x;
    int i   = idx & 1023;
    int c   = (idx >> 10) & 7;
    int b   = (idx >> 13) & 3;
    int dir = (idx >> 15) & 1;
    int s   = (idx >> 16) & 1;

    const float* Alog = s ? IA : VA;
    const float* Bown = s ? IB : VB;
    const float* Both = s ? VB : IB;
    const float* Cp   = s ? IC : VC;
    float w0 = 0.5f * d_lam[b * 2 + 0];
    float w1 = 0.5f * d_lam[b * 2 + 1];

    u64 A2[8], B02[8], B12[8], C2[8], h02[8], h12[8];
    size_t o0 = hf_off(s, dir, b, c, 0, i);
    size_t o1 = hf_off(s, dir, b, c, 1, i);
#pragma unroll
    for (int k = 0; k < 8; k++) {
        float a0 = fminf(fmaxf(-expf(Alog[i * DS + 2 * k]),     -10.f), -0.01f);
        float a1 = fminf(fmaxf(-expf(Alog[i * DS + 2 * k + 1]), -10.f), -0.01f);
        A2[k]  = pack2(a0, a1);
        B02[k] = pack2(Bown[i * DS + 2 * k], Bown[i * DS + 2 * k + 1]);
        B12[k] = pack2(Both[i * DS + 2 * k], Both[i * DS + 2 * k + 1]);
        C2[k]  = pack2(Cp[i * DS + 2 * k],   Cp[i * DS + 2 * k + 1]);
        h02[k] = pack2(d_hfin[o0 + (size_t)(2 * k) * 1024],
                       d_hfin[o0 + (size_t)(2 * k + 1) * 1024]);
        h12[k] = pack2(d_hfin[o1 + (size_t)(2 * k) * 1024],
                       d_hfin[o1 + (size_t)(2 * k + 1) * 1024]);
    }

    const bf16* xs = d_xp[s] + (size_t)b * LSEQ * (2 * DI) + i;
    bf16* yo = d_y2[s][dir] + (size_t)b * LSEQ * DI + i;
    int t  = dir ? (LSEQ - 1 - c * CHL) : c * CHL;
    int dt = dir ? -1 : 1;

    for (int step = 0; step < CHL; step++, t += dt) {
        float x = __bfloat162float(xs[(size_t)t * (2 * DI)]);
        u64 xd = pack2(x, x);
        u64 y0p = 0ull, y1p = 0ull;
#pragma unroll
        for (int k = 0; k < 8; k++) {
            h02[k] = fma2_(h02[k], A2[k], fma2_(B02[k], xd, 0ull));
            y0p = fma2_(h02[k], C2[k], y0p);
            h12[k] = fma2_(h12[k], A2[k], fma2_(B12[k], xd, 0ull));
            y1p = fma2_(h12[k], C2[k], y1p);
        }
        float2 f0 = unpack2(y0p), f1 = unpack2(y1p);
        float y = w0 * (f0.x + f0.y) + w1 * (f1.x + f1.y);
        yo[(size_t)t * DI] = __float2bfloat16(y);
    }
}

// ---------------- gated combine, bf16 in/out ----------------
__global__ void gated_combine() {
    int s = blockIdx.y;
    int idx = blockIdx.x * 256 + threadIdx.x;
    int i = idx & 1023;
    int n = idx >> 10;
    float g = __bfloat162float(d_xp[s][(size_t)n * (2 * DI) + DI + i]);
    float sig = 1.f / (1.f + expf(-g));
    float y = __bfloat162float(d_y2[s][0][idx]) + __bfloat162float(d_y2[s][1][idx]);
    d_u[s][idx] = __float2bfloat16(y * g * sig);
}

// ---------------- final: transpose + BN + residual + gate ----------------
__global__ void final_kernel(const float* __restrict__ x0, const float* __restrict__ x1,
                             float* __restrict__ out,
                             const float* __restrict__ g, const float* __restrict__ bb,
                             const float* __restrict__ m, const float* __restrict__ v,
                             const float* __restrict__ gatep) {
    __shared__ float tile[32][33];
    int s = blockIdx.z >> 2;
    int b = blockIdx.z & 3;
    int hw0 = blockIdx.x * 32, o0 = blockIdx.y * 32;
    int tx = threadIdx.x, ty = threadIdx.y;
    tile[ty][tx] = d_res[s][((size_t)b * LSEQ + hw0 + ty) * CIN + o0 + tx];
    __syncthreads();
    int o = o0 + ty, hw = hw0 + tx;
    float sc = g[o] * rsqrtf(v[o] + 1e-5f);
    float sh = bb[o] - m[o] * sc;
    float sg = 1.f / (1.f + expf(-gatep[0]));
    const float* xin = s ? x1 : x0;
    size_t pos = ((size_t)b * CIN + o) * LSEQ + hw;
    float val = tile[tx][ty] * sc + sh;
    out[(size_t)s * BSZ * CIN * LSEQ + pos] = xin[pos] + sg * val;
}

// ---------------- launch ----------------
extern "C" void kernel_launch(void* const* d_in, const int* in_sizes, int n_in,
                              void* d_out, int out_size) {
    const float* x_V        = (const float*)d_in[0];
    const float* x_I        = (const float*)d_in[1];
    const float* conv_red_w = (const float*)d_in[2];
    const float* bn_red_g   = (const float*)d_in[3];
    const float* bn_red_b   = (const float*)d_in[4];
    const float* bn_red_m   = (const float*)d_in[5];
    const float* bn_red_v   = (const float*)d_in[6];
    const float* conv_res_w = (const float*)d_in[7];
    const float* bn_res_g   = (const float*)d_in[8];
    const float* bn_res_b   = (const float*)d_in[9];
    const float* bn_res_m   = (const float*)d_in[10];
    const float* bn_res_v   = (const float*)d_in[11];
    const float* lam_w1     = (const float*)d_in[12];
    const float* lam_b1     = (const float*)d_in[13];
    const float* lam_w2     = (const float*)d_in[14];
    const float* lam_b2     = (const float*)d_in[15];
    const float* in_w[2]    = {(const float*)d_in[16], (const float*)d_in[23]};
    const float* out_w[2]   = {(const float*)d_in[17], (const float*)d_in[24]};
    const float* A_log[2]   = {(const float*)d_in[18], (const float*)d_in[25]};
    const float* Bmat[2]    = {(const float*)d_in[19], (const float*)d_in[26]};
    const float* Cmat[2]    = {(const float*)d_in[20], (const float*)d_in[27]};
    const float* ln_g[2]    = {(const float*)d_in[21], (const float*)d_in[28]};
    const float* ln_b[2]    = {(const float*)d_in[22], (const float*)d_in[29]};
    const float* gate       = (const float*)d_in[30];

    bf16 *XT, *XN, *XP, *U, *WT, *WC, *CRW, *CRSW, *INW;
    float *SEQ, *RES;
    cudaGetSymbolAddress((void**)&XT,   d_xt);
    cudaGetSymbolAddress((void**)&SEQ,  d_seq);
    cudaGetSymbolAddress((void**)&XN,   d_xn);
    cudaGetSymbolAddress((void**)&XP,   d_xp);
    cudaGetSymbolAddress((void**)&U,    d_u);
    cudaGetSymbolAddress((void**)&RES,  d_res);
    cudaGetSymbolAddress((void**)&WT,   d_wt);
    cudaGetSymbolAddress((void**)&WC,   d_wc);
    cudaGetSymbolAddress((void**)&CRW,  d_crw);
    cudaGetSymbolAddress((void**)&CRSW, d_crsw);
    cudaGetSymbolAddress((void**)&INW,  d_inw);

    cudaFuncSetAttribute(tgemm<0>, cudaFuncAttributeMaxDynamicSharedMemorySize, TG_SMEM);
    cudaFuncSetAttribute(tgemm<1>, cudaFuncAttributeMaxDynamicSharedMemorySize, TG_SMEM);
    cudaFuncSetAttribute(tgemm<2>, cudaFuncAttributeMaxDynamicSharedMemorySize, TG_SMEM);

    // 0. weight conversion + transposes
    prep_all<<<(PREP_N + 255) / 256, 256>>>(conv_red_w, conv_res_w, in_w[0], in_w[1]);
    transpose_in<<<dim3(32, 8, 8), dim3(32, 32)>>>(x_V, x_I);
    transpose_w<<<dim3(DI / 32, DM / 32, 2), dim3(32, 32)>>>(out_w[0], out_w[1]);

    // 1. Wc[z] = conv_res_w @ out_w[z] -> bf16
    tgemm<2><<<dim3(DI / 128, CIN / 256, 2), 256, TG_SMEM>>>(
        CRSW, CRSW, WT, WT + (size_t)DI * DM, WC, CIN, DI, DM,
        (long long)CIN * DI, nullptr, nullptr, nullptr, nullptr);

    // 2. conv_red + BN + ReLU
    tgemm<1><<<dim3(DM / 128, NTOK / 256, 2), 256, TG_SMEM>>>(
        XT, XT + (size_t)NTOK * CIN, CRW, CRW, SEQ, NTOK, DM, CIN,
        (long long)NTOK * DM, bn_red_g, bn_red_b, bn_red_m, bn_red_v);

    // 3. pool + lambda (pool2 merged into lambda)
    pool1_kernel<<<dim3(16, 8), 512>>>();
    lambda_kernel<<<4, 128>>>(lam_w1, lam_b1, lam_w2, lam_b2);

    // 4. layernorm + in_proj (bf16 out)
    ln_kernel<<<dim3(NTOK, 2), 128>>>(ln_g[0], ln_b[0], ln_g[1], ln_b[1]);
    tgemm<2><<<dim3(2 * DI / 128, NTOK / 256, 2), 256, TG_SMEM>>>(
        XN, XN + (size_t)NTOK * DM, INW, INW + (size_t)2 * DI * DM, XP, NTOK, 2 * DI, DM,
        (long long)NTOK * 2 * DI, nullptr, nullptr, nullptr, nullptr);

    // 5. chunked parallel scan (packed f32x2)
    scan_pass1<<<512, 256>>>(A_log[0], Bmat[0], A_log[1], Bmat[1]);
    scan_pass2<<<64, 256>>>(A_log[0], A_log[1]);
    scan_pass3<<<512, 256>>>(A_log[0], Bmat[0], Cmat[0], A_log[1], Bmat[1], Cmat[1]);

    // 6. gated combine
    gated_combine<<<dim3(NTOK * DI / 256, 2), 256>>>();

    // 7. fused out_proj + conv_res
    tgemm<0><<<dim3(CIN / 128, NTOK / 256, 2), 256, TG_SMEM>>>(
        U, U + (size_t)NTOK * DI, WC, WC + (size_t)CIN * DI, RES, NTOK, CIN, DI,
        (long long)NTOK * CIN, nullptr, nullptr, nullptr, nullptr);

    // 8. BN + residual + gate -> output
    final_kernel<<<dim3(32, 8, 8), dim3(32, 32)>>>(x_V, x_I, (float*)d_out,
                                                   bn_res_g, bn_res_b, bn_res_m,
                                                   bn_res_v, gate);
}

// round 9
// speedup vs baseline: 3.6082x; 1.1128x over previous
#include <cuda_runtime.h>
#include <cuda_bf16.h>
#include <math.h>
#include <stdint.h>

#define NS   2
#define BSZ  4
#define LSEQ 1024
#define NTOK 4096
#define DM   512
#define DI   1024
#define DS   16
#define CIN  256
#define NCH  8
#define CHL  128

typedef __nv_bfloat16 bf16;
typedef unsigned long long u64;

// ---------------- scratch (static device globals; no runtime alloc) ----------------
__device__ bf16  d_xt[NS][NTOK * CIN];
__device__ float d_seq[NS][NTOK * DM];
__device__ float d_ppart[NS][16][BSZ * DM];
__device__ float d_lam[BSZ * 2];
__device__ bf16  d_xn[NS][NTOK * DM];
__device__ bf16  d_xp[NS][NTOK * 2 * DI];
__device__ bf16  d_yf[NS][NTOK * DI];          // forward-scan y
__device__ bf16  d_u[NS][NTOK * DI];
__device__ float d_res[NS][NTOK * CIN];
__device__ bf16  d_wt[NS][DI * DM];
__device__ bf16  d_wc[NS][CIN * DI];
__device__ float d_wcp[8][CIN * DI];           // split-K partials for Wc
__device__ bf16  d_crw[DM * CIN];
__device__ bf16  d_crsw[CIN * DM];
__device__ bf16  d_inw[NS][2 * DI * DM];
__device__ float d_hfin[NS * 2 * BSZ * NCH * DS * 1024];

// ---------------- PTX helpers ----------------
__device__ __forceinline__ uint32_t smem_u32(const void* p) {
    uint32_t a;
    asm("{ .reg .u64 t; cvta.to.shared.u64 t, %1; cvt.u32.u64 %0, t; }" : "=r"(a) : "l"(p));
    return a;
}
#define CP_ASYNC16(sp, gp) \
    asm volatile("cp.async.cg.shared.global [%0], [%1], 16;" :: "r"(sp), "l"(gp) : "memory")
#define CP_COMMIT() asm volatile("cp.async.commit_group;" ::: "memory")
#define CP_WAIT1()  asm volatile("cp.async.wait_group 1;" ::: "memory")
#define CP_WAIT0()  asm volatile("cp.async.wait_group 0;" ::: "memory")

#define LDSM_X4(r0, r1, r2, r3, addr) \
    asm volatile("ldmatrix.sync.aligned.m8n8.x4.shared.b16 {%0,%1,%2,%3}, [%4];" \
                 : "=r"(r0), "=r"(r1), "=r"(r2), "=r"(r3) : "r"(addr))

#define MMA_BF16(d, a, b) \
    asm volatile("mma.sync.aligned.m16n8k16.row.col.f32.bf16.bf16.f32 " \
                 "{%0,%1,%2,%3}, {%4,%5,%6,%7}, {%8,%9}, {%0,%1,%2,%3};" \
                 : "+f"((d)[0]), "+f"((d)[1]), "+f"((d)[2]), "+f"((d)[3]) \
                 : "r"((a)[0]), "r"((a)[1]), "r"((a)[2]), "r"((a)[3]), \
                   "r"((b)[0]), "r"((b)[1]))

__device__ __forceinline__ u64 fma2_(u64 a, u64 b, u64 c) {
    u64 d;
    asm("fma.rn.f32x2 %0, %1, %2, %3;" : "=l"(d) : "l"(a), "l"(b), "l"(c));
    return d;
}
__device__ __forceinline__ u64 pack2(float lo, float hi) {
    u64 r;
    asm("mov.b64 %0, {%1, %2};" : "=l"(r) : "f"(lo), "f"(hi));
    return r;
}
__device__ __forceinline__ float2 unpack2(u64 v) {
    float2 f;
    asm("mov.b64 {%0, %1}, %2;" : "=f"(f.x), "=f"(f.y) : "l"(v));
    return f;
}

// ---------------- bf16 mma.sync GEMM: C[M,N] = A[M,K(lda)] * B[N,K(ldb)]^T ----------------
// CTA 256x128, 8 warps (4Mx2N), warp tile 64x64, k-chunk 32, pitch 80B, dbl-buffered.
// z decodes (stream, k-split): zs = z / zdiv, kc = z % zdiv; A,B advance kc*K along k.
#define TG_PITCH   80
#define TG_MATA    (256 * TG_PITCH)
#define TG_MATB    (128 * TG_PITCH)
#define TG_STAGE_B (TG_MATA + TG_MATB)
#define TG_SMEM    (2 * TG_STAGE_B)

template <int EPI>   // 0 plain fp32, 1 BN+ReLU fp32, 2 bf16 output
__global__ void __launch_bounds__(256, 1)
tgemm(const bf16* __restrict__ A0, const bf16* __restrict__ A1,
      const bf16* __restrict__ B0, const bf16* __restrict__ B1,
      void* __restrict__ Cv, int M, int N, int K, int lda, int ldb, int zdiv,
      long long sCz,
      const float* __restrict__ eg, const float* __restrict__ eb,
      const float* __restrict__ em, const float* __restrict__ ev) {
    extern __shared__ float smf[];
    const uint32_t sbase = smem_u32(smf);

    const int tid  = threadIdx.x;
    const int lane = tid & 31;
    const int wid  = tid >> 5;
    const int z = blockIdx.z;
    const int zs = z / zdiv, kc = z % zdiv;
    const bf16* __restrict__ A = (zs ? A1 : A0) + (size_t)kc * K;
    const bf16* __restrict__ B = (zs ? B1 : B0) + (size_t)kc * K;
    const int m0 = blockIdx.y * 256, n0 = blockIdx.x * 128;
    const int wm = (wid >> 1) * 64;
    const int wn = (wid & 1) * 64;

    const int lr = tid >> 2;
    const int lc = tid & 3;

    auto load_stage = [&](int t) {
        const int k0 = t * 32;
        uint32_t dst = sbase + (t & 1) * TG_STAGE_B;
#pragma unroll
        for (int i = 0; i < 4; i++) {
            int m = lr + i * 64;
            CP_ASYNC16(dst + m * TG_PITCH + lc * 16, A + (size_t)(m0 + m) * lda + k0 + lc * 8);
        }
        dst += TG_MATA;
#pragma unroll
        for (int i = 0; i < 2; i++) {
            int n = lr + i * 64;
            CP_ASYNC16(dst + n * TG_PITCH + lc * 16, B + (size_t)(n0 + n) * ldb + k0 + lc * 8);
        }
        CP_COMMIT();
    };

    float c[4][8][4];
#pragma unroll
    for (int mt = 0; mt < 4; mt++)
#pragma unroll
        for (int nt = 0; nt < 8; nt++)
#pragma unroll
            for (int q = 0; q < 4; q++) c[mt][nt][q] = 0.f;

    const int T = K / 32;
    load_stage(0);
    load_stage(1);

    const int l15   = lane & 15;
    const int lhiA  = (lane >> 4) * 16;
    const int bnrow = (lane & 7) + ((lane >> 4) << 3);
    const int bkoff = ((lane >> 3) & 1) * 16;

    for (int t = 0; t < T; t++) {
        if (t + 1 < T) { CP_WAIT1(); } else { CP_WAIT0(); }
        __syncthreads();
        const uint32_t aB = sbase + (t & 1) * TG_STAGE_B;
        const uint32_t bB = aB + TG_MATA;
#pragma unroll
        for (int kk = 0; kk < 2; kk++) {
            uint32_t a[4][4], b[8][2];
#pragma unroll
            for (int mt = 0; mt < 4; mt++) {
                uint32_t addr = aB + (wm + mt * 16 + l15) * TG_PITCH + kk * 32 + lhiA;
                LDSM_X4(a[mt][0], a[mt][1], a[mt][2], a[mt][3], addr);
            }
#pragma unroll
            for (int nh = 0; nh < 4; nh++) {
                uint32_t addr = bB + (wn + nh * 16 + bnrow) * TG_PITCH + kk * 32 + bkoff;
                uint32_t r0, r1, r2, r3;
                LDSM_X4(r0, r1, r2, r3, addr);
                b[nh * 2][0] = r0; b[nh * 2][1] = r1;
                b[nh * 2 + 1][0] = r2; b[nh * 2 + 1][1] = r3;
            }
#pragma unroll
            for (int mt = 0; mt < 4; mt++)
#pragma unroll
                for (int nt = 0; nt < 8; nt++)
                    MMA_BF16(c[mt][nt], a[mt], b[nt]);
        }
        __syncthreads();
        if (t + 2 < T) load_stage(t + 2);
    }

    const int gid = lane >> 2;
    const int tig = lane & 3;
#pragma unroll
    for (int mt = 0; mt < 4; mt++) {
        const int r0 = m0 + wm + mt * 16 + gid;
#pragma unroll
        for (int nt = 0; nt < 8; nt++) {
            const int col = n0 + wn + nt * 8 + tig * 2;
            float v0 = c[mt][nt][0], v1 = c[mt][nt][1];
            float v2 = c[mt][nt][2], v3 = c[mt][nt][3];
            if (EPI == 1) {
                float s0 = eg[col] * rsqrtf(ev[col] + 1e-5f);
                float h0 = eb[col] - em[col] * s0;
                float s1 = eg[col + 1] * rsqrtf(ev[col + 1] + 1e-5f);
                float h1 = eb[col + 1] - em[col + 1] * s1;
                v0 = fmaxf(v0 * s0 + h0, 0.f);
                v1 = fmaxf(v1 * s1 + h1, 0.f);
                v2 = fmaxf(v2 * s0 + h0, 0.f);
                v3 = fmaxf(v3 * s1 + h1, 0.f);
            }
            if (EPI == 2) {
                bf16* Cb = (bf16*)Cv + (size_t)z * sCz;
                *(__nv_bfloat162*)&Cb[(size_t)r0 * N + col] =
                    __floats2bfloat162_rn(v0, v1);
                *(__nv_bfloat162*)&Cb[(size_t)(r0 + 8) * N + col] =
                    __floats2bfloat162_rn(v2, v3);
            } else {
                float* Cf = (float*)Cv + (size_t)z * sCz;
                *(float2*)&Cf[(size_t)r0 * N + col]       = make_float2(v0, v1);
                *(float2*)&Cf[(size_t)(r0 + 8) * N + col] = make_float2(v2, v3);
            }
        }
    }
}

// ---------------- Wc split-K reduce: sum 4 fp32 partials -> bf16 ----------------
__global__ void wc_reduce() {
    int idx = blockIdx.x * 256 + threadIdx.x;      // 2 * CIN*DI = 524288
    int s = idx >> 18;                             // CIN*DI = 262144 = 2^18
    int j = idx & (CIN * DI - 1);
    float v = d_wcp[s * 4 + 0][j] + d_wcp[s * 4 + 1][j] +
              d_wcp[s * 4 + 2][j] + d_wcp[s * 4 + 3][j];
    d_wc[s][j] = __float2bfloat16(v);
}

// ---------------- merged weight conversion fp32 -> bf16 ----------------
#define PREP_N (DM * CIN + CIN * DM + 2 * (2 * DI * DM))
__global__ void prep_all(const float* __restrict__ crw, const float* __restrict__ crsw,
                         const float* __restrict__ iw0, const float* __restrict__ iw1) {
    int i = blockIdx.x * 256 + threadIdx.x;
    const int n1 = DM * CIN, n2 = n1 + CIN * DM, n3 = n2 + 2 * DI * DM;
    if (i < n1)       d_crw[i]          = __float2bfloat16(crw[i]);
    else if (i < n2)  d_crsw[i - n1]    = __float2bfloat16(crsw[i - n1]);
    else if (i < n3)  d_inw[0][i - n2]  = __float2bfloat16(iw0[i - n2]);
    else if (i < PREP_N) d_inw[1][i - n3] = __float2bfloat16(iw1[i - n3]);
}

// ---------------- transpose x: (B,C,HW) -> (B*HW, C), bf16 ----------------
__global__ void transpose_in(const float* __restrict__ x0, const float* __restrict__ x1) {
    __shared__ float tile[32][33];
    int s = blockIdx.z >> 2, b = blockIdx.z & 3;
    const float* x = s ? x1 : x0;
    int hw0 = blockIdx.x * 32, c0 = blockIdx.y * 32;
    int tx = threadIdx.x, ty = threadIdx.y;
    tile[ty][tx] = x[((size_t)b * CIN + (c0 + ty)) * LSEQ + hw0 + tx];
    __syncthreads();
    d_xt[s][((size_t)b * LSEQ + hw0 + ty) * CIN + c0 + tx] = __float2bfloat16(tile[tx][ty]);
}

// ---------------- transpose out_w: [DM, DI] -> [DI, DM], bf16 ----------------
__global__ void transpose_w(const float* __restrict__ w0, const float* __restrict__ w1) {
    __shared__ float tile[32][33];
    int s = blockIdx.z;
    const float* w = s ? w1 : w0;
    int c0 = blockIdx.x * 32, r0 = blockIdx.y * 32;
    int tx = threadIdx.x, ty = threadIdx.y;
    tile[ty][tx] = w[(size_t)(r0 + ty) * DI + c0 + tx];
    __syncthreads();
    d_wt[s][(size_t)(c0 + ty) * DM + r0 + tx] = __float2bfloat16(tile[tx][ty]);
}

// ---------------- pool stage 1 ----------------
__global__ void pool1_kernel() {
    int s = blockIdx.y >> 2, b = blockIdx.y & 3, chunk = blockIdx.x;
    int d = threadIdx.x;
    const float* p = d_seq[s] + ((size_t)b * LSEQ + chunk * 64) * DM + d;
    float acc = 0.f;
#pragma unroll 8
    for (int l = 0; l < 64; l++) acc += p[(size_t)l * DM];
    d_ppart[s][chunk][b * DM + d] = acc;
}

// ---------------- lambda predictor (pool stage 2 merged) ----------------
__global__ void lambda_kernel(const float* __restrict__ w1, const float* __restrict__ b1,
                              const float* __restrict__ w2, const float* __restrict__ b2) {
    int b = blockIdx.x, j = threadIdx.x;
    __shared__ float pooled[2 * DM];
    for (int idx = j; idx < 2 * DM; idx += 128) {
        int s = idx >> 9, d = idx & (DM - 1);
        float acc = 0.f;
#pragma unroll
        for (int c = 0; c < 16; c++) acc += d_ppart[s][c][b * DM + d];
        pooled[idx] = acc * (1.0f / LSEQ);
    }
    __syncthreads();
    const float* w = w1 + (size_t)j * (2 * DM);
    float acc = b1[j];
    for (int c = 0; c < DM; c++) acc += pooled[c] * w[c];
    for (int c = 0; c < DM; c++) acc += pooled[DM + c] * w[DM + c];
    __shared__ float h1[128];
    h1[j] = fmaxf(acc, 0.f);
    __syncthreads();
    if (j == 0) {
        float l0 = b2[0], l1 = b2[1];
        for (int c = 0; c < 128; c++) { l0 += h1[c] * w2[c]; l1 += h1[c] * w2[128 + c]; }
        float mx = fmaxf(l0, l1);
        float e0 = expf(l0 - mx), e1 = expf(l1 - mx);
        float inv = 1.f / (e0 + e1);
        d_lam[b * 2 + 0] = e0 * inv;
        d_lam[b * 2 + 1] = e1 * inv;
    }
}

// ---------------- LayerNorm over D=512, bf16 output ----------------
__global__ void ln_kernel(const float* __restrict__ g0, const float* __restrict__ b0,
                          const float* __restrict__ g1, const float* __restrict__ b1) {
    int s = blockIdx.y;
    const float* g = s ? g1 : g0;
    const float* b = s ? b1 : b0;
    int n = blockIdx.x, t = threadIdx.x;
    float4 v = ((const float4*)(d_seq[s] + (size_t)n * DM))[t];
    float sm = v.x + v.y + v.z + v.w;
    float sq = v.x * v.x + v.y * v.y + v.z * v.z + v.w * v.w;
#pragma unroll
    for (int o = 16; o; o >>= 1) {
        sm += __shfl_xor_sync(0xffffffffu, sm, o);
        sq += __shfl_xor_sync(0xffffffffu, sq, o);
    }
    __shared__ float ss[4], sqs[4];
    int w = t >> 5, ln = t & 31;
    if (ln == 0) { ss[w] = sm; sqs[w] = sq; }
    __syncthreads();
    sm = ss[0] + ss[1] + ss[2] + ss[3];
    sq = sqs[0] + sqs[1] + sqs[2] + sqs[3];
    float mu = sm * (1.f / DM);
    float var = sq * (1.f / DM) - mu * mu;
    float inv = rsqrtf(var + 1e-5f);
    float4 gg = ((const float4*)g)[t];
    float4 bb = ((const float4*)b)[t];
    __nv_bfloat162* dst = (__nv_bfloat162*)(d_xn[s] + (size_t)n * DM);
    dst[2 * t]     = __floats2bfloat162_rn((v.x - mu) * inv * gg.x + bb.x,
                                           (v.y - mu) * inv * gg.y + bb.y);
    dst[2 * t + 1] = __floats2bfloat162_rn((v.z - mu) * inv * gg.z + bb.z,
                                           (v.w - mu) * inv * gg.w + bb.w);
}

// ================= chunked parallel scan, lambda-combined recurrence =================
// g = w0*h_std + w1*h_cross obeys g' = A g + x*(w0*B_own + w1*B_other); y = C.g
__device__ __forceinline__ size_t hf_off(int s, int dir, int b, int c, int i) {
    return (((((size_t)s * 2 + dir) * 4 + b) * NCH + c) * DS) * 1024 + i;
}

__global__ void __launch_bounds__(256)
scan_pass1(const float* __restrict__ VA, const float* __restrict__ VB,
           const float* __restrict__ IA, const float* __restrict__ IB) {
    int idx = blockIdx.x * 256 + threadIdx.x;   // 131072
    int i   = idx & 1023;
    int c   = (idx >> 10) & 7;
    int b   = (idx >> 13) & 3;
    int dir = (idx >> 15) & 1;
    int s   = (idx >> 16) & 1;

    const float* Alog = s ? IA : VA;
    const float* Bown = s ? IB : VB;
    const float* Both = s ? VB : IB;
    float w0 = 0.5f * d_lam[b * 2 + 0];
    float w1 = 0.5f * d_lam[b * 2 + 1];

    u64 A2[8], Be2[8], h2[8];
#pragma unroll
    for (int k = 0; k < 8; k++) {
        float a0 = fminf(fmaxf(-expf(Alog[i * DS + 2 * k]),     -10.f), -0.01f);
        float a1 = fminf(fmaxf(-expf(Alog[i * DS + 2 * k + 1]), -10.f), -0.01f);
        A2[k]  = pack2(a0, a1);
        Be2[k] = pack2(w0 * Bown[i * DS + 2 * k]     + w1 * Both[i * DS + 2 * k],
                       w0 * Bown[i * DS + 2 * k + 1] + w1 * Both[i * DS + 2 * k + 1]);
        h2[k] = 0ull;
    }

    const bf16* xs = d_xp[s] + (size_t)b * LSEQ * (2 * DI) + i;
    int t  = dir ? (LSEQ - 1 - c * CHL) : c * CHL;
    int dt = dir ? -1 : 1;

    for (int step = 0; step < CHL; step++, t += dt) {
        float x = __bfloat162float(xs[(size_t)t * (2 * DI)]);
        u64 xd = pack2(x, x);
#pragma unroll
        for (int k = 0; k < 8; k++)
            h2[k] = fma2_(h2[k], A2[k], fma2_(Be2[k], xd, 0ull));
    }

    size_t o0 = hf_off(s, dir, b, c, i);
#pragma unroll
    for (int k = 0; k < 8; k++) {
        float2 f = unpack2(h2[k]);
        d_hfin[o0 + (size_t)(2 * k) * 1024]     = f.x;
        d_hfin[o0 + (size_t)(2 * k + 1) * 1024] = f.y;
    }
}

__global__ void __launch_bounds__(256)
scan_pass2(const float* __restrict__ VA, const float* __restrict__ IA) {
    int idx = blockIdx.x * 256 + threadIdx.x;   // 16384
    int i   = idx & 1023;
    int b   = (idx >> 10) & 3;
    int dir = (idx >> 12) & 1;
    int s   = (idx >> 13) & 1;

    const float* Alog = s ? IA : VA;
    float a128[DS];
#pragma unroll
    for (int k = 0; k < DS; k++) {
        float a = fminf(fmaxf(-expf(Alog[i * DS + k]), -10.f), -0.01f);
#pragma unroll
        for (int q = 0; q < 7; q++) a = a * a;
        a128[k] = a;
    }

    const size_t cstride = (size_t)DS * 1024;
    size_t base = hf_off(s, dir, b, 0, i);
    float hin[DS];
#pragma unroll
    for (int k = 0; k < DS; k++) hin[k] = 0.f;
    for (int c = 0; c < NCH; c++) {
        size_t o = base + c * cstride;
#pragma unroll
        for (int k = 0; k < DS; k++) {
            float fin = d_hfin[o + (size_t)k * 1024];
            d_hfin[o + (size_t)k * 1024] = hin[k];
            hin[k] = fmaf(a128[k], hin[k], fin);
        }
    }
}

// DIR=0: write y_fwd.  DIR=1: combine with y_fwd + gate, write u.
template <int DIR>
__global__ void __launch_bounds__(256)
scan_pass3(const float* __restrict__ VA, const float* __restrict__ VB,
           const float* __restrict__ VC, const float* __restrict__ IA,
           const float* __restrict__ IB, const float* __restrict__ IC) {
    int idx = blockIdx.x * 256 + threadIdx.x;   // 65536
    int i   = idx & 1023;
    int c   = (idx >> 10) & 7;
    int b   = (idx >> 13) & 3;
    int s   = (idx >> 14) & 1;

    const float* Alog = s ? IA : VA;
    const float* Bown = s ? IB : VB;
    const float* Both = s ? VB : IB;
    const float* Cp   = s ? IC : VC;
    float w0 = 0.5f * d_lam[b * 2 + 0];
    float w1 = 0.5f * d_lam[b * 2 + 1];

    u64 A2[8], Be2[8], C2[8], h2[8];
    size_t o0 = hf_off(s, DIR, b, c, i);
#pragma unroll
    for (int k = 0; k < 8; k++) {
        float a0 = fminf(fmaxf(-expf(Alog[i * DS + 2 * k]),     -10.f), -0.01f);
        float a1 = fminf(fmaxf(-expf(Alog[i * DS + 2 * k + 1]), -10.f), -0.01f);
        A2[k]  = pack2(a0, a1);
        Be2[k] = pack2(w0 * Bown[i * DS + 2 * k]     + w1 * Both[i * DS + 2 * k],
                       w0 * Bown[i * DS + 2 * k + 1] + w1 * Both[i * DS + 2 * k + 1]);
        C2[k]  = pack2(Cp[i * DS + 2 * k], Cp[i * DS + 2 * k + 1]);
        h2[k]  = pack2(d_hfin[o0 + (size_t)(2 * k) * 1024],
                       d_hfin[o0 + (size_t)(2 * k + 1) * 1024]);
    }

    const bf16* xs = d_xp[s] + (size_t)b * LSEQ * (2 * DI) + i;
    const bf16* gs = xs + DI;
    bf16* yo = d_yf[s] + (size_t)b * LSEQ * DI + i;
    bf16* uo = d_u[s]  + (size_t)b * LSEQ * DI + i;
    int t  = DIR ? (LSEQ - 1 - c * CHL) : c * CHL;
    int dt = DIR ? -1 : 1;

    for (int step = 0; step < CHL; step++, t += dt) {
        float x = __bfloat162float(xs[(size_t)t * (2 * DI)]);
        u64 xd = pack2(x, x);
        u64 yp = 0ull;
#pragma unroll
        for (int k = 0; k < 8; k++) {
            h2[k] = fma2_(h2[k], A2[k], fma2_(Be2[k], xd, 0ull));
            yp = fma2_(h2[k], C2[k], yp);
        }
        float2 f = unpack2(yp);
        float y = f.x + f.y;
        if (DIR == 0) {
            yo[(size_t)t * DI] = __float2bfloat16(y);
        } else {
            float g = __bfloat162float(gs[(size_t)t * (2 * DI)]);
            float sig = 1.f / (1.f + expf(-g));
            float yf = __bfloat162float(yo[(size_t)t * DI]);
            uo[(size_t)t * DI] = __float2bfloat16((yf + y) * g * sig);
        }
    }
}

// ---------------- final: transpose + BN + residual + gate ----------------
__global__ void final_kernel(const float* __restrict__ x0, const float* __restrict__ x1,
                             float* __restrict__ out,
                             const float* __restrict__ g, const float* __restrict__ bb,
                             const float* __restrict__ m, const float* __restrict__ v,
                             const float* __restrict__ gatep) {
    __shared__ float tile[32][33];
    int s = blockIdx.z >> 2;
    int b = blockIdx.z & 3;
    int hw0 = blockIdx.x * 32, o0 = blockIdx.y * 32;
    int tx = threadIdx.x, ty = threadIdx.y;
    tile[ty][tx] = d_res[s][((size_t)b * LSEQ + hw0 + ty) * CIN + o0 + tx];
    __syncthreads();
    int o = o0 + ty, hw = hw0 + tx;
    float sc = g[o] * rsqrtf(v[o] + 1e-5f);
    float sh = bb[o] - m[o] * sc;
    float sg = 1.f / (1.f + expf(-gatep[0]));
    const float* xin = s ? x1 : x0;
    size_t pos = ((size_t)b * CIN + o) * LSEQ + hw;
    float val = tile[tx][ty] * sc + sh;
    out[(size_t)s * BSZ * CIN * LSEQ + pos] = xin[pos] + sg * val;
}

// ---------------- launch ----------------
extern "C" void kernel_launch(void* const* d_in, const int* in_sizes, int n_in,
                              void* d_out, int out_size) {
    const float* x_V        = (const float*)d_in[0];
    const float* x_I        = (const float*)d_in[1];
    const float* conv_red_w = (const float*)d_in[2];
    const float* bn_red_g   = (const float*)d_in[3];
    const float* bn_red_b   = (const float*)d_in[4];
    const float* bn_red_m   = (const float*)d_in[5];
    const float* bn_red_v   = (const float*)d_in[6];
    const float* conv_res_w = (const float*)d_in[7];
    const float* bn_res_g   = (const float*)d_in[8];
    const float* bn_res_b   = (const float*)d_in[9];
    const float* bn_res_m   = (const float*)d_in[10];
    const float* bn_res_v   = (const float*)d_in[11];
    const float* lam_w1     = (const float*)d_in[12];
    const float* lam_b1     = (const float*)d_in[13];
    const float* lam_w2     = (const float*)d_in[14];
    const float* lam_b2     = (const float*)d_in[15];
    const float* in_w[2]    = {(const float*)d_in[16], (const float*)d_in[23]};
    const float* out_w[2]   = {(const float*)d_in[17], (const float*)d_in[24]};
    const float* A_log[2]   = {(const float*)d_in[18], (const float*)d_in[25]};
    const float* Bmat[2]    = {(const float*)d_in[19], (const float*)d_in[26]};
    const float* Cmat[2]    = {(const float*)d_in[20], (const float*)d_in[27]};
    const float* ln_g[2]    = {(const float*)d_in[21], (const float*)d_in[28]};
    const float* ln_b[2]    = {(const float*)d_in[22], (const float*)d_in[29]};
    const float* gate       = (const float*)d_in[30];

    bf16 *XT, *XN, *XP, *U, *WT, *WC, *CRW, *CRSW, *INW;
    float *SEQ, *RES, *WCP;
    cudaGetSymbolAddress((void**)&XT,   d_xt);
    cudaGetSymbolAddress((void**)&SEQ,  d_seq);
    cudaGetSymbolAddress((void**)&XN,   d_xn);
    cudaGetSymbolAddress((void**)&XP,   d_xp);
    cudaGetSymbolAddress((void**)&U,    d_u);
    cudaGetSymbolAddress((void**)&RES,  d_res);
    cudaGetSymbolAddress((void**)&WT,   d_wt);
    cudaGetSymbolAddress((void**)&WC,   d_wc);
    cudaGetSymbolAddress((void**)&WCP,  d_wcp);
    cudaGetSymbolAddress((void**)&CRW,  d_crw);
    cudaGetSymbolAddress((void**)&CRSW, d_crsw);
    cudaGetSymbolAddress((void**)&INW,  d_inw);

    cudaFuncSetAttribute(tgemm<0>, cudaFuncAttributeMaxDynamicSharedMemorySize, TG_SMEM);
    cudaFuncSetAttribute(tgemm<1>, cudaFuncAttributeMaxDynamicSharedMemorySize, TG_SMEM);
    cudaFuncSetAttribute(tgemm<2>, cudaFuncAttributeMaxDynamicSharedMemorySize, TG_SMEM);

    // 0. weight conversion + transposes
    prep_all<<<(PREP_N + 255) / 256, 256>>>(conv_red_w, conv_res_w, in_w[0], in_w[1]);
    transpose_in<<<dim3(32, 8, 8), dim3(32, 32)>>>(x_V, x_I);
    transpose_w<<<dim3(DI / 32, DM / 32, 2), dim3(32, 32)>>>(out_w[0], out_w[1]);

    // 1. Wc[z] = conv_res_w @ out_w[z], split-K x4 (z = s*4 + kc), fp32 partials -> reduce
    tgemm<0><<<dim3(DI / 128, 1, 8), 256, TG_SMEM>>>(
        CRSW, CRSW, WT, WT + (size_t)DI * DM, WCP, CIN, DI, DM / 4, DM, DM, 4,
        (long long)CIN * DI, nullptr, nullptr, nullptr, nullptr);
    wc_reduce<<<2 * CIN * DI / 256, 256>>>();

    // 2. conv_red + BN + ReLU  (M=4096, N=512, K=256)
    tgemm<1><<<dim3(DM / 128, NTOK / 256, 2), 256, TG_SMEM>>>(
        XT, XT + (size_t)NTOK * CIN, CRW, CRW, SEQ, NTOK, DM, CIN, CIN, CIN, 1,
        (long long)NTOK * DM, bn_red_g, bn_red_b, bn_red_m, bn_red_v);

    // 3. pool + lambda
    pool1_kernel<<<dim3(16, 8), 512>>>();
    lambda_kernel<<<4, 128>>>(lam_w1, lam_b1, lam_w2, lam_b2);

    // 4. layernorm + in_proj (bf16 out)
    ln_kernel<<<dim3(NTOK, 2), 128>>>(ln_g[0], ln_b[0], ln_g[1], ln_b[1]);
    tgemm<2><<<dim3(2 * DI / 128, NTOK / 256, 2), 256, TG_SMEM>>>(
        XN, XN + (size_t)NTOK * DM, INW, INW + (size_t)2 * DI * DM, XP, NTOK, 2 * DI,
        DM, DM, DM, 1, (long long)NTOK * 2 * DI, nullptr, nullptr, nullptr, nullptr);

    // 5. chunked parallel scan (lambda-combined single recurrence)
    scan_pass1<<<512, 256>>>(A_log[0], Bmat[0], A_log[1], Bmat[1]);
    scan_pass2<<<64, 256>>>(A_log[0], A_log[1]);
    scan_pass3<0><<<256, 256>>>(A_log[0], Bmat[0], Cmat[0], A_log[1], Bmat[1], Cmat[1]);
    scan_pass3<1><<<256, 256>>>(A_log[0], Bmat[0], Cmat[0], A_log[1], Bmat[1], Cmat[1]);

    // 6. fused out_proj + conv_res  (M=4096, N=256, K=1024)
    tgemm<0><<<dim3(CIN / 128, NTOK / 256, 2), 256, TG_SMEM>>>(
        U, U + (size_t)NTOK * DI, WC, WC + (size_t)CIN * DI, RES, NTOK, CIN,
        DI, DI, DI, 1, (long long)NTOK * CIN, nullptr, nullptr, nullptr, nullptr);

    // 7. BN + residual + gate -> output
    final_kernel<<<dim3(32, 8, 8), dim3(32, 32)>>>(x_V, x_I, (float*)d_out,
                                                   bn_res_g, bn_res_b, bn_res_m,
                                                   bn_res_v, gate);
}

// round 10
// speedup vs baseline: 4.3213x; 1.1976x over previous
#include <cuda_runtime.h>
#include <cuda_bf16.h>
#include <math.h>
#include <stdint.h>

#define NS   2
#define BSZ  4
#define LSEQ 1024
#define NTOK 4096
#define DM   512
#define DI   1024
#define DS   16
#define CIN  256
#define NCH  8
#define CHL  128

typedef __nv_bfloat16 bf16;
typedef unsigned long long u64;

// ---------------- scratch ----------------
__device__ bf16  d_xt[NS][NTOK * CIN];
__device__ float d_seq[NS][NTOK * DM];
__device__ float d_ppart[NS][16][BSZ * DM];
__device__ float d_lam[BSZ * 2];
__device__ bf16  d_xn[NS][NTOK * DM];
__device__ bf16  d_xp[NS][NTOK * 2 * DI];
__device__ bf16  d_u[NS][NTOK * DI];
__device__ bf16  d_wt[NS][DI * DM];
__device__ bf16  d_wc[NS][CIN * DI];
__device__ float d_wcp[8][CIN * DI];
__device__ bf16  d_crw[DM * CIN];
__device__ bf16  d_crsw[CIN * DM];
__device__ bf16  d_inw[NS][2 * DI * DM];
__device__ float d_hfin[NS * 2 * BSZ * NCH * DS * 1024];

// ---------------- PTX helpers ----------------
__device__ __forceinline__ uint32_t smem_u32(const void* p) {
    uint32_t a;
    asm("{ .reg .u64 t; cvta.to.shared.u64 t, %1; cvt.u32.u64 %0, t; }" : "=r"(a) : "l"(p));
    return a;
}
#define CP_ASYNC16(sp, gp) \
    asm volatile("cp.async.cg.shared.global [%0], [%1], 16;" :: "r"(sp), "l"(gp) : "memory")
#define CP_COMMIT() asm volatile("cp.async.commit_group;" ::: "memory")
#define CP_WAIT2()  asm volatile("cp.async.wait_group 2;" ::: "memory")

#define LDSM_X4(r0, r1, r2, r3, addr) \
    asm volatile("ldmatrix.sync.aligned.m8n8.x4.shared.b16 {%0,%1,%2,%3}, [%4];" \
                 : "=r"(r0), "=r"(r1), "=r"(r2), "=r"(r3) : "r"(addr))

#define MMA_BF16(d, a, b) \
    asm volatile("mma.sync.aligned.m16n8k16.row.col.f32.bf16.bf16.f32 " \
                 "{%0,%1,%2,%3}, {%4,%5,%6,%7}, {%8,%9}, {%0,%1,%2,%3};" \
                 : "+f"((d)[0]), "+f"((d)[1]), "+f"((d)[2]), "+f"((d)[3]) \
                 : "r"((a)[0]), "r"((a)[1]), "r"((a)[2]), "r"((a)[3]), \
                   "r"((b)[0]), "r"((b)[1]))

__device__ __forceinline__ u64 fma2_(u64 a, u64 b, u64 c) {
    u64 d;
    asm("fma.rn.f32x2 %0, %1, %2, %3;" : "=l"(d) : "l"(a), "l"(b), "l"(c));
    return d;
}
__device__ __forceinline__ u64 pack2(float lo, float hi) {
    u64 r;
    asm("mov.b64 %0, {%1, %2};" : "=l"(r) : "f"(lo), "f"(hi));
    return r;
}
__device__ __forceinline__ float2 unpack2(u64 v) {
    float2 f;
    asm("mov.b64 {%0, %1}, %2;" : "=f"(f.x), "=f"(f.y) : "l"(v));
    return f;
}

// ---------------- bf16 mma.sync GEMM: C[M,N] = A[M,K(lda)] * B[N,K(ldb)]^T ----------------
// CTA 256x128, 8 warps (4Mx2N), warp tile 64x64, k-chunk 32, pitch 80B.
// 4-stage cp.async ring, prefetch distance 3, ONE __syncthreads per k-iter.
#define TG_PITCH   80
#define TG_MATA    (256 * TG_PITCH)
#define TG_MATB    (128 * TG_PITCH)
#define TG_STAGE_B (TG_MATA + TG_MATB)       // 30720
#define TG_NST     4
#define TG_SMEM    (TG_NST * TG_STAGE_B)     // 122880

// EPI: 0 plain fp32, 1 BN+ReLU fp32, 2 bf16 out, 3 fused BN+residual+gate transposed out
template <int EPI>
__global__ void __launch_bounds__(256, 1)
tgemm(const bf16* __restrict__ A0, const bf16* __restrict__ A1,
      const bf16* __restrict__ B0, const bf16* __restrict__ B1,
      void* __restrict__ Cv, int M, int N, int K, int lda, int ldb, int zdiv,
      long long sCz,
      const float* __restrict__ eg, const float* __restrict__ eb,
      const float* __restrict__ em, const float* __restrict__ ev,
      const float* __restrict__ RX0, const float* __restrict__ RX1,
      const float* __restrict__ gp) {
    extern __shared__ float smf[];
    const uint32_t sbase = smem_u32(smf);

    const int tid  = threadIdx.x;
    const int lane = tid & 31;
    const int wid  = tid >> 5;
    const int z = blockIdx.z;
    const int zs = z / zdiv, kc = z % zdiv;
    const bf16* __restrict__ A = (zs ? A1 : A0) + (size_t)kc * K;
    const bf16* __restrict__ B = (zs ? B1 : B0) + (size_t)kc * K;
    const int m0 = blockIdx.y * 256, n0 = blockIdx.x * 128;
    const int wm = (wid >> 1) * 64;
    const int wn = (wid & 1) * 64;

    const int lr = tid >> 2;
    const int lc = tid & 3;
    const int T = K / 32;

    auto load_stage = [&](int t) {
        if (t < T) {
            const int k0 = t * 32;
            uint32_t dst = sbase + (t & 3) * TG_STAGE_B;
#pragma unroll
            for (int i = 0; i < 4; i++) {
                int m = lr + i * 64;
                CP_ASYNC16(dst + m * TG_PITCH + lc * 16,
                           A + (size_t)(m0 + m) * lda + k0 + lc * 8);
            }
            dst += TG_MATA;
#pragma unroll
            for (int i = 0; i < 2; i++) {
                int n = lr + i * 64;
                CP_ASYNC16(dst + n * TG_PITCH + lc * 16,
                           B + (size_t)(n0 + n) * ldb + k0 + lc * 8);
            }
        }
        CP_COMMIT();
    };

    float c[4][8][4];
#pragma unroll
    for (int mt = 0; mt < 4; mt++)
#pragma unroll
        for (int nt = 0; nt < 8; nt++)
#pragma unroll
            for (int q = 0; q < 4; q++) c[mt][nt][q] = 0.f;

    load_stage(0);
    load_stage(1);
    load_stage(2);

    const int l15   = lane & 15;
    const int lhiA  = (lane >> 4) * 16;
    const int bnrow = (lane & 7) + ((lane >> 4) << 3);
    const int bkoff = ((lane >> 3) & 1) * 16;

    for (int t = 0; t < T; t++) {
        CP_WAIT2();
        __syncthreads();
        load_stage(t + 3);
        const uint32_t aB = sbase + (t & 3) * TG_STAGE_B;
        const uint32_t bB = aB + TG_MATA;
#pragma unroll
        for (int kk = 0; kk < 2; kk++) {
            uint32_t a[4][4], b[8][2];
#pragma unroll
            for (int mt = 0; mt < 4; mt++) {
                uint32_t addr = aB + (wm + mt * 16 + l15) * TG_PITCH + kk * 32 + lhiA;
                LDSM_X4(a[mt][0], a[mt][1], a[mt][2], a[mt][3], addr);
            }
#pragma unroll
            for (int nh = 0; nh < 4; nh++) {
                uint32_t addr = bB + (wn + nh * 16 + bnrow) * TG_PITCH + kk * 32 + bkoff;
                uint32_t r0, r1, r2, r3;
                LDSM_X4(r0, r1, r2, r3, addr);
                b[nh * 2][0] = r0; b[nh * 2][1] = r1;
                b[nh * 2 + 1][0] = r2; b[nh * 2 + 1][1] = r3;
            }
#pragma unroll
            for (int mt = 0; mt < 4; mt++)
#pragma unroll
                for (int nt = 0; nt < 8; nt++)
                    MMA_BF16(c[mt][nt], a[mt], b[nt]);
        }
    }

    const int gid = lane >> 2;
    const int tig = lane & 3;
    float sg = 0.f;
    if (EPI == 3) sg = 1.f / (1.f + expf(-gp[0]));
#pragma unroll
    for (int mt = 0; mt < 4; mt++) {
        const int r0 = m0 + wm + mt * 16 + gid;
#pragma unroll
        for (int nt = 0; nt < 8; nt++) {
            const int col = n0 + wn + nt * 8 + tig * 2;
            float v0 = c[mt][nt][0], v1 = c[mt][nt][1];
            float v2 = c[mt][nt][2], v3 = c[mt][nt][3];
            if (EPI == 1) {
                float s0 = eg[col] * rsqrtf(ev[col] + 1e-5f);
                float h0 = eb[col] - em[col] * s0;
                float s1 = eg[col + 1] * rsqrtf(ev[col + 1] + 1e-5f);
                float h1 = eb[col + 1] - em[col + 1] * s1;
                v0 = fmaxf(v0 * s0 + h0, 0.f);
                v1 = fmaxf(v1 * s1 + h1, 0.f);
                v2 = fmaxf(v2 * s0 + h0, 0.f);
                v3 = fmaxf(v3 * s1 + h1, 0.f);
            }
            if (EPI == 2) {
                bf16* Cb = (bf16*)Cv + (size_t)z * sCz;
                *(__nv_bfloat162*)&Cb[(size_t)r0 * N + col] =
                    __floats2bfloat162_rn(v0, v1);
                *(__nv_bfloat162*)&Cb[(size_t)(r0 + 8) * N + col] =
                    __floats2bfloat162_rn(v2, v3);
            } else if (EPI == 3) {
                // BN(res) + residual + gate, transposed store
                float s0 = eg[col] * rsqrtf(ev[col] + 1e-5f);
                float h0 = eb[col] - em[col] * s0;
                float s1 = eg[col + 1] * rsqrtf(ev[col + 1] + 1e-5f);
                float h1 = eb[col + 1] - em[col + 1] * s1;
                const float* xin = zs ? RX1 : RX0;
                float* outp = (float*)Cv + (size_t)zs * BSZ * CIN * LSEQ;
                int b = r0 >> 10, hw = r0 & 1023;
                size_t p0 = ((size_t)b * CIN + col) * LSEQ + hw;
                size_t p1 = p0 + LSEQ;                 // col+1
                outp[p0]     = xin[p0]     + sg * (v0 * s0 + h0);
                outp[p1]     = xin[p1]     + sg * (v1 * s1 + h1);
                outp[p0 + 8] = xin[p0 + 8] + sg * (v2 * s0 + h0);   // row r0+8 -> hw+8
                outp[p1 + 8] = xin[p1 + 8] + sg * (v3 * s1 + h1);
            } else {
                float* Cf = (float*)Cv + (size_t)z * sCz;
                *(float2*)&Cf[(size_t)r0 * N + col]       = make_float2(v0, v1);
                *(float2*)&Cf[(size_t)(r0 + 8) * N + col] = make_float2(v2, v3);
            }
        }
    }
}

// ---------------- Wc split-K reduce ----------------
__global__ void wc_reduce() {
    int idx = blockIdx.x * 256 + threadIdx.x;
    int s = idx >> 18;
    int j = idx & (CIN * DI - 1);
    float v = d_wcp[s * 4 + 0][j] + d_wcp[s * 4 + 1][j] +
              d_wcp[s * 4 + 2][j] + d_wcp[s * 4 + 3][j];
    d_wc[s][j] = __float2bfloat16(v);
}

// ---------------- merged weight conversion ----------------
#define PREP_N (DM * CIN + CIN * DM + 2 * (2 * DI * DM))
__global__ void prep_all(const float* __restrict__ crw, const float* __restrict__ crsw,
                         const float* __restrict__ iw0, const float* __restrict__ iw1) {
    int i = blockIdx.x * 256 + threadIdx.x;
    const int n1 = DM * CIN, n2 = n1 + CIN * DM, n3 = n2 + 2 * DI * DM;
    if (i < n1)       d_crw[i]          = __float2bfloat16(crw[i]);
    else if (i < n2)  d_crsw[i - n1]    = __float2bfloat16(crsw[i - n1]);
    else if (i < n3)  d_inw[0][i - n2]  = __float2bfloat16(iw0[i - n2]);
    else if (i < PREP_N) d_inw[1][i - n3] = __float2bfloat16(iw1[i - n3]);
}

// ---------------- transpose x -> bf16 token-major ----------------
__global__ void transpose_in(const float* __restrict__ x0, const float* __restrict__ x1) {
    __shared__ float tile[32][33];
    int s = blockIdx.z >> 2, b = blockIdx.z & 3;
    const float* x = s ? x1 : x0;
    int hw0 = blockIdx.x * 32, c0 = blockIdx.y * 32;
    int tx = threadIdx.x, ty = threadIdx.y;
    tile[ty][tx] = x[((size_t)b * CIN + (c0 + ty)) * LSEQ + hw0 + tx];
    __syncthreads();
    d_xt[s][((size_t)b * LSEQ + hw0 + ty) * CIN + c0 + tx] = __float2bfloat16(tile[tx][ty]);
}

// ---------------- transpose out_w -> bf16 [DI, DM] ----------------
__global__ void transpose_w(const float* __restrict__ w0, const float* __restrict__ w1) {
    __shared__ float tile[32][33];
    int s = blockIdx.z;
    const float* w = s ? w1 : w0;
    int c0 = blockIdx.x * 32, r0 = blockIdx.y * 32;
    int tx = threadIdx.x, ty = threadIdx.y;
    tile[ty][tx] = w[(size_t)(r0 + ty) * DI + c0 + tx];
    __syncthreads();
    d_wt[s][(size_t)(c0 + ty) * DM + r0 + tx] = __float2bfloat16(tile[tx][ty]);
}

// ---------------- pool stage 1 ----------------
__global__ void pool1_kernel() {
    int s = blockIdx.y >> 2, b = blockIdx.y & 3, chunk = blockIdx.x;
    int d = threadIdx.x;
    const float* p = d_seq[s] + ((size_t)b * LSEQ + chunk * 64) * DM + d;
    float acc = 0.f;
#pragma unroll 8
    for (int l = 0; l < 64; l++) acc += p[(size_t)l * DM];
    d_ppart[s][chunk][b * DM + d] = acc;
}

// ---------------- lambda predictor ----------------
__global__ void lambda_kernel(const float* __restrict__ w1, const float* __restrict__ b1,
                              const float* __restrict__ w2, const float* __restrict__ b2) {
    int b = blockIdx.x, j = threadIdx.x;
    __shared__ float pooled[2 * DM];
    for (int idx = j; idx < 2 * DM; idx += 128) {
        int s = idx >> 9, d = idx & (DM - 1);
        float acc = 0.f;
#pragma unroll
        for (int c = 0; c < 16; c++) acc += d_ppart[s][c][b * DM + d];
        pooled[idx] = acc * (1.0f / LSEQ);
    }
    __syncthreads();
    const float* w = w1 + (size_t)j * (2 * DM);
    float acc = b1[j];
    for (int c = 0; c < DM; c++) acc += pooled[c] * w[c];
    for (int c = 0; c < DM; c++) acc += pooled[DM + c] * w[DM + c];
    __shared__ float h1[128];
    h1[j] = fmaxf(acc, 0.f);
    __syncthreads();
    if (j == 0) {
        float l0 = b2[0], l1 = b2[1];
        for (int c = 0; c < 128; c++) { l0 += h1[c] * w2[c]; l1 += h1[c] * w2[128 + c]; }
        float mx = fmaxf(l0, l1);
        float e0 = expf(l0 - mx), e1 = expf(l1 - mx);
        float inv = 1.f / (e0 + e1);
        d_lam[b * 2 + 0] = e0 * inv;
        d_lam[b * 2 + 1] = e1 * inv;
    }
}

// ---------------- LayerNorm, bf16 out ----------------
__global__ void ln_kernel(const float* __restrict__ g0, const float* __restrict__ b0,
                          const float* __restrict__ g1, const float* __restrict__ b1) {
    int s = blockIdx.y;
    const float* g = s ? g1 : g0;
    const float* b = s ? b1 : b0;
    int n = blockIdx.x, t = threadIdx.x;
    float4 v = ((const float4*)(d_seq[s] + (size_t)n * DM))[t];
    float sm = v.x + v.y + v.z + v.w;
    float sq = v.x * v.x + v.y * v.y + v.z * v.z + v.w * v.w;
#pragma unroll
    for (int o = 16; o; o >>= 1) {
        sm += __shfl_xor_sync(0xffffffffu, sm, o);
        sq += __shfl_xor_sync(0xffffffffu, sq, o);
    }
    __shared__ float ss[4], sqs[4];
    int w = t >> 5, ln = t & 31;
    if (ln == 0) { ss[w] = sm; sqs[w] = sq; }
    __syncthreads();
    sm = ss[0] + ss[1] + ss[2] + ss[3];
    sq = sqs[0] + sqs[1] + sqs[2] + sqs[3];
    float mu = sm * (1.f / DM);
    float var = sq * (1.f / DM) - mu * mu;
    float inv = rsqrtf(var + 1e-5f);
    float4 gg = ((const float4*)g)[t];
    float4 bb = ((const float4*)b)[t];
    __nv_bfloat162* dst = (__nv_bfloat162*)(d_xn[s] + (size_t)n * DM);
    dst[2 * t]     = __floats2bfloat162_rn((v.x - mu) * inv * gg.x + bb.x,
                                           (v.y - mu) * inv * gg.y + bb.y);
    dst[2 * t + 1] = __floats2bfloat162_rn((v.z - mu) * inv * gg.z + bb.z,
                                           (v.w - mu) * inv * gg.w + bb.w);
}

// ================= chunked parallel scan, lambda-combined recurrence =================
__device__ __forceinline__ size_t hf_off(int s, int dir, int b, int c, int i) {
    return (((((size_t)s * 2 + dir) * 4 + b) * NCH + c) * DS) * 1024 + i;
}

__global__ void __launch_bounds__(256)
scan_pass1(const float* __restrict__ VA, const float* __restrict__ VB,
           const float* __restrict__ IA, const float* __restrict__ IB) {
    int idx = blockIdx.x * 256 + threadIdx.x;   // 131072
    int i   = idx & 1023;
    int c   = (idx >> 10) & 7;
    int b   = (idx >> 13) & 3;
    int dir = (idx >> 15) & 1;
    int s   = (idx >> 16) & 1;

    const float* Alog = s ? IA : VA;
    const float* Bown = s ? IB : VB;
    const float* Both = s ? VB : IB;
    float w0 = 0.5f * d_lam[b * 2 + 0];
    float w1 = 0.5f * d_lam[b * 2 + 1];

    u64 A2[8], Be2[8], h2[8];
#pragma unroll
    for (int k = 0; k < 8; k++) {
        float a0 = fminf(fmaxf(-expf(Alog[i * DS + 2 * k]),     -10.f), -0.01f);
        float a1 = fminf(fmaxf(-expf(Alog[i * DS + 2 * k + 1]), -10.f), -0.01f);
        A2[k]  = pack2(a0, a1);
        Be2[k] = pack2(w0 * Bown[i * DS + 2 * k]     + w1 * Both[i * DS + 2 * k],
                       w0 * Bown[i * DS + 2 * k + 1] + w1 * Both[i * DS + 2 * k + 1]);
        h2[k] = 0ull;
    }

    const bf16* xs = d_xp[s] + (size_t)b * LSEQ * (2 * DI) + i;
    int t  = dir ? (LSEQ - 1 - c * CHL) : c * CHL;
    int dt = dir ? -1 : 1;

    for (int step = 0; step < CHL; step++, t += dt) {
        float x = __bfloat162float(xs[(size_t)t * (2 * DI)]);
        u64 xd = pack2(x, x);
#pragma unroll
        for (int k = 0; k < 8; k++)
            h2[k] = fma2_(h2[k], A2[k], fma2_(Be2[k], xd, 0ull));
    }

    size_t o0 = hf_off(s, dir, b, c, i);
#pragma unroll
    for (int k = 0; k < 8; k++) {
        float2 f = unpack2(h2[k]);
        d_hfin[o0 + (size_t)(2 * k) * 1024]     = f.x;
        d_hfin[o0 + (size_t)(2 * k + 1) * 1024] = f.y;
    }
}

__global__ void __launch_bounds__(256)
scan_pass2(const float* __restrict__ VA, const float* __restrict__ IA) {
    int idx = blockIdx.x * 256 + threadIdx.x;   // 16384
    int i   = idx & 1023;
    int b   = (idx >> 10) & 3;
    int dir = (idx >> 12) & 1;
    int s   = (idx >> 13) & 1;

    const float* Alog = s ? IA : VA;
    float a128[DS];
#pragma unroll
    for (int k = 0; k < DS; k++) {
        float a = fminf(fmaxf(-expf(Alog[i * DS + k]), -10.f), -0.01f);
#pragma unroll
        for (int q = 0; q < 7; q++) a = a * a;
        a128[k] = a;
    }

    const size_t cstride = (size_t)DS * 1024;
    size_t base = hf_off(s, dir, b, 0, i);
    float hin[DS];
#pragma unroll
    for (int k = 0; k < DS; k++) hin[k] = 0.f;
    for (int c = 0; c < NCH; c++) {
        size_t o = base + c * cstride;
#pragma unroll
        for (int k = 0; k < DS; k++) {
            float fin = d_hfin[o + (size_t)k * 1024];
            d_hfin[o + (size_t)k * 1024] = hin[k];
            hin[k] = fmaf(a128[k], hin[k], fin);
        }
    }
}

// merged pass3: fwd scan stashes y_fwd in smem (thread-private), bwd scan emits u.
__global__ void __launch_bounds__(256)
scan_pass3m(const float* __restrict__ VA, const float* __restrict__ VB,
            const float* __restrict__ VC, const float* __restrict__ IA,
            const float* __restrict__ IB, const float* __restrict__ IC) {
    extern __shared__ bf16 yfs[];               // [CHL][256]
    int tid = threadIdx.x;
    int idx = blockIdx.x * 256 + tid;           // 65536
    int i   = idx & 1023;
    int c   = (idx >> 10) & 7;
    int b   = (idx >> 13) & 3;
    int s   = (idx >> 14) & 1;

    const float* Alog = s ? IA : VA;
    const float* Bown = s ? IB : VB;
    const float* Both = s ? VB : IB;
    const float* Cp   = s ? IC : VC;
    float w0 = 0.5f * d_lam[b * 2 + 0];
    float w1 = 0.5f * d_lam[b * 2 + 1];

    u64 A2[8], Be2[8], C2[8], h2[8];
#pragma unroll
    for (int k = 0; k < 8; k++) {
        float a0 = fminf(fmaxf(-expf(Alog[i * DS + 2 * k]),     -10.f), -0.01f);
        float a1 = fminf(fmaxf(-expf(Alog[i * DS + 2 * k + 1]), -10.f), -0.01f);
        A2[k]  = pack2(a0, a1);
        Be2[k] = pack2(w0 * Bown[i * DS + 2 * k]     + w1 * Both[i * DS + 2 * k],
                       w0 * Bown[i * DS + 2 * k + 1] + w1 * Both[i * DS + 2 * k + 1]);
        C2[k]  = pack2(Cp[i * DS + 2 * k], Cp[i * DS + 2 * k + 1]);
    }

    const bf16* xs = d_xp[s] + (size_t)b * LSEQ * (2 * DI) + i;
    const bf16* gs = xs + DI;
    bf16* uo = d_u[s] + (size_t)b * LSEQ * DI + i;
    const int t0 = c * CHL;

    // ---- forward over window ----
    {
        size_t o0 = hf_off(s, 0, b, c, i);
#pragma unroll
        for (int k = 0; k < 8; k++)
            h2[k] = pack2(d_hfin[o0 + (size_t)(2 * k) * 1024],
                          d_hfin[o0 + (size_t)(2 * k + 1) * 1024]);
        for (int step = 0; step < CHL; step++) {
            float x = __bfloat162float(xs[(size_t)(t0 + step) * (2 * DI)]);
            u64 xd = pack2(x, x);
            u64 yp = 0ull;
#pragma unroll
            for (int k = 0; k < 8; k++) {
                h2[k] = fma2_(h2[k], A2[k], fma2_(Be2[k], xd, 0ull));
                yp = fma2_(h2[k], C2[k], yp);
            }
            float2 f = unpack2(yp);
            yfs[step * 256 + tid] = __float2bfloat16(f.x + f.y);
        }
    }
    // ---- backward over same window, emit u ----
    {
        size_t o1 = hf_off(s, 1, b, NCH - 1 - c, i);
#pragma unroll
        for (int k = 0; k < 8; k++)
            h2[k] = pack2(d_hfin[o1 + (size_t)(2 * k) * 1024],
                          d_hfin[o1 + (size_t)(2 * k + 1) * 1024]);
        for (int step = 0; step < CHL; step++) {
            int ls = CHL - 1 - step;            // local index in window
            int t = t0 + ls;
            float x = __bfloat162float(xs[(size_t)t * (2 * DI)]);
            u64 xd = pack2(x, x);
            u64 yp = 0ull;
#pragma unroll
            for (int k = 0; k < 8; k++) {
                h2[k] = fma2_(h2[k], A2[k], fma2_(Be2[k], xd, 0ull));
                yp = fma2_(h2[k], C2[k], yp);
            }
            float2 f = unpack2(yp);
            float yb = f.x + f.y;
            float yf = __bfloat162float(yfs[ls * 256 + tid]);
            float g = __bfloat162float(gs[(size_t)t * (2 * DI)]);
            float sig = 1.f / (1.f + expf(-g));
            uo[(size_t)t * DI] = __float2bfloat16((yf + yb) * g * sig);
        }
    }
}

// ---------------- launch ----------------
extern "C" void kernel_launch(void* const* d_in, const int* in_sizes, int n_in,
                              void* d_out, int out_size) {
    const float* x_V        = (const float*)d_in[0];
    const float* x_I        = (const float*)d_in[1];
    const float* conv_red_w = (const float*)d_in[2];
    const float* bn_red_g   = (const float*)d_in[3];
    const float* bn_red_b   = (const float*)d_in[4];
    const float* bn_red_m   = (const float*)d_in[5];
    const float* bn_red_v   = (const float*)d_in[6];
    const float* conv_res_w = (const float*)d_in[7];
    const float* bn_res_g   = (const float*)d_in[8];
    const float* bn_res_b   = (const float*)d_in[9];
    const float* bn_res_m   = (const float*)d_in[10];
    const float* bn_res_v   = (const float*)d_in[11];
    const float* lam_w1     = (const float*)d_in[12];
    const float* lam_b1     = (const float*)d_in[13];
    const float* lam_w2     = (const float*)d_in[14];
    const float* lam_b2     = (const float*)d_in[15];
    const float* in_w[2]    = {(const float*)d_in[16], (const float*)d_in[23]};
    const float* out_w[2]   = {(const float*)d_in[17], (const float*)d_in[24]};
    const float* A_log[2]   = {(const float*)d_in[18], (const float*)d_in[25]};
    const float* Bmat[2]    = {(const float*)d_in[19], (const float*)d_in[26]};
    const float* Cmat[2]    = {(const float*)d_in[20], (const float*)d_in[27]};
    const float* ln_g[2]    = {(const float*)d_in[21], (const float*)d_in[28]};
    const float* ln_b[2]    = {(const float*)d_in[22], (const float*)d_in[29]};
    const float* gate       = (const float*)d_in[30];

    bf16 *XT, *XN, *XP, *U, *WT, *WC, *CRW, *CRSW, *INW;
    float *SEQ, *WCP;
    cudaGetSymbolAddress((void**)&XT,   d_xt);
    cudaGetSymbolAddress((void**)&SEQ,  d_seq);
    cudaGetSymbolAddress((void**)&XN,   d_xn);
    cudaGetSymbolAddress((void**)&XP,   d_xp);
    cudaGetSymbolAddress((void**)&U,    d_u);
    cudaGetSymbolAddress((void**)&WT,   d_wt);
    cudaGetSymbolAddress((void**)&WC,   d_wc);
    cudaGetSymbolAddress((void**)&WCP,  d_wcp);
    cudaGetSymbolAddress((void**)&CRW,  d_crw);
    cudaGetSymbolAddress((void**)&CRSW, d_crsw);
    cudaGetSymbolAddress((void**)&INW,  d_inw);

    cudaFuncSetAttribute(tgemm<0>, cudaFuncAttributeMaxDynamicSharedMemorySize, TG_SMEM);
    cudaFuncSetAttribute(tgemm<1>, cudaFuncAttributeMaxDynamicSharedMemorySize, TG_SMEM);
    cudaFuncSetAttribute(tgemm<2>, cudaFuncAttributeMaxDynamicSharedMemorySize, TG_SMEM);
    cudaFuncSetAttribute(tgemm<3>, cudaFuncAttributeMaxDynamicSharedMemorySize, TG_SMEM);
    cudaFuncSetAttribute(scan_pass3m, cudaFuncAttributeMaxDynamicSharedMemorySize, 65536);

    // 0. weight conversion + transposes
    prep_all<<<(PREP_N + 255) / 256, 256>>>(conv_red_w, conv_res_w, in_w[0], in_w[1]);
    transpose_in<<<dim3(32, 8, 8), dim3(32, 32)>>>(x_V, x_I);
    transpose_w<<<dim3(DI / 32, DM / 32, 2), dim3(32, 32)>>>(out_w[0], out_w[1]);

    // 1. Wc split-K x4, fp32 partials -> reduce
    tgemm<0><<<dim3(DI / 128, 1, 8), 256, TG_SMEM>>>(
        CRSW, CRSW, WT, WT + (size_t)DI * DM, WCP, CIN, DI, DM / 4, DM, DM, 4,
        (long long)CIN * DI, nullptr, nullptr, nullptr, nullptr,
        nullptr, nullptr, nullptr);
    wc_reduce<<<2 * CIN * DI / 256, 256>>>();

    // 2. conv_red + BN + ReLU
    tgemm<1><<<dim3(DM / 128, NTOK / 256, 2), 256, TG_SMEM>>>(
        XT, XT + (size_t)NTOK * CIN, CRW, CRW, SEQ, NTOK, DM, CIN, CIN, CIN, 1,
        (long long)NTOK * DM, bn_red_g, bn_red_b, bn_red_m, bn_red_v,
        nullptr, nullptr, nullptr);

    // 3. pool + lambda
    pool1_kernel<<<dim3(16, 8), 512>>>();
    lambda_kernel<<<4, 128>>>(lam_w1, lam_b1, lam_w2, lam_b2);

    // 4. layernorm + in_proj (bf16 out)
    ln_kernel<<<dim3(NTOK, 2), 128>>>(ln_g[0], ln_b[0], ln_g[1], ln_b[1]);
    tgemm<2><<<dim3(2 * DI / 128, NTOK / 256, 2), 256, TG_SMEM>>>(
        XN, XN + (size_t)NTOK * DM, INW, INW + (size_t)2 * DI * DM, XP, NTOK, 2 * DI,
        DM, DM, DM, 1, (long long)NTOK * 2 * DI, nullptr, nullptr, nullptr, nullptr,
        nullptr, nullptr, nullptr);

    // 5. chunked parallel scan (merged fwd+bwd pass3 -> u directly)
    scan_pass1<<<512, 256>>>(A_log[0], Bmat[0], A_log[1], Bmat[1]);
    scan_pass2<<<64, 256>>>(A_log[0], A_log[1]);
    scan_pass3m<<<256, 256, 65536>>>(A_log[0], Bmat[0], Cmat[0],
                                     A_log[1], Bmat[1], Cmat[1]);

    // 6. fused out_proj + conv_res + BN + residual + gate -> output
    tgemm<3><<<dim3(CIN / 128, NTOK / 256, 2), 256, TG_SMEM>>>(
        U, U + (size_t)NTOK * DI, WC, WC + (size_t)CIN * DI, (float*)d_out, NTOK, CIN,
        DI, DI, DI, 1, 0LL, bn_res_g, bn_res_b, bn_res_m, bn_res_v,
        x_V, x_I, gate);
}

// round 11
// speedup vs baseline: 4.3617x; 1.0094x over previous
#include <cuda_runtime.h>
#include <cuda_bf16.h>
#include <math.h>
#include <stdint.h>

#define NS   2
#define BSZ  4
#define LSEQ 1024
#define NTOK 4096
#define DM   512
#define DI   1024
#define DS   16
#define CIN  256
#define NCH  8
#define CHL  128

typedef __nv_bfloat16 bf16;
typedef unsigned long long u64;

// ---------------- scratch ----------------
__device__ bf16  d_xt[NS][NTOK * CIN];
__device__ float d_seq[NS][NTOK * DM];
__device__ float d_ppart[NS][16][BSZ * DM];
__device__ float d_lam[BSZ * 2];
__device__ bf16  d_xn[NS][NTOK * DM];
__device__ bf16  d_xp[NS][NTOK * 2 * DI];
__device__ bf16  d_u[NS][NTOK * DI];
__device__ bf16  d_wt[NS][DI * DM];
__device__ bf16  d_wc[NS][CIN * DI];
__device__ float d_wcp[8][CIN * DI];
__device__ bf16  d_crw[DM * CIN];
__device__ bf16  d_crsw[CIN * DM];
__device__ bf16  d_inw[NS][2 * DI * DM];
__device__ float d_hfin[NS * 2 * BSZ * NCH * DS * 1024];

// ---------------- PTX helpers ----------------
__device__ __forceinline__ uint32_t smem_u32(const void* p) {
    uint32_t a;
    asm("{ .reg .u64 t; cvta.to.shared.u64 t, %1; cvt.u32.u64 %0, t; }" : "=r"(a) : "l"(p));
    return a;
}
#define CP_ASYNC16(sp, gp) \
    asm volatile("cp.async.cg.shared.global [%0], [%1], 16;" :: "r"(sp), "l"(gp) : "memory")
#define CP_COMMIT() asm volatile("cp.async.commit_group;" ::: "memory")
#define CP_WAIT2()  asm volatile("cp.async.wait_group 2;" ::: "memory")

#define LDSM_X4(r0, r1, r2, r3, addr) \
    asm volatile("ldmatrix.sync.aligned.m8n8.x4.shared.b16 {%0,%1,%2,%3}, [%4];" \
                 : "=r"(r0), "=r"(r1), "=r"(r2), "=r"(r3) : "r"(addr))

#define MMA_BF16(d, a, b) \
    asm volatile("mma.sync.aligned.m16n8k16.row.col.f32.bf16.bf16.f32 " \
                 "{%0,%1,%2,%3}, {%4,%5,%6,%7}, {%8,%9}, {%0,%1,%2,%3};" \
                 : "+f"((d)[0]), "+f"((d)[1]), "+f"((d)[2]), "+f"((d)[3]) \
                 : "r"((a)[0]), "r"((a)[1]), "r"((a)[2]), "r"((a)[3]), \
                   "r"((b)[0]), "r"((b)[1]))

__device__ __forceinline__ u64 fma2_(u64 a, u64 b, u64 c) {
    u64 d;
    asm("fma.rn.f32x2 %0, %1, %2, %3;" : "=l"(d) : "l"(a), "l"(b), "l"(c));
    return d;
}
__device__ __forceinline__ u64 pack2(float lo, float hi) {
    u64 r;
    asm("mov.b64 %0, {%1, %2};" : "=l"(r) : "f"(lo), "f"(hi));
    return r;
}
__device__ __forceinline__ float2 unpack2(u64 v) {
    float2 f;
    asm("mov.b64 {%0, %1}, %2;" : "=f"(f.x), "=f"(f.y) : "l"(v));
    return f;
}

// ---------------- bf16 mma.sync GEMM (unchanged core) ----------------
#define TG_PITCH   80
#define TG_MATA    (256 * TG_PITCH)
#define TG_MATB    (128 * TG_PITCH)
#define TG_STAGE_B (TG_MATA + TG_MATB)
#define TG_NST     4
#define TG_SMEM    (TG_NST * TG_STAGE_B)

// EPI: 0 plain fp32, 1 BN+ReLU fp32, 2 bf16 out, 3 fused BN+residual+gate transposed out
template <int EPI>
__global__ void __launch_bounds__(256, 1)
tgemm(const bf16* __restrict__ A0, const bf16* __restrict__ A1,
      const bf16* __restrict__ B0, const bf16* __restrict__ B1,
      void* __restrict__ Cv, int M, int N, int K, int lda, int ldb, int zdiv,
      long long sCz,
      const float* __restrict__ eg, const float* __restrict__ eb,
      const float* __restrict__ em, const float* __restrict__ ev,
      const float* __restrict__ RX0, const float* __restrict__ RX1,
      const float* __restrict__ gp) {
    extern __shared__ float smf[];
    const uint32_t sbase = smem_u32(smf);

    const int tid  = threadIdx.x;
    const int lane = tid & 31;
    const int wid  = tid >> 5;
    const int z = blockIdx.z;
    const int zs = z / zdiv, kc = z % zdiv;
    const bf16* __restrict__ A = (zs ? A1 : A0) + (size_t)kc * K;
    const bf16* __restrict__ B = (zs ? B1 : B0) + (size_t)kc * K;
    const int m0 = blockIdx.y * 256, n0 = blockIdx.x * 128;
    const int wm = (wid >> 1) * 64;
    const int wn = (wid & 1) * 64;

    const int lr = tid >> 2;
    const int lc = tid & 3;
    const int T = K / 32;

    auto load_stage = [&](int t) {
        if (t < T) {
            const int k0 = t * 32;
            uint32_t dst = sbase + (t & 3) * TG_STAGE_B;
#pragma unroll
            for (int i = 0; i < 4; i++) {
                int m = lr + i * 64;
                CP_ASYNC16(dst + m * TG_PITCH + lc * 16,
                           A + (size_t)(m0 + m) * lda + k0 + lc * 8);
            }
            dst += TG_MATA;
#pragma unroll
            for (int i = 0; i < 2; i++) {
                int n = lr + i * 64;
                CP_ASYNC16(dst + n * TG_PITCH + lc * 16,
                           B + (size_t)(n0 + n) * ldb + k0 + lc * 8);
            }
        }
        CP_COMMIT();
    };

    float c[4][8][4];
#pragma unroll
    for (int mt = 0; mt < 4; mt++)
#pragma unroll
        for (int nt = 0; nt < 8; nt++)
#pragma unroll
            for (int q = 0; q < 4; q++) c[mt][nt][q] = 0.f;

    load_stage(0);
    load_stage(1);
    load_stage(2);

    const int l15   = lane & 15;
    const int lhiA  = (lane >> 4) * 16;
    const int bnrow = (lane & 7) + ((lane >> 4) << 3);
    const int bkoff = ((lane >> 3) & 1) * 16;

    for (int t = 0; t < T; t++) {
        CP_WAIT2();
        __syncthreads();
        load_stage(t + 3);
        const uint32_t aB = sbase + (t & 3) * TG_STAGE_B;
        const uint32_t bB = aB + TG_MATA;
#pragma unroll
        for (int kk = 0; kk < 2; kk++) {
            uint32_t a[4][4], b[8][2];
#pragma unroll
            for (int mt = 0; mt < 4; mt++) {
                uint32_t addr = aB + (wm + mt * 16 + l15) * TG_PITCH + kk * 32 + lhiA;
                LDSM_X4(a[mt][0], a[mt][1], a[mt][2], a[mt][3], addr);
            }
#pragma unroll
            for (int nh = 0; nh < 4; nh++) {
                uint32_t addr = bB + (wn + nh * 16 + bnrow) * TG_PITCH + kk * 32 + bkoff;
                uint32_t r0, r1, r2, r3;
                LDSM_X4(r0, r1, r2, r3, addr);
                b[nh * 2][0] = r0; b[nh * 2][1] = r1;
                b[nh * 2 + 1][0] = r2; b[nh * 2 + 1][1] = r3;
            }
#pragma unroll
            for (int mt = 0; mt < 4; mt++)
#pragma unroll
                for (int nt = 0; nt < 8; nt++)
                    MMA_BF16(c[mt][nt], a[mt], b[nt]);
        }
    }

    const int gid = lane >> 2;
    const int tig = lane & 3;
    float sg = 0.f;
    if (EPI == 3) sg = 1.f / (1.f + expf(-gp[0]));
#pragma unroll
    for (int mt = 0; mt < 4; mt++) {
        const int r0 = m0 + wm + mt * 16 + gid;
#pragma unroll
        for (int nt = 0; nt < 8; nt++) {
            const int col = n0 + wn + nt * 8 + tig * 2;
            float v0 = c[mt][nt][0], v1 = c[mt][nt][1];
            float v2 = c[mt][nt][2], v3 = c[mt][nt][3];
            if (EPI == 1) {
                float s0 = eg[col] * rsqrtf(ev[col] + 1e-5f);
                float h0 = eb[col] - em[col] * s0;
                float s1 = eg[col + 1] * rsqrtf(ev[col + 1] + 1e-5f);
                float h1 = eb[col + 1] - em[col + 1] * s1;
                v0 = fmaxf(v0 * s0 + h0, 0.f);
                v1 = fmaxf(v1 * s1 + h1, 0.f);
                v2 = fmaxf(v2 * s0 + h0, 0.f);
                v3 = fmaxf(v3 * s1 + h1, 0.f);
            }
            if (EPI == 2) {
                bf16* Cb = (bf16*)Cv + (size_t)z * sCz;
                *(__nv_bfloat162*)&Cb[(size_t)r0 * N + col] =
                    __floats2bfloat162_rn(v0, v1);
                *(__nv_bfloat162*)&Cb[(size_t)(r0 + 8) * N + col] =
                    __floats2bfloat162_rn(v2, v3);
            } else if (EPI == 3) {
                float s0 = eg[col] * rsqrtf(ev[col] + 1e-5f);
                float h0 = eb[col] - em[col] * s0;
                float s1 = eg[col + 1] * rsqrtf(ev[col + 1] + 1e-5f);
                float h1 = eb[col + 1] - em[col + 1] * s1;
                const float* xin = zs ? RX1 : RX0;
                float* outp = (float*)Cv + (size_t)zs * BSZ * CIN * LSEQ;
                int b = r0 >> 10, hw = r0 & 1023;
                size_t p0 = ((size_t)b * CIN + col) * LSEQ + hw;
                size_t p1 = p0 + LSEQ;
                outp[p0]     = xin[p0]     + sg * (v0 * s0 + h0);
                outp[p1]     = xin[p1]     + sg * (v1 * s1 + h1);
                outp[p0 + 8] = xin[p0 + 8] + sg * (v2 * s0 + h0);
                outp[p1 + 8] = xin[p1 + 8] + sg * (v3 * s1 + h1);
            } else {
                float* Cf = (float*)Cv + (size_t)z * sCz;
                *(float2*)&Cf[(size_t)r0 * N + col]       = make_float2(v0, v1);
                *(float2*)&Cf[(size_t)(r0 + 8) * N + col] = make_float2(v2, v3);
            }
        }
    }
}

// ---------------- Wc split-K reduce ----------------
__global__ void wc_reduce() {
    int idx = blockIdx.x * 256 + threadIdx.x;
    int s = idx >> 18;
    int j = idx & (CIN * DI - 1);
    float v = d_wcp[s * 4 + 0][j] + d_wcp[s * 4 + 1][j] +
              d_wcp[s * 4 + 2][j] + d_wcp[s * 4 + 3][j];
    d_wc[s][j] = __float2bfloat16(v);
}

// ---------------- mega prep: weight cvt + input transpose + out_w transpose ----------------
#define PREP_N (DM * CIN + CIN * DM + 2 * (2 * DI * DM))
#define NB_PREP (PREP_N / 256)              // 9216
#define NB_TIN  (32 * 8 * 8)                // 2048
#define NB_TW   (32 * 16 * 2)               // 1024
__global__ void __launch_bounds__(256)
mega_prep(const float* __restrict__ crw, const float* __restrict__ crsw,
          const float* __restrict__ iw0, const float* __restrict__ iw1,
          const float* __restrict__ x0, const float* __restrict__ x1,
          const float* __restrict__ ow0, const float* __restrict__ ow1) {
    int bid = blockIdx.x;
    int tid = threadIdx.x;
    if (bid < NB_PREP) {
        int i = bid * 256 + tid;
        const int n1 = DM * CIN, n2 = n1 + CIN * DM, n3 = n2 + 2 * DI * DM;
        if (i < n1)       d_crw[i]           = __float2bfloat16(crw[i]);
        else if (i < n2)  d_crsw[i - n1]     = __float2bfloat16(crsw[i - n1]);
        else if (i < n3)  d_inw[0][i - n2]   = __float2bfloat16(iw0[i - n2]);
        else              d_inw[1][i - n3]   = __float2bfloat16(iw1[i - n3]);
    } else if (bid < NB_PREP + NB_TIN) {
        __shared__ float tile[32][33];
        int q = bid - NB_PREP;
        int zc = q >> 8;                    // 0..7
        int s = zc >> 2, b = zc & 3;
        int rem = q & 255;
        int c0 = (rem >> 5) * 32, hw0 = (rem & 31) * 32;
        const float* x = s ? x1 : x0;
        int tx = tid & 31, ty = tid >> 5;   // ty 0..7
#pragma unroll
        for (int r = 0; r < 4; r++) {
            int row = ty + r * 8;
            tile[row][tx] = x[((size_t)b * CIN + (c0 + row)) * LSEQ + hw0 + tx];
        }
        __syncthreads();
#pragma unroll
        for (int r = 0; r < 4; r++) {
            int row = ty + r * 8;
            d_xt[s][((size_t)b * LSEQ + hw0 + row) * CIN + c0 + tx] =
                __float2bfloat16(tile[tx][row]);
        }
    } else {
        __shared__ float tile[32][33];
        int q = bid - NB_PREP - NB_TIN;
        int s = q >> 9;
        int rem = q & 511;
        int r0 = (rem >> 5) * 32, c0 = (rem & 31) * 32;   // r over DM, c over DI
        const float* w = s ? ow1 : ow0;
        int tx = tid & 31, ty = tid >> 5;
#pragma unroll
        for (int r = 0; r < 4; r++) {
            int row = ty + r * 8;
            tile[row][tx] = w[(size_t)(r0 + row) * DI + c0 + tx];
        }
        __syncthreads();
#pragma unroll
        for (int r = 0; r < 4; r++) {
            int row = ty + r * 8;
            d_wt[s][(size_t)(c0 + row) * DM + r0 + tx] = __float2bfloat16(tile[tx][row]);
        }
    }
}

// ---------------- merged pool1 + layernorm ----------------
__global__ void __launch_bounds__(128)
poolln(const float* __restrict__ g0, const float* __restrict__ b0,
       const float* __restrict__ g1, const float* __restrict__ b1) {
    int bid = blockIdx.x;
    int t = threadIdx.x;
    if (bid < 2 * NTOK) {
        int s = bid >> 12;
        int n = bid & (NTOK - 1);
        const float* g = s ? g1 : g0;
        const float* b = s ? b1 : b0;
        float4 v = ((const float4*)(d_seq[s] + (size_t)n * DM))[t];
        float sm = v.x + v.y + v.z + v.w;
        float sq = v.x * v.x + v.y * v.y + v.z * v.z + v.w * v.w;
#pragma unroll
        for (int o = 16; o; o >>= 1) {
            sm += __shfl_xor_sync(0xffffffffu, sm, o);
            sq += __shfl_xor_sync(0xffffffffu, sq, o);
        }
        __shared__ float ss[4], sqs[4];
        int w = t >> 5, ln = t & 31;
        if (ln == 0) { ss[w] = sm; sqs[w] = sq; }
        __syncthreads();
        sm = ss[0] + ss[1] + ss[2] + ss[3];
        sq = sqs[0] + sqs[1] + sqs[2] + sqs[3];
        float mu = sm * (1.f / DM);
        float var = sq * (1.f / DM) - mu * mu;
        float inv = rsqrtf(var + 1e-5f);
        float4 gg = ((const float4*)g)[t];
        float4 bb = ((const float4*)b)[t];
        __nv_bfloat162* dst = (__nv_bfloat162*)(d_xn[s] + (size_t)n * DM);
        dst[2 * t]     = __floats2bfloat162_rn((v.x - mu) * inv * gg.x + bb.x,
                                               (v.y - mu) * inv * gg.y + bb.y);
        dst[2 * t + 1] = __floats2bfloat162_rn((v.z - mu) * inv * gg.z + bb.z,
                                               (v.w - mu) * inv * gg.w + bb.w);
    } else {
        int p = bid - 2 * NTOK;             // 0..127
        int chunk = p & 15;
        int sb = p >> 4;
        int s = sb >> 2, b = sb & 3;
#pragma unroll
        for (int j = 0; j < 4; j++) {
            int d = t + j * 128;
            const float* pp = d_seq[s] + ((size_t)b * LSEQ + chunk * 64) * DM + d;
            float acc = 0.f;
#pragma unroll 8
            for (int l = 0; l < 64; l++) acc += pp[(size_t)l * DM];
            d_ppart[s][chunk][b * DM + d] = acc;
        }
    }
}

// ---------------- lambda predictor ----------------
__global__ void lambda_kernel(const float* __restrict__ w1, const float* __restrict__ b1,
                              const float* __restrict__ w2, const float* __restrict__ b2) {
    int b = blockIdx.x, j = threadIdx.x;
    __shared__ float pooled[2 * DM];
    for (int idx = j; idx < 2 * DM; idx += 128) {
        int s = idx >> 9, d = idx & (DM - 1);
        float acc = 0.f;
#pragma unroll
        for (int c = 0; c < 16; c++) acc += d_ppart[s][c][b * DM + d];
        pooled[idx] = acc * (1.0f / LSEQ);
    }
    __syncthreads();
    const float* w = w1 + (size_t)j * (2 * DM);
    float acc = b1[j];
    for (int c = 0; c < DM; c++) acc += pooled[c] * w[c];
    for (int c = 0; c < DM; c++) acc += pooled[DM + c] * w[DM + c];
    __shared__ float h1[128];
    h1[j] = fmaxf(acc, 0.f);
    __syncthreads();
    if (j == 0) {
        float l0 = b2[0], l1 = b2[1];
        for (int c = 0; c < 128; c++) { l0 += h1[c] * w2[c]; l1 += h1[c] * w2[128 + c]; }
        float mx = fmaxf(l0, l1);
        float e0 = expf(l0 - mx), e1 = expf(l1 - mx);
        float inv = 1.f / (e0 + e1);
        d_lam[b * 2 + 0] = e0 * inv;
        d_lam[b * 2 + 1] = e1 * inv;
    }
}

// ================= chunked parallel scan =================
__device__ __forceinline__ size_t hf_off(int s, int dir, int b, int c, int i) {
    return (((((size_t)s * 2 + dir) * 4 + b) * NCH + c) * DS) * 1024 + i;
}

// pass1: chunk-final h for chunks 0..6 (chunk 7's final feeds nothing)
__global__ void __launch_bounds__(256)
scan_pass1(const float* __restrict__ VA, const float* __restrict__ VB,
           const float* __restrict__ IA, const float* __restrict__ IB) {
    int idx = blockIdx.x * 256 + threadIdx.x;   // 114688
    int i   = idx & 1023;
    int r   = idx >> 10;                        // 0..111
    int c   = r % 7;
    int r2  = r / 7;
    int b   = r2 & 3;
    int dir = (r2 >> 2) & 1;
    int s   = (r2 >> 3) & 1;

    const float* Alog = s ? IA : VA;
    const float* Bown = s ? IB : VB;
    const float* Both = s ? VB : IB;
    float w0 = 0.5f * d_lam[b * 2 + 0];
    float w1 = 0.5f * d_lam[b * 2 + 1];

    u64 A2[8], Be2[8], h2[8];
#pragma unroll
    for (int k = 0; k < 8; k++) {
        float a0 = fminf(fmaxf(-expf(Alog[i * DS + 2 * k]),     -10.f), -0.01f);
        float a1 = fminf(fmaxf(-expf(Alog[i * DS + 2 * k + 1]), -10.f), -0.01f);
        A2[k]  = pack2(a0, a1);
        Be2[k] = pack2(w0 * Bown[i * DS + 2 * k]     + w1 * Both[i * DS + 2 * k],
                       w0 * Bown[i * DS + 2 * k + 1] + w1 * Both[i * DS + 2 * k + 1]);
        h2[k] = 0ull;
    }

    const bf16* xs = d_xp[s] + (size_t)b * LSEQ * (2 * DI) + i;
    int t  = dir ? (LSEQ - 1 - c * CHL) : c * CHL;
    int dt = dir ? -1 : 1;

    for (int step = 0; step < CHL; step++, t += dt) {
        float x = __bfloat162float(xs[(size_t)t * (2 * DI)]);
        u64 xd = pack2(x, x);
#pragma unroll
        for (int k = 0; k < 8; k++)
            h2[k] = fma2_(h2[k], A2[k], fma2_(Be2[k], xd, 0ull));
    }

    size_t o0 = hf_off(s, dir, b, c, i);
#pragma unroll
    for (int k = 0; k < 8; k++) {
        float2 f = unpack2(h2[k]);
        d_hfin[o0 + (size_t)(2 * k) * 1024]     = f.x;
        d_hfin[o0 + (size_t)(2 * k + 1) * 1024] = f.y;
    }
}

// merged pass3: in-thread chunk prefix (replaces pass2) + fwd scan (y_fwd in smem)
// + bwd scan emitting u.
__global__ void __launch_bounds__(256)
scan_pass3m(const float* __restrict__ VA, const float* __restrict__ VB,
            const float* __restrict__ VC, const float* __restrict__ IA,
            const float* __restrict__ IB, const float* __restrict__ IC) {
    extern __shared__ bf16 yfs[];               // [CHL][256]
    int tid = threadIdx.x;
    int idx = blockIdx.x * 256 + tid;           // 65536
    int i   = idx & 1023;
    int c   = (idx >> 10) & 7;
    int b   = (idx >> 13) & 3;
    int s   = (idx >> 14) & 1;

    const float* Alog = s ? IA : VA;
    const float* Bown = s ? IB : VB;
    const float* Both = s ? VB : IB;
    const float* Cp   = s ? IC : VC;
    float w0 = 0.5f * d_lam[b * 2 + 0];
    float w1 = 0.5f * d_lam[b * 2 + 1];

    u64 A2[8], Be2[8], C2[8], h2[8];
#pragma unroll
    for (int k = 0; k < 8; k++) {
        float a0 = fminf(fmaxf(-expf(Alog[i * DS + 2 * k]),     -10.f), -0.01f);
        float a1 = fminf(fmaxf(-expf(Alog[i * DS + 2 * k + 1]), -10.f), -0.01f);
        A2[k]  = pack2(a0, a1);
        Be2[k] = pack2(w0 * Bown[i * DS + 2 * k]     + w1 * Both[i * DS + 2 * k],
                       w0 * Bown[i * DS + 2 * k + 1] + w1 * Both[i * DS + 2 * k + 1]);
        C2[k]  = pack2(Cp[i * DS + 2 * k], Cp[i * DS + 2 * k + 1]);
    }

    // a128 = A^CHL via 7 packed squarings (same arithmetic as old pass2)
    u64 a128[8];
#pragma unroll
    for (int k = 0; k < 8; k++) {
        u64 a = A2[k];
#pragma unroll
        for (int q = 0; q < 7; q++) a = fma2_(a, a, 0ull);
        a128[k] = a;
    }

    const bf16* xs = d_xp[s] + (size_t)b * LSEQ * (2 * DI) + i;
    const bf16* gs = xs + DI;
    bf16* uo = d_u[s] + (size_t)b * LSEQ * DI + i;
    const int t0 = c * CHL;
    const int cb = NCH - 1 - c;                 // bwd chunk covering same window

    // ---- forward: fold prefix (chunks 0..c-1), then scan window ----
    {
#pragma unroll
        for (int k = 0; k < 8; k++) h2[k] = 0ull;
        for (int cc = 0; cc < c; cc++) {
            size_t o = hf_off(s, 0, b, cc, i);
#pragma unroll
            for (int k = 0; k < 8; k++) {
                u64 fin = pack2(d_hfin[o + (size_t)(2 * k) * 1024],
                                d_hfin[o + (size_t)(2 * k + 1) * 1024]);
                h2[k] = fma2_(h2[k], a128[k], fin);
            }
        }
        for (int step = 0; step < CHL; step++) {
            float x = __bfloat162float(xs[(size_t)(t0 + step) * (2 * DI)]);
            u64 xd = pack2(x, x);
            u64 yp = 0ull;
#pragma unroll
            for (int k = 0; k < 8; k++) {
                h2[k] = fma2_(h2[k], A2[k], fma2_(Be2[k], xd, 0ull));
                yp = fma2_(h2[k], C2[k], yp);
            }
            float2 f = unpack2(yp);
            yfs[step * 256 + tid] = __float2bfloat16(f.x + f.y);
        }
    }
    // ---- backward: fold prefix (bwd chunks 0..cb-1), scan window, emit u ----
    {
#pragma unroll
        for (int k = 0; k < 8; k++) h2[k] = 0ull;
        for (int cc = 0; cc < cb; cc++) {
            size_t o = hf_off(s, 1, b, cc, i);
#pragma unroll
            for (int k = 0; k < 8; k++) {
                u64 fin = pack2(d_hfin[o + (size_t)(2 * k) * 1024],
                                d_hfin[o + (size_t)(2 * k + 1) * 1024]);
                h2[k] = fma2_(h2[k], a128[k], fin);
            }
        }
        for (int step = 0; step < CHL; step++) {
            int ls = CHL - 1 - step;
            int t = t0 + ls;
            float x = __bfloat162float(xs[(size_t)t * (2 * DI)]);
            u64 xd = pack2(x, x);
            u64 yp = 0ull;
#pragma unroll
            for (int k = 0; k < 8; k++) {
                h2[k] = fma2_(h2[k], A2[k], fma2_(Be2[k], xd, 0ull));
                yp = fma2_(h2[k], C2[k], yp);
            }
            float2 f = unpack2(yp);
            float yb = f.x + f.y;
            float yf = __bfloat162float(yfs[ls * 256 + tid]);
            float g = __bfloat162float(gs[(size_t)t * (2 * DI)]);
            float sig = 1.f / (1.f + expf(-g));
            uo[(size_t)t * DI] = __float2bfloat16((yf + yb) * g * sig);
        }
    }
}

// ---------------- launch ----------------
extern "C" void kernel_launch(void* const* d_in, const int* in_sizes, int n_in,
                              void* d_out, int out_size) {
    const float* x_V        = (const float*)d_in[0];
    const float* x_I        = (const float*)d_in[1];
    const float* conv_red_w = (const float*)d_in[2];
    const float* bn_red_g   = (const float*)d_in[3];
    const float* bn_red_b   = (const float*)d_in[4];
    const float* bn_red_m   = (const float*)d_in[5];
    const float* bn_red_v   = (const float*)d_in[6];
    const float* conv_res_w = (const float*)d_in[7];
    const float* bn_res_g   = (const float*)d_in[8];
    const float* bn_res_b   = (const float*)d_in[9];
    const float* bn_res_m   = (const float*)d_in[10];
    const float* bn_res_v   = (const float*)d_in[11];
    const float* lam_w1     = (const float*)d_in[12];
    const float* lam_b1     = (const float*)d_in[13];
    const float* lam_w2     = (const float*)d_in[14];
    const float* lam_b2     = (const float*)d_in[15];
    const float* in_w[2]    = {(const float*)d_in[16], (const float*)d_in[23]};
    const float* out_w[2]   = {(const float*)d_in[17], (const float*)d_in[24]};
    const float* A_log[2]   = {(const float*)d_in[18], (const float*)d_in[25]};
    const float* Bmat[2]    = {(const float*)d_in[19], (const float*)d_in[26]};
    const float* Cmat[2]    = {(const float*)d_in[20], (const float*)d_in[27]};
    const float* ln_g[2]    = {(const float*)d_in[21], (const float*)d_in[28]};
    const float* ln_b[2]    = {(const float*)d_in[22], (const float*)d_in[29]};
    const float* gate       = (const float*)d_in[30];

    bf16 *XT, *XN, *XP, *U, *WT, *WC, *CRW, *CRSW, *INW;
    float *SEQ, *WCP;
    cudaGetSymbolAddress((void**)&XT,   d_xt);
    cudaGetSymbolAddress((void**)&SEQ,  d_seq);
    cudaGetSymbolAddress((void**)&XN,   d_xn);
    cudaGetSymbolAddress((void**)&XP,   d_xp);
    cudaGetSymbolAddress((void**)&U,    d_u);
    cudaGetSymbolAddress((void**)&WT,   d_wt);
    cudaGetSymbolAddress((void**)&WC,   d_wc);
    cudaGetSymbolAddress((void**)&WCP,  d_wcp);
    cudaGetSymbolAddress((void**)&CRW,  d_crw);
    cudaGetSymbolAddress((void**)&CRSW, d_crsw);
    cudaGetSymbolAddress((void**)&INW,  d_inw);

    cudaFuncSetAttribute(tgemm<0>, cudaFuncAttributeMaxDynamicSharedMemorySize, TG_SMEM);
    cudaFuncSetAttribute(tgemm<1>, cudaFuncAttributeMaxDynamicSharedMemorySize, TG_SMEM);
    cudaFuncSetAttribute(tgemm<2>, cudaFuncAttributeMaxDynamicSharedMemorySize, TG_SMEM);
    cudaFuncSetAttribute(tgemm<3>, cudaFuncAttributeMaxDynamicSharedMemorySize, TG_SMEM);
    cudaFuncSetAttribute(scan_pass3m, cudaFuncAttributeMaxDynamicSharedMemorySize, 65536);

    // 0. mega prep (weights cvt + both transposes in one launch)
    mega_prep<<<NB_PREP + NB_TIN + NB_TW, 256>>>(
        conv_red_w, conv_res_w, in_w[0], in_w[1], x_V, x_I, out_w[0], out_w[1]);

    // 1. Wc split-K x4 -> reduce
    tgemm<0><<<dim3(DI / 128, 1, 8), 256, TG_SMEM>>>(
        CRSW, CRSW, WT, WT + (size_t)DI * DM, WCP, CIN, DI, DM / 4, DM, DM, 4,
        (long long)CIN * DI, nullptr, nullptr, nullptr, nullptr,
        nullptr, nullptr, nullptr);
    wc_reduce<<<2 * CIN * DI / 256, 256>>>();

    // 2. conv_red + BN + ReLU
    tgemm<1><<<dim3(DM / 128, NTOK / 256, 2), 256, TG_SMEM>>>(
        XT, XT + (size_t)NTOK * CIN, CRW, CRW, SEQ, NTOK, DM, CIN, CIN, CIN, 1,
        (long long)NTOK * DM, bn_red_g, bn_red_b, bn_red_m, bn_red_v,
        nullptr, nullptr, nullptr);

    // 3. merged pool + layernorm, then lambda
    poolln<<<2 * NTOK + 128, 128>>>(ln_g[0], ln_b[0], ln_g[1], ln_b[1]);
    lambda_kernel<<<4, 128>>>(lam_w1, lam_b1, lam_w2, lam_b2);

    // 4. in_proj (bf16 out)
    tgemm<2><<<dim3(2 * DI / 128, NTOK / 256, 2), 256, TG_SMEM>>>(
        XN, XN + (size_t)NTOK * DM, INW, INW + (size_t)2 * DI * DM, XP, NTOK, 2 * DI,
        DM, DM, DM, 1, (long long)NTOK * 2 * DI, nullptr, nullptr, nullptr, nullptr,
        nullptr, nullptr, nullptr);

    // 5. scan: pass1 (7 chunks/dir) + merged pass3 (in-thread prefix)
    scan_pass1<<<448, 256>>>(A_log[0], Bmat[0], A_log[1], Bmat[1]);
    scan_pass3m<<<256, 256, 65536>>>(A_log[0], Bmat[0], Cmat[0],
                                     A_log[1], Bmat[1], Cmat[1]);

    // 6. fused out_proj + conv_res + BN + residual + gate -> output
    tgemm<3><<<dim3(CIN / 128, NTOK / 256, 2), 256, TG_SMEM>>>(
        U, U + (size_t)NTOK * DI, WC, WC + (size_t)CIN * DI, (float*)d_out, NTOK, CIN,
        DI, DI, DI, 1, 0LL, bn_res_g, bn_res_b, bn_res_m, bn_res_v,
        x_V, x_I, gate);
}

// round 12
// speedup vs baseline: 4.7521x; 1.0895x over previous
#include <cuda_runtime.h>
#include <cuda_bf16.h>
#include <math.h>
#include <stdint.h>

#define NS   2
#define BSZ  4
#define LSEQ 1024
#define NTOK 4096
#define DM   512
#define DI   1024
#define DS   16
#define CIN  256
#define NCH  8
#define CHL  128

typedef __nv_bfloat16 bf16;
typedef unsigned long long u64;

// ---------------- scratch ----------------
__device__ bf16  d_xt[NS][NTOK * CIN];
__device__ float d_seq[NS][NTOK * DM];
__device__ float d_ppart[NS][16][BSZ * DM];
__device__ float d_lam[BSZ * 2];
__device__ bf16  d_xn[NS][NTOK * DM];
__device__ bf16  d_xp[NS][NTOK * 2 * DI];
__device__ bf16  d_u[NS][NTOK * DI];
__device__ bf16  d_wt[NS][DI * DM];
__device__ bf16  d_wc[NS][CIN * DI];
__device__ float d_wcp[8][CIN * DI];
__device__ bf16  d_crw[DM * CIN];
__device__ bf16  d_crsw[CIN * DM];
__device__ bf16  d_inw[NS][2 * DI * DM];
__device__ float d_hfin[NS * 2 * BSZ * NCH * DS * 1024];

// ---------------- PTX helpers ----------------
__device__ __forceinline__ uint32_t smem_u32(const void* p) {
    uint32_t a;
    asm("{ .reg .u64 t; cvta.to.shared.u64 t, %1; cvt.u32.u64 %0, t; }" : "=r"(a) : "l"(p));
    return a;
}
#define CP_ASYNC16(sp, gp) \
    asm volatile("cp.async.cg.shared.global [%0], [%1], 16;" :: "r"(sp), "l"(gp) : "memory")
#define CP_COMMIT() asm volatile("cp.async.commit_group;" ::: "memory")
#define CP_WAIT2()  asm volatile("cp.async.wait_group 2;" ::: "memory")

#define LDSM_X4(r0, r1, r2, r3, addr) \
    asm volatile("ldmatrix.sync.aligned.m8n8.x4.shared.b16 {%0,%1,%2,%3}, [%4];" \
                 : "=r"(r0), "=r"(r1), "=r"(r2), "=r"(r3) : "r"(addr))

#define MMA_BF16(d, a, b) \
    asm volatile("mma.sync.aligned.m16n8k16.row.col.f32.bf16.bf16.f32 " \
                 "{%0,%1,%2,%3}, {%4,%5,%6,%7}, {%8,%9}, {%0,%1,%2,%3};" \
                 : "+f"((d)[0]), "+f"((d)[1]), "+f"((d)[2]), "+f"((d)[3]) \
                 : "r"((a)[0]), "r"((a)[1]), "r"((a)[2]), "r"((a)[3]), \
                   "r"((b)[0]), "r"((b)[1]))

__device__ __forceinline__ u64 fma2_(u64 a, u64 b, u64 c) {
    u64 d;
    asm("fma.rn.f32x2 %0, %1, %2, %3;" : "=l"(d) : "l"(a), "l"(b), "l"(c));
    return d;
}
__device__ __forceinline__ u64 pack2(float lo, float hi) {
    u64 r;
    asm("mov.b64 %0, {%1, %2};" : "=l"(r) : "f"(lo), "f"(hi));
    return r;
}
__device__ __forceinline__ float2 unpack2(u64 v) {
    float2 f;
    asm("mov.b64 {%0, %1}, %2;" : "=f"(f.x), "=f"(f.y) : "l"(v));
    return f;
}

// ---------------- bf16 mma.sync GEMM: CTA 128x128, 128 threads, 2 CTAs/SM ----------------
// 4 warps (2Mx2N), warp tile 64x64, k-chunk 32, pitch 80B, 4-stage cp.async ring.
#define TG_PITCH   80
#define TG_MATA    (128 * TG_PITCH)          // 10240
#define TG_STAGE_B (2 * TG_MATA)             // 20480
#define TG_NST     4
#define TG_SMEM    (TG_NST * TG_STAGE_B)     // 81920

// EPI: 0 plain fp32, 1 BN+ReLU fp32, 2 bf16 out, 3 fused BN+residual+gate transposed out
template <int EPI>
__global__ void __launch_bounds__(128, 2)
tgemm(const bf16* __restrict__ A0, const bf16* __restrict__ A1,
      const bf16* __restrict__ B0, const bf16* __restrict__ B1,
      void* __restrict__ Cv, int M, int N, int K, int lda, int ldb, int zdiv,
      long long sCz,
      const float* __restrict__ eg, const float* __restrict__ eb,
      const float* __restrict__ em, const float* __restrict__ ev,
      const float* __restrict__ RX0, const float* __restrict__ RX1,
      const float* __restrict__ gp) {
    extern __shared__ float smf[];
    const uint32_t sbase = smem_u32(smf);

    const int tid  = threadIdx.x;
    const int lane = tid & 31;
    const int wid  = tid >> 5;               // 0..3
    const int z = blockIdx.z;
    const int zs = z / zdiv, kc = z % zdiv;
    const bf16* __restrict__ A = (zs ? A1 : A0) + (size_t)kc * K;
    const bf16* __restrict__ B = (zs ? B1 : B0) + (size_t)kc * K;
    const int m0 = blockIdx.y * 128, n0 = blockIdx.x * 128;
    const int wm = (wid >> 1) * 64;
    const int wn = (wid & 1) * 64;

    const int lr = tid >> 2;                 // 0..31
    const int lc = tid & 3;
    const int T = K / 32;

    auto load_stage = [&](int t) {
        if (t < T) {
            const int k0 = t * 32;
            uint32_t dst = sbase + (t & 3) * TG_STAGE_B;
#pragma unroll
            for (int i = 0; i < 4; i++) {
                int m = lr + i * 32;
                CP_ASYNC16(dst + m * TG_PITCH + lc * 16,
                           A + (size_t)(m0 + m) * lda + k0 + lc * 8);
            }
            dst += TG_MATA;
#pragma unroll
            for (int i = 0; i < 4; i++) {
                int n = lr + i * 32;
                CP_ASYNC16(dst + n * TG_PITCH + lc * 16,
                           B + (size_t)(n0 + n) * ldb + k0 + lc * 8);
            }
        }
        CP_COMMIT();
    };

    float c[4][8][4];
#pragma unroll
    for (int mt = 0; mt < 4; mt++)
#pragma unroll
        for (int nt = 0; nt < 8; nt++)
#pragma unroll
            for (int q = 0; q < 4; q++) c[mt][nt][q] = 0.f;

    load_stage(0);
    load_stage(1);
    load_stage(2);

    const int l15   = lane & 15;
    const int lhiA  = (lane >> 4) * 16;
    const int bnrow = (lane & 7) + ((lane >> 4) << 3);
    const int bkoff = ((lane >> 3) & 1) * 16;

    for (int t = 0; t < T; t++) {
        CP_WAIT2();
        __syncthreads();
        load_stage(t + 3);
        const uint32_t aB = sbase + (t & 3) * TG_STAGE_B;
        const uint32_t bB = aB + TG_MATA;
#pragma unroll
        for (int kk = 0; kk < 2; kk++) {
            uint32_t a[4][4], b[8][2];
#pragma unroll
            for (int mt = 0; mt < 4; mt++) {
                uint32_t addr = aB + (wm + mt * 16 + l15) * TG_PITCH + kk * 32 + lhiA;
                LDSM_X4(a[mt][0], a[mt][1], a[mt][2], a[mt][3], addr);
            }
#pragma unroll
            for (int nh = 0; nh < 4; nh++) {
                uint32_t addr = bB + (wn + nh * 16 + bnrow) * TG_PITCH + kk * 32 + bkoff;
                uint32_t r0, r1, r2, r3;
                LDSM_X4(r0, r1, r2, r3, addr);
                b[nh * 2][0] = r0; b[nh * 2][1] = r1;
                b[nh * 2 + 1][0] = r2; b[nh * 2 + 1][1] = r3;
            }
#pragma unroll
            for (int mt = 0; mt < 4; mt++)
#pragma unroll
                for (int nt = 0; nt < 8; nt++)
                    MMA_BF16(c[mt][nt], a[mt], b[nt]);
        }
    }

    const int gid = lane >> 2;
    const int tig = lane & 3;
    float sg = 0.f;
    if (EPI == 3) sg = 1.f / (1.f + expf(-gp[0]));
#pragma unroll
    for (int mt = 0; mt < 4; mt++) {
        const int r0 = m0 + wm + mt * 16 + gid;
#pragma unroll
        for (int nt = 0; nt < 8; nt++) {
            const int col = n0 + wn + nt * 8 + tig * 2;
            float v0 = c[mt][nt][0], v1 = c[mt][nt][1];
            float v2 = c[mt][nt][2], v3 = c[mt][nt][3];
            if (EPI == 1) {
                float s0 = eg[col] * rsqrtf(ev[col] + 1e-5f);
                float h0 = eb[col] - em[col] * s0;
                float s1 = eg[col + 1] * rsqrtf(ev[col + 1] + 1e-5f);
                float h1 = eb[col + 1] - em[col + 1] * s1;
                v0 = fmaxf(v0 * s0 + h0, 0.f);
                v1 = fmaxf(v1 * s1 + h1, 0.f);
                v2 = fmaxf(v2 * s0 + h0, 0.f);
                v3 = fmaxf(v3 * s1 + h1, 0.f);
            }
            if (EPI == 2) {
                bf16* Cb = (bf16*)Cv + (size_t)z * sCz;
                *(__nv_bfloat162*)&Cb[(size_t)r0 * N + col] =
                    __floats2bfloat162_rn(v0, v1);
                *(__nv_bfloat162*)&Cb[(size_t)(r0 + 8) * N + col] =
                    __floats2bfloat162_rn(v2, v3);
            } else if (EPI == 3) {
                float s0 = eg[col] * rsqrtf(ev[col] + 1e-5f);
                float h0 = eb[col] - em[col] * s0;
                float s1 = eg[col + 1] * rsqrtf(ev[col + 1] + 1e-5f);
                float h1 = eb[col + 1] - em[col + 1] * s1;
                const float* xin = zs ? RX1 : RX0;
                float* outp = (float*)Cv + (size_t)zs * BSZ * CIN * LSEQ;
                int b = r0 >> 10, hw = r0 & 1023;
                size_t p0 = ((size_t)b * CIN + col) * LSEQ + hw;
                size_t p1 = p0 + LSEQ;
                outp[p0]     = xin[p0]     + sg * (v0 * s0 + h0);
                outp[p1]     = xin[p1]     + sg * (v1 * s1 + h1);
                outp[p0 + 8] = xin[p0 + 8] + sg * (v2 * s0 + h0);
                outp[p1 + 8] = xin[p1 + 8] + sg * (v3 * s1 + h1);
            } else {
                float* Cf = (float*)Cv + (size_t)z * sCz;
                *(float2*)&Cf[(size_t)r0 * N + col]       = make_float2(v0, v1);
                *(float2*)&Cf[(size_t)(r0 + 8) * N + col] = make_float2(v2, v3);
            }
        }
    }
}

// ---------------- mega prep ----------------
#define PREP_N (DM * CIN + CIN * DM + 2 * (2 * DI * DM))
#define NB_PREP (PREP_N / 256)
#define NB_TIN  (32 * 8 * 8)
#define NB_TW   (32 * 16 * 2)
__global__ void __launch_bounds__(256)
mega_prep(const float* __restrict__ crw, const float* __restrict__ crsw,
          const float* __restrict__ iw0, const float* __restrict__ iw1,
          const float* __restrict__ x0, const float* __restrict__ x1,
          const float* __restrict__ ow0, const float* __restrict__ ow1) {
    int bid = blockIdx.x;
    int tid = threadIdx.x;
    if (bid < NB_PREP) {
        int i = bid * 256 + tid;
        const int n1 = DM * CIN, n2 = n1 + CIN * DM, n3 = n2 + 2 * DI * DM;
        if (i < n1)       d_crw[i]           = __float2bfloat16(crw[i]);
        else if (i < n2)  d_crsw[i - n1]     = __float2bfloat16(crsw[i - n1]);
        else if (i < n3)  d_inw[0][i - n2]   = __float2bfloat16(iw0[i - n2]);
        else              d_inw[1][i - n3]   = __float2bfloat16(iw1[i - n3]);
    } else if (bid < NB_PREP + NB_TIN) {
        __shared__ float tile[32][33];
        int q = bid - NB_PREP;
        int zc = q >> 8;
        int s = zc >> 2, b = zc & 3;
        int rem = q & 255;
        int c0 = (rem >> 5) * 32, hw0 = (rem & 31) * 32;
        const float* x = s ? x1 : x0;
        int tx = tid & 31, ty = tid >> 5;
#pragma unroll
        for (int r = 0; r < 4; r++) {
            int row = ty + r * 8;
            tile[row][tx] = x[((size_t)b * CIN + (c0 + row)) * LSEQ + hw0 + tx];
        }
        __syncthreads();
#pragma unroll
        for (int r = 0; r < 4; r++) {
            int row = ty + r * 8;
            d_xt[s][((size_t)b * LSEQ + hw0 + row) * CIN + c0 + tx] =
                __float2bfloat16(tile[tx][row]);
        }
    } else {
        __shared__ float tile[32][33];
        int q = bid - NB_PREP - NB_TIN;
        int s = q >> 9;
        int rem = q & 511;
        int r0 = (rem >> 5) * 32, c0 = (rem & 31) * 32;
        const float* w = s ? ow1 : ow0;
        int tx = tid & 31, ty = tid >> 5;
#pragma unroll
        for (int r = 0; r < 4; r++) {
            int row = ty + r * 8;
            tile[row][tx] = w[(size_t)(r0 + row) * DI + c0 + tx];
        }
        __syncthreads();
#pragma unroll
        for (int r = 0; r < 4; r++) {
            int row = ty + r * 8;
            d_wt[s][(size_t)(c0 + row) * DM + r0 + tx] = __float2bfloat16(tile[tx][row]);
        }
    }
}

// ---------------- merged pool1 + layernorm + wc_reduce ----------------
#define NB_WCR (2 * CIN * DI / 128)          // 4096
__global__ void __launch_bounds__(128)
poolln(const float* __restrict__ g0, const float* __restrict__ b0,
       const float* __restrict__ g1, const float* __restrict__ b1) {
    int bid = blockIdx.x;
    int t = threadIdx.x;
    if (bid < 2 * NTOK) {
        int s = bid >> 12;
        int n = bid & (NTOK - 1);
        const float* g = s ? g1 : g0;
        const float* b = s ? b1 : b0;
        float4 v = ((const float4*)(d_seq[s] + (size_t)n * DM))[t];
        float sm = v.x + v.y + v.z + v.w;
        float sq = v.x * v.x + v.y * v.y + v.z * v.z + v.w * v.w;
#pragma unroll
        for (int o = 16; o; o >>= 1) {
            sm += __shfl_xor_sync(0xffffffffu, sm, o);
            sq += __shfl_xor_sync(0xffffffffu, sq, o);
        }
        __shared__ float ss[4], sqs[4];
        int w = t >> 5, ln = t & 31;
        if (ln == 0) { ss[w] = sm; sqs[w] = sq; }
        __syncthreads();
        sm = ss[0] + ss[1] + ss[2] + ss[3];
        sq = sqs[0] + sqs[1] + sqs[2] + sqs[3];
        float mu = sm * (1.f / DM);
        float var = sq * (1.f / DM) - mu * mu;
        float inv = rsqrtf(var + 1e-5f);
        float4 gg = ((const float4*)g)[t];
        float4 bb = ((const float4*)b)[t];
        __nv_bfloat162* dst = (__nv_bfloat162*)(d_xn[s] + (size_t)n * DM);
        dst[2 * t]     = __floats2bfloat162_rn((v.x - mu) * inv * gg.x + bb.x,
                                               (v.y - mu) * inv * gg.y + bb.y);
        dst[2 * t + 1] = __floats2bfloat162_rn((v.z - mu) * inv * gg.z + bb.z,
                                               (v.w - mu) * inv * gg.w + bb.w);
    } else if (bid < 2 * NTOK + 128) {
        int p = bid - 2 * NTOK;
        int chunk = p & 15;
        int sb = p >> 4;
        int s = sb >> 2, b = sb & 3;
#pragma unroll
        for (int j = 0; j < 4; j++) {
            int d = t + j * 128;
            const float* pp = d_seq[s] + ((size_t)b * LSEQ + chunk * 64) * DM + d;
            float acc = 0.f;
#pragma unroll 8
            for (int l = 0; l < 64; l++) acc += pp[(size_t)l * DM];
            d_ppart[s][chunk][b * DM + d] = acc;
        }
    } else {
        int idx = (bid - 2 * NTOK - 128) * 128 + t;     // 0..524287
        int s = idx >> 18;
        int j = idx & (CIN * DI - 1);
        float v = d_wcp[s * 4 + 0][j] + d_wcp[s * 4 + 1][j] +
                  d_wcp[s * 4 + 2][j] + d_wcp[s * 4 + 3][j];
        d_wc[s][j] = __float2bfloat16(v);
    }
}

// ---------------- lambda predictor ----------------
__global__ void lambda_kernel(const float* __restrict__ w1, const float* __restrict__ b1,
                              const float* __restrict__ w2, const float* __restrict__ b2) {
    int b = blockIdx.x, j = threadIdx.x;
    __shared__ float pooled[2 * DM];
    for (int idx = j; idx < 2 * DM; idx += 128) {
        int s = idx >> 9, d = idx & (DM - 1);
        float acc = 0.f;
#pragma unroll
        for (int c = 0; c < 16; c++) acc += d_ppart[s][c][b * DM + d];
        pooled[idx] = acc * (1.0f / LSEQ);
    }
    __syncthreads();
    const float* w = w1 + (size_t)j * (2 * DM);
    float acc = b1[j];
    for (int c = 0; c < DM; c++) acc += pooled[c] * w[c];
    for (int c = 0; c < DM; c++) acc += pooled[DM + c] * w[DM + c];
    __shared__ float h1[128];
    h1[j] = fmaxf(acc, 0.f);
    __syncthreads();
    if (j == 0) {
        float l0 = b2[0], l1 = b2[1];
        for (int c = 0; c < 128; c++) { l0 += h1[c] * w2[c]; l1 += h1[c] * w2[128 + c]; }
        float mx = fmaxf(l0, l1);
        float e0 = expf(l0 - mx), e1 = expf(l1 - mx);
        float inv = 1.f / (e0 + e1);
        d_lam[b * 2 + 0] = e0 * inv;
        d_lam[b * 2 + 1] = e1 * inv;
    }
}

// ================= chunked parallel scan =================
__device__ __forceinline__ size_t hf_off(int s, int dir, int b, int c, int i) {
    return (((((size_t)s * 2 + dir) * 4 + b) * NCH + c) * DS) * 1024 + i;
}

__global__ void __launch_bounds__(256)
scan_pass1(const float* __restrict__ VA, const float* __restrict__ VB,
           const float* __restrict__ IA, const float* __restrict__ IB) {
    int idx = blockIdx.x * 256 + threadIdx.x;
    int i   = idx & 1023;
    int r   = idx >> 10;
    int c   = r % 7;
    int r2  = r / 7;
    int b   = r2 & 3;
    int dir = (r2 >> 2) & 1;
    int s   = (r2 >> 3) & 1;

    const float* Alog = s ? IA : VA;
    const float* Bown = s ? IB : VB;
    const float* Both = s ? VB : IB;
    float w0 = 0.5f * d_lam[b * 2 + 0];
    float w1 = 0.5f * d_lam[b * 2 + 1];

    u64 A2[8], Be2[8], h2[8];
#pragma unroll
    for (int k = 0; k < 8; k++) {
        float a0 = fminf(fmaxf(-expf(Alog[i * DS + 2 * k]),     -10.f), -0.01f);
        float a1 = fminf(fmaxf(-expf(Alog[i * DS + 2 * k + 1]), -10.f), -0.01f);
        A2[k]  = pack2(a0, a1);
        Be2[k] = pack2(w0 * Bown[i * DS + 2 * k]     + w1 * Both[i * DS + 2 * k],
                       w0 * Bown[i * DS + 2 * k + 1] + w1 * Both[i * DS + 2 * k + 1]);
        h2[k] = 0ull;
    }

    const bf16* xs = d_xp[s] + (size_t)b * LSEQ * (2 * DI) + i;
    int t  = dir ? (LSEQ - 1 - c * CHL) : c * CHL;
    int dt = dir ? -1 : 1;

    for (int step = 0; step < CHL; step++, t += dt) {
        float x = __bfloat162float(xs[(size_t)t * (2 * DI)]);
        u64 xd = pack2(x, x);
#pragma unroll
        for (int k = 0; k < 8; k++)
            h2[k] = fma2_(h2[k], A2[k], fma2_(Be2[k], xd, 0ull));
    }

    size_t o0 = hf_off(s, dir, b, c, i);
#pragma unroll
    for (int k = 0; k < 8; k++) {
        float2 f = unpack2(h2[k]);
        d_hfin[o0 + (size_t)(2 * k) * 1024]     = f.x;
        d_hfin[o0 + (size_t)(2 * k + 1) * 1024] = f.y;
    }
}

__global__ void __launch_bounds__(256)
scan_pass3m(const float* __restrict__ VA, const float* __restrict__ VB,
            const float* __restrict__ VC, const float* __restrict__ IA,
            const float* __restrict__ IB, const float* __restrict__ IC) {
    extern __shared__ bf16 yfs[];
    int tid = threadIdx.x;
    int idx = blockIdx.x * 256 + tid;
    int i   = idx & 1023;
    int c   = (idx >> 10) & 7;
    int b   = (idx >> 13) & 3;
    int s   = (idx >> 14) & 1;

    const float* Alog = s ? IA : VA;
    const float* Bown = s ? IB : VB;
    const float* Both = s ? VB : IB;
    const float* Cp   = s ? IC : VC;
    float w0 = 0.5f * d_lam[b * 2 + 0];
    float w1 = 0.5f * d_lam[b * 2 + 1];

    u64 A2[8], Be2[8], C2[8], h2[8];
#pragma unroll
    for (int k = 0; k < 8; k++) {
        float a0 = fminf(fmaxf(-expf(Alog[i * DS + 2 * k]),     -10.f), -0.01f);
        float a1 = fminf(fmaxf(-expf(Alog[i * DS + 2 * k + 1]), -10.f), -0.01f);
        A2[k]  = pack2(a0, a1);
        Be2[k] = pack2(w0 * Bown[i * DS + 2 * k]     + w1 * Both[i * DS + 2 * k],
                       w0 * Bown[i * DS + 2 * k + 1] + w1 * Both[i * DS + 2 * k + 1]);
        C2[k]  = pack2(Cp[i * DS + 2 * k], Cp[i * DS + 2 * k + 1]);
    }

    u64 a128[8];
#pragma unroll
    for (int k = 0; k < 8; k++) {
        u64 a = A2[k];
#pragma unroll
        for (int q = 0; q < 7; q++) a = fma2_(a, a, 0ull);
        a128[k] = a;
    }

    const bf16* xs = d_xp[s] + (size_t)b * LSEQ * (2 * DI) + i;
    const bf16* gs = xs + DI;
    bf16* uo = d_u[s] + (size_t)b * LSEQ * DI + i;
    const int t0 = c * CHL;
    const int cb = NCH - 1 - c;

    {
#pragma unroll
        for (int k = 0; k < 8; k++) h2[k] = 0ull;
        for (int cc = 0; cc < c; cc++) {
            size_t o = hf_off(s, 0, b, cc, i);
#pragma unroll
            for (int k = 0; k < 8; k++) {
                u64 fin = pack2(d_hfin[o + (size_t)(2 * k) * 1024],
                                d_hfin[o + (size_t)(2 * k + 1) * 1024]);
                h2[k] = fma2_(h2[k], a128[k], fin);
            }
        }
        for (int step = 0; step < CHL; step++) {
            float x = __bfloat162float(xs[(size_t)(t0 + step) * (2 * DI)]);
            u64 xd = pack2(x, x);
            u64 yp = 0ull;
#pragma unroll
            for (int k = 0; k < 8; k++) {
                h2[k] = fma2_(h2[k], A2[k], fma2_(Be2[k], xd, 0ull));
                yp = fma2_(h2[k], C2[k], yp);
            }
            float2 f = unpack2(yp);
            yfs[step * 256 + tid] = __float2bfloat16(f.x + f.y);
        }
    }
    {
#pragma unroll
        for (int k = 0; k < 8; k++) h2[k] = 0ull;
        for (int cc = 0; cc < cb; cc++) {
            size_t o = hf_off(s, 1, b, cc, i);
#pragma unroll
            for (int k = 0; k < 8; k++) {
                u64 fin = pack2(d_hfin[o + (size_t)(2 * k) * 1024],
                                d_hfin[o + (size_t)(2 * k + 1) * 1024]);
                h2[k] = fma2_(h2[k], a128[k], fin);
            }
        }
        for (int step = 0; step < CHL; step++) {
            int ls = CHL - 1 - step;
            int t = t0 + ls;
            float x = __bfloat162float(xs[(size_t)t * (2 * DI)]);
            u64 xd = pack2(x, x);
            u64 yp = 0ull;
#pragma unroll
            for (int k = 0; k < 8; k++) {
                h2[k] = fma2_(h2[k], A2[k], fma2_(Be2[k], xd, 0ull));
                yp = fma2_(h2[k], C2[k], yp);
            }
            float2 f = unpack2(yp);
            float yb = f.x + f.y;
            float yf = __bfloat162float(yfs[ls * 256 + tid]);
            float g = __bfloat162float(gs[(size_t)t * (2 * DI)]);
            float sig = 1.f / (1.f + expf(-g));
            uo[(size_t)t * DI] = __float2bfloat16((yf + yb) * g * sig);
        }
    }
}

// ---------------- launch ----------------
extern "C" void kernel_launch(void* const* d_in, const int* in_sizes, int n_in,
                              void* d_out, int out_size) {
    const float* x_V        = (const float*)d_in[0];
    const float* x_I        = (const float*)d_in[1];
    const float* conv_red_w = (const float*)d_in[2];
    const float* bn_red_g   = (const float*)d_in[3];
    const float* bn_red_b   = (const float*)d_in[4];
    const float* bn_red_m   = (const float*)d_in[5];
    const float* bn_red_v   = (const float*)d_in[6];
    const float* conv_res_w = (const float*)d_in[7];
    const float* bn_res_g   = (const float*)d_in[8];
    const float* bn_res_b   = (const float*)d_in[9];
    const float* bn_res_m   = (const float*)d_in[10];
    const float* bn_res_v   = (const float*)d_in[11];
    const float* lam_w1     = (const float*)d_in[12];
    const float* lam_b1     = (const float*)d_in[13];
    const float* lam_w2     = (const float*)d_in[14];
    const float* lam_b2     = (const float*)d_in[15];
    const float* in_w[2]    = {(const float*)d_in[16], (const float*)d_in[23]};
    const float* out_w[2]   = {(const float*)d_in[17], (const float*)d_in[24]};
    const float* A_log[2]   = {(const float*)d_in[18], (const float*)d_in[25]};
    const float* Bmat[2]    = {(const float*)d_in[19], (const float*)d_in[26]};
    const float* Cmat[2]    = {(const float*)d_in[20], (const float*)d_in[27]};
    const float* ln_g[2]    = {(const float*)d_in[21], (const float*)d_in[28]};
    const float* ln_b[2]    = {(const float*)d_in[22], (const float*)d_in[29]};
    const float* gate       = (const float*)d_in[30];

    bf16 *XT, *XN, *XP, *U, *WT, *WC, *CRW, *CRSW, *INW;
    float *SEQ, *WCP;
    cudaGetSymbolAddress((void**)&XT,   d_xt);
    cudaGetSymbolAddress((void**)&SEQ,  d_seq);
    cudaGetSymbolAddress((void**)&XN,   d_xn);
    cudaGetSymbolAddress((void**)&XP,   d_xp);
    cudaGetSymbolAddress((void**)&U,    d_u);
    cudaGetSymbolAddress((void**)&WT,   d_wt);
    cudaGetSymbolAddress((void**)&WC,   d_wc);
    cudaGetSymbolAddress((void**)&WCP,  d_wcp);
    cudaGetSymbolAddress((void**)&CRW,  d_crw);
    cudaGetSymbolAddress((void**)&CRSW, d_crsw);
    cudaGetSymbolAddress((void**)&INW,  d_inw);

    cudaFuncSetAttribute(tgemm<0>, cudaFuncAttributeMaxDynamicSharedMemorySize, TG_SMEM);
    cudaFuncSetAttribute(tgemm<1>, cudaFuncAttributeMaxDynamicSharedMemorySize, TG_SMEM);
    cudaFuncSetAttribute(tgemm<2>, cudaFuncAttributeMaxDynamicSharedMemorySize, TG_SMEM);
    cudaFuncSetAttribute(tgemm<3>, cudaFuncAttributeMaxDynamicSharedMemorySize, TG_SMEM);
    cudaFuncSetAttribute(scan_pass3m, cudaFuncAttributeMaxDynamicSharedMemorySize, 65536);

    // 0. mega prep
    mega_prep<<<NB_PREP + NB_TIN + NB_TW, 256>>>(
        conv_red_w, conv_res_w, in_w[0], in_w[1], x_V, x_I, out_w[0], out_w[1]);

    // 1. Wc split-K x4 (reduce folded into poolln)
    tgemm<0><<<dim3(DI / 128, CIN / 128, 8), 128, TG_SMEM>>>(
        CRSW, CRSW, WT, WT + (size_t)DI * DM, WCP, CIN, DI, DM / 4, DM, DM, 4,
        (long long)CIN * DI, nullptr, nullptr, nullptr, nullptr,
        nullptr, nullptr, nullptr);

    // 2. conv_red + BN + ReLU
    tgemm<1><<<dim3(DM / 128, NTOK / 128, 2), 128, TG_SMEM>>>(
        XT, XT + (size_t)NTOK * CIN, CRW, CRW, SEQ, NTOK, DM, CIN, CIN, CIN, 1,
        (long long)NTOK * DM, bn_red_g, bn_red_b, bn_red_m, bn_red_v,
        nullptr, nullptr, nullptr);

    // 3. pool + layernorm + wc_reduce, then lambda
    poolln<<<2 * NTOK + 128 + NB_WCR, 128>>>(ln_g[0], ln_b[0], ln_g[1], ln_b[1]);
    lambda_kernel<<<4, 128>>>(lam_w1, lam_b1, lam_w2, lam_b2);

    // 4. in_proj (bf16 out)
    tgemm<2><<<dim3(2 * DI / 128, NTOK / 128, 2), 128, TG_SMEM>>>(
        XN, XN + (size_t)NTOK * DM, INW, INW + (size_t)2 * DI * DM, XP, NTOK, 2 * DI,
        DM, DM, DM, 1, (long long)NTOK * 2 * DI, nullptr, nullptr, nullptr, nullptr,
        nullptr, nullptr, nullptr);

    // 5. scan
    scan_pass1<<<448, 256>>>(A_log[0], Bmat[0], A_log[1], Bmat[1]);
    scan_pass3m<<<256, 256, 65536>>>(A_log[0], Bmat[0], Cmat[0],
                                     A_log[1], Bmat[1], Cmat[1]);

    // 6. fused out_proj + conv_res + BN + residual + gate -> output
    tgemm<3><<<dim3(CIN / 128, NTOK / 128, 2), 128, TG_SMEM>>>(
        U, U + (size_t)NTOK * DI, WC, WC + (size_t)CIN * DI, (float*)d_out, NTOK, CIN,
        DI, DI, DI, 1, 0LL, bn_res_g, bn_res_b, bn_res_m, bn_res_v,
        x_V, x_I, gate);
}

// round 13
// speedup vs baseline: 4.8436x; 1.0193x over previous
#include <cuda_runtime.h>
#include <cuda_bf16.h>
#include <math.h>
#include <stdint.h>

#define NS   2
#define BSZ  4
#define LSEQ 1024
#define NTOK 4096
#define DM   512
#define DI   1024
#define DS   16
#define CIN  256
#define NCH  8
#define CHL  128

typedef __nv_bfloat16 bf16;
typedef unsigned long long u64;

// ---------------- scratch ----------------
__device__ bf16  d_xt[NS][NTOK * CIN];
__device__ bf16  d_seq[NS][NTOK * DM];        // conv_red out, bf16
__device__ float d_ppart[NS][16][BSZ * DM];
__device__ float d_lam[BSZ * 2];
__device__ bf16  d_xn[NS][NTOK * DM];
__device__ bf16  d_xp[NS][NTOK * 2 * DI];
__device__ bf16  d_u[NS][NTOK * DI];
__device__ bf16  d_wt[NS][DI * DM];
__device__ bf16  d_wc[NS][CIN * DI];
__device__ float d_wcp[8][CIN * DI];
__device__ bf16  d_crw[DM * CIN];
__device__ bf16  d_crsw[CIN * DM];
__device__ bf16  d_inw[NS][2 * DI * DM];
__device__ float d_hfin[NS * 2 * BSZ * NCH * DS * 1024];

// ---------------- PTX helpers ----------------
__device__ __forceinline__ uint32_t smem_u32(const void* p) {
    uint32_t a;
    asm("{ .reg .u64 t; cvta.to.shared.u64 t, %1; cvt.u32.u64 %0, t; }" : "=r"(a) : "l"(p));
    return a;
}
#define CP_ASYNC16(sp, gp) \
    asm volatile("cp.async.cg.shared.global [%0], [%1], 16;" :: "r"(sp), "l"(gp) : "memory")
#define CP_COMMIT() asm volatile("cp.async.commit_group;" ::: "memory")
#define CP_WAIT2()  asm volatile("cp.async.wait_group 2;" ::: "memory")

#define LDSM_X4(r0, r1, r2, r3, addr) \
    asm volatile("ldmatrix.sync.aligned.m8n8.x4.shared.b16 {%0,%1,%2,%3}, [%4];" \
                 : "=r"(r0), "=r"(r1), "=r"(r2), "=r"(r3) : "r"(addr))

#define MMA_BF16(d, a, b) \
    asm volatile("mma.sync.aligned.m16n8k16.row.col.f32.bf16.bf16.f32 " \
                 "{%0,%1,%2,%3}, {%4,%5,%6,%7}, {%8,%9}, {%0,%1,%2,%3};" \
                 : "+f"((d)[0]), "+f"((d)[1]), "+f"((d)[2]), "+f"((d)[3]) \
                 : "r"((a)[0]), "r"((a)[1]), "r"((a)[2]), "r"((a)[3]), \
                   "r"((b)[0]), "r"((b)[1]))

__device__ __forceinline__ u64 fma2_(u64 a, u64 b, u64 c) {
    u64 d;
    asm("fma.rn.f32x2 %0, %1, %2, %3;" : "=l"(d) : "l"(a), "l"(b), "l"(c));
    return d;
}
__device__ __forceinline__ u64 pack2(float lo, float hi) {
    u64 r;
    asm("mov.b64 %0, {%1, %2};" : "=l"(r) : "f"(lo), "f"(hi));
    return r;
}
__device__ __forceinline__ float2 unpack2(u64 v) {
    float2 f;
    asm("mov.b64 {%0, %1}, %2;" : "=f"(f.x), "=f"(f.y) : "l"(v));
    return f;
}

// ---------------- bf16 mma.sync GEMM: CTA 128x128, 128 threads, 2 CTAs/SM ----------------
#define TG_PITCH   80
#define TG_MATA    (128 * TG_PITCH)
#define TG_STAGE_B (2 * TG_MATA)
#define TG_NST     4
#define TG_SMEM    (TG_NST * TG_STAGE_B)

// EPI: 0 plain fp32, 1 BN+ReLU bf16 out, 2 bf16 out, 3 fused BN+residual+gate transposed out
template <int EPI>
__global__ void __launch_bounds__(128, 2)
tgemm(const bf16* __restrict__ A0, const bf16* __restrict__ A1,
      const bf16* __restrict__ B0, const bf16* __restrict__ B1,
      void* __restrict__ Cv, int M, int N, int K, int lda, int ldb, int zdiv,
      long long sCz,
      const float* __restrict__ eg, const float* __restrict__ eb,
      const float* __restrict__ em, const float* __restrict__ ev,
      const float* __restrict__ RX0, const float* __restrict__ RX1,
      const float* __restrict__ gp) {
    extern __shared__ float smf[];
    const uint32_t sbase = smem_u32(smf);

    const int tid  = threadIdx.x;
    const int lane = tid & 31;
    const int wid  = tid >> 5;
    const int z = blockIdx.z;
    const int zs = z / zdiv, kc = z % zdiv;
    const bf16* __restrict__ A = (zs ? A1 : A0) + (size_t)kc * K;
    const bf16* __restrict__ B = (zs ? B1 : B0) + (size_t)kc * K;
    const int m0 = blockIdx.y * 128, n0 = blockIdx.x * 128;
    const int wm = (wid >> 1) * 64;
    const int wn = (wid & 1) * 64;

    const int lr = tid >> 2;
    const int lc = tid & 3;
    const int T = K / 32;

    auto load_stage = [&](int t) {
        if (t < T) {
            const int k0 = t * 32;
            uint32_t dst = sbase + (t & 3) * TG_STAGE_B;
#pragma unroll
            for (int i = 0; i < 4; i++) {
                int m = lr + i * 32;
                CP_ASYNC16(dst + m * TG_PITCH + lc * 16,
                           A + (size_t)(m0 + m) * lda + k0 + lc * 8);
            }
            dst += TG_MATA;
#pragma unroll
            for (int i = 0; i < 4; i++) {
                int n = lr + i * 32;
                CP_ASYNC16(dst + n * TG_PITCH + lc * 16,
                           B + (size_t)(n0 + n) * ldb + k0 + lc * 8);
            }
        }
        CP_COMMIT();
    };

    float c[4][8][4];
#pragma unroll
    for (int mt = 0; mt < 4; mt++)
#pragma unroll
        for (int nt = 0; nt < 8; nt++)
#pragma unroll
            for (int q = 0; q < 4; q++) c[mt][nt][q] = 0.f;

    load_stage(0);
    load_stage(1);
    load_stage(2);

    const int l15   = lane & 15;
    const int lhiA  = (lane >> 4) * 16;
    const int bnrow = (lane & 7) + ((lane >> 4) << 3);
    const int bkoff = ((lane >> 3) & 1) * 16;

    for (int t = 0; t < T; t++) {
        CP_WAIT2();
        __syncthreads();
        load_stage(t + 3);
        const uint32_t aB = sbase + (t & 3) * TG_STAGE_B;
        const uint32_t bB = aB + TG_MATA;
#pragma unroll
        for (int kk = 0; kk < 2; kk++) {
            uint32_t a[4][4], b[8][2];
#pragma unroll
            for (int mt = 0; mt < 4; mt++) {
                uint32_t addr = aB + (wm + mt * 16 + l15) * TG_PITCH + kk * 32 + lhiA;
                LDSM_X4(a[mt][0], a[mt][1], a[mt][2], a[mt][3], addr);
            }
#pragma unroll
            for (int nh = 0; nh < 4; nh++) {
                uint32_t addr = bB + (wn + nh * 16 + bnrow) * TG_PITCH + kk * 32 + bkoff;
                uint32_t r0, r1, r2, r3;
                LDSM_X4(r0, r1, r2, r3, addr);
                b[nh * 2][0] = r0; b[nh * 2][1] = r1;
                b[nh * 2 + 1][0] = r2; b[nh * 2 + 1][1] = r3;
            }
#pragma unroll
            for (int mt = 0; mt < 4; mt++)
#pragma unroll
                for (int nt = 0; nt < 8; nt++)
                    MMA_BF16(c[mt][nt], a[mt], b[nt]);
        }
    }

    const int gid = lane >> 2;
    const int tig = lane & 3;
    float sg = 0.f;
    if (EPI == 3) sg = 1.f / (1.f + expf(-gp[0]));
#pragma unroll
    for (int mt = 0; mt < 4; mt++) {
        const int r0 = m0 + wm + mt * 16 + gid;
#pragma unroll
        for (int nt = 0; nt < 8; nt++) {
            const int col = n0 + wn + nt * 8 + tig * 2;
            float v0 = c[mt][nt][0], v1 = c[mt][nt][1];
            float v2 = c[mt][nt][2], v3 = c[mt][nt][3];
            if (EPI == 1) {
                float s0 = eg[col] * rsqrtf(ev[col] + 1e-5f);
                float h0 = eb[col] - em[col] * s0;
                float s1 = eg[col + 1] * rsqrtf(ev[col + 1] + 1e-5f);
                float h1 = eb[col + 1] - em[col + 1] * s1;
                v0 = fmaxf(v0 * s0 + h0, 0.f);
                v1 = fmaxf(v1 * s1 + h1, 0.f);
                v2 = fmaxf(v2 * s0 + h0, 0.f);
                v3 = fmaxf(v3 * s1 + h1, 0.f);
                bf16* Cb = (bf16*)Cv + (size_t)z * sCz;
                *(__nv_bfloat162*)&Cb[(size_t)r0 * N + col] =
                    __floats2bfloat162_rn(v0, v1);
                *(__nv_bfloat162*)&Cb[(size_t)(r0 + 8) * N + col] =
                    __floats2bfloat162_rn(v2, v3);
            } else if (EPI == 2) {
                bf16* Cb = (bf16*)Cv + (size_t)z * sCz;
                *(__nv_bfloat162*)&Cb[(size_t)r0 * N + col] =
                    __floats2bfloat162_rn(v0, v1);
                *(__nv_bfloat162*)&Cb[(size_t)(r0 + 8) * N + col] =
                    __floats2bfloat162_rn(v2, v3);
            } else if (EPI == 3) {
                float s0 = eg[col] * rsqrtf(ev[col] + 1e-5f);
                float h0 = eb[col] - em[col] * s0;
                float s1 = eg[col + 1] * rsqrtf(ev[col + 1] + 1e-5f);
                float h1 = eb[col + 1] - em[col + 1] * s1;
                const float* xin = zs ? RX1 : RX0;
                float* outp = (float*)Cv + (size_t)zs * BSZ * CIN * LSEQ;
                int b = r0 >> 10, hw = r0 & 1023;
                size_t p0 = ((size_t)b * CIN + col) * LSEQ + hw;
                size_t p1 = p0 + LSEQ;
                outp[p0]     = xin[p0]     + sg * (v0 * s0 + h0);
                outp[p1]     = xin[p1]     + sg * (v1 * s1 + h1);
                outp[p0 + 8] = xin[p0 + 8] + sg * (v2 * s0 + h0);
                outp[p1 + 8] = xin[p1 + 8] + sg * (v3 * s1 + h1);
            } else {
                float* Cf = (float*)Cv + (size_t)z * sCz;
                *(float2*)&Cf[(size_t)r0 * N + col]       = make_float2(v0, v1);
                *(float2*)&Cf[(size_t)(r0 + 8) * N + col] = make_float2(v2, v3);
            }
        }
    }
}

// ---------------- mega prep ----------------
#define PREP_N (DM * CIN + CIN * DM + 2 * (2 * DI * DM))
#define NB_PREP (PREP_N / 256)
#define NB_TIN  (32 * 8 * 8)
#define NB_TW   (32 * 16 * 2)
__global__ void __launch_bounds__(256)
mega_prep(const float* __restrict__ crw, const float* __restrict__ crsw,
          const float* __restrict__ iw0, const float* __restrict__ iw1,
          const float* __restrict__ x0, const float* __restrict__ x1,
          const float* __restrict__ ow0, const float* __restrict__ ow1) {
    int bid = blockIdx.x;
    int tid = threadIdx.x;
    if (bid < NB_PREP) {
        int i = bid * 256 + tid;
        const int n1 = DM * CIN, n2 = n1 + CIN * DM, n3 = n2 + 2 * DI * DM;
        if (i < n1)       d_crw[i]           = __float2bfloat16(crw[i]);
        else if (i < n2)  d_crsw[i - n1]     = __float2bfloat16(crsw[i - n1]);
        else if (i < n3)  d_inw[0][i - n2]   = __float2bfloat16(iw0[i - n2]);
        else              d_inw[1][i - n3]   = __float2bfloat16(iw1[i - n3]);
    } else if (bid < NB_PREP + NB_TIN) {
        __shared__ float tile[32][33];
        int q = bid - NB_PREP;
        int zc = q >> 8;
        int s = zc >> 2, b = zc & 3;
        int rem = q & 255;
        int c0 = (rem >> 5) * 32, hw0 = (rem & 31) * 32;
        const float* x = s ? x1 : x0;
        int tx = tid & 31, ty = tid >> 5;
#pragma unroll
        for (int r = 0; r < 4; r++) {
            int row = ty + r * 8;
            tile[row][tx] = x[((size_t)b * CIN + (c0 + row)) * LSEQ + hw0 + tx];
        }
        __syncthreads();
#pragma unroll
        for (int r = 0; r < 4; r++) {
            int row = ty + r * 8;
            d_xt[s][((size_t)b * LSEQ + hw0 + row) * CIN + c0 + tx] =
                __float2bfloat16(tile[tx][row]);
        }
    } else {
        __shared__ float tile[32][33];
        int q = bid - NB_PREP - NB_TIN;
        int s = q >> 9;
        int rem = q & 511;
        int r0 = (rem >> 5) * 32, c0 = (rem & 31) * 32;
        const float* w = s ? ow1 : ow0;
        int tx = tid & 31, ty = tid >> 5;
#pragma unroll
        for (int r = 0; r < 4; r++) {
            int row = ty + r * 8;
            tile[row][tx] = w[(size_t)(r0 + row) * DI + c0 + tx];
        }
        __syncthreads();
#pragma unroll
        for (int r = 0; r < 4; r++) {
            int row = ty + r * 8;
            d_wt[s][(size_t)(c0 + row) * DM + r0 + tx] = __float2bfloat16(tile[tx][row]);
        }
    }
}

// ---------------- merged pool1 + layernorm + wc_reduce (bf16 d_seq) ----------------
#define NB_WCR (2 * CIN * DI / 128)
__global__ void __launch_bounds__(128)
poolln(const float* __restrict__ g0, const float* __restrict__ b0,
       const float* __restrict__ g1, const float* __restrict__ b1) {
    int bid = blockIdx.x;
    int t = threadIdx.x;
    if (bid < 2 * NTOK) {
        int s = bid >> 12;
        int n = bid & (NTOK - 1);
        const float* g = s ? g1 : g0;
        const float* b = s ? b1 : b0;
        const __nv_bfloat162* src = (const __nv_bfloat162*)(d_seq[s] + (size_t)n * DM);
        float2 p0 = __bfloat1622float2(src[2 * t]);
        float2 p1 = __bfloat1622float2(src[2 * t + 1]);
        float4 v = make_float4(p0.x, p0.y, p1.x, p1.y);
        float sm = v.x + v.y + v.z + v.w;
        float sq = v.x * v.x + v.y * v.y + v.z * v.z + v.w * v.w;
#pragma unroll
        for (int o = 16; o; o >>= 1) {
            sm += __shfl_xor_sync(0xffffffffu, sm, o);
            sq += __shfl_xor_sync(0xffffffffu, sq, o);
        }
        __shared__ float ss[4], sqs[4];
        int w = t >> 5, ln = t & 31;
        if (ln == 0) { ss[w] = sm; sqs[w] = sq; }
        __syncthreads();
        sm = ss[0] + ss[1] + ss[2] + ss[3];
        sq = sqs[0] + sqs[1] + sqs[2] + sqs[3];
        float mu = sm * (1.f / DM);
        float var = sq * (1.f / DM) - mu * mu;
        float inv = rsqrtf(var + 1e-5f);
        float4 gg = ((const float4*)g)[t];
        float4 bb = ((const float4*)b)[t];
        __nv_bfloat162* dst = (__nv_bfloat162*)(d_xn[s] + (size_t)n * DM);
        dst[2 * t]     = __floats2bfloat162_rn((v.x - mu) * inv * gg.x + bb.x,
                                               (v.y - mu) * inv * gg.y + bb.y);
        dst[2 * t + 1] = __floats2bfloat162_rn((v.z - mu) * inv * gg.z + bb.z,
                                               (v.w - mu) * inv * gg.w + bb.w);
    } else if (bid < 2 * NTOK + 128) {
        int p = bid - 2 * NTOK;
        int chunk = p & 15;
        int sb = p >> 4;
        int s = sb >> 2, b = sb & 3;
#pragma unroll
        for (int j = 0; j < 2; j++) {
            int d2 = t + j * 128;                     // bf16x2 index: 256 pairs cover 512
            const __nv_bfloat162* pp = (const __nv_bfloat162*)
                (d_seq[s] + ((size_t)b * LSEQ + chunk * 64) * DM) + d2;
            float a0 = 0.f, a1 = 0.f;
#pragma unroll 8
            for (int l = 0; l < 64; l++) {
                float2 f = __bfloat1622float2(pp[(size_t)l * (DM / 2)]);
                a0 += f.x; a1 += f.y;
            }
            d_ppart[s][chunk][b * DM + 2 * d2]     = a0;
            d_ppart[s][chunk][b * DM + 2 * d2 + 1] = a1;
        }
    } else {
        int idx = (bid - 2 * NTOK - 128) * 128 + t;
        int s = idx >> 18;
        int j = idx & (CIN * DI - 1);
        float v = d_wcp[s * 4 + 0][j] + d_wcp[s * 4 + 1][j] +
                  d_wcp[s * 4 + 2][j] + d_wcp[s * 4 + 3][j];
        d_wc[s][j] = __float2bfloat16(v);
    }
}

// ---------------- lambda predictor ----------------
__global__ void lambda_kernel(const float* __restrict__ w1, const float* __restrict__ b1,
                              const float* __restrict__ w2, const float* __restrict__ b2) {
    int b = blockIdx.x, j = threadIdx.x;
    __shared__ float pooled[2 * DM];
    for (int idx = j; idx < 2 * DM; idx += 128) {
        int s = idx >> 9, d = idx & (DM - 1);
        float acc = 0.f;
#pragma unroll
        for (int c = 0; c < 16; c++) acc += d_ppart[s][c][b * DM + d];
        pooled[idx] = acc * (1.0f / LSEQ);
    }
    __syncthreads();
    const float* w = w1 + (size_t)j * (2 * DM);
    float acc = b1[j];
    for (int c = 0; c < DM; c++) acc += pooled[c] * w[c];
    for (int c = 0; c < DM; c++) acc += pooled[DM + c] * w[DM + c];
    __shared__ float h1[128];
    h1[j] = fmaxf(acc, 0.f);
    __syncthreads();
    if (j == 0) {
        float l0 = b2[0], l1 = b2[1];
        for (int c = 0; c < 128; c++) { l0 += h1[c] * w2[c]; l1 += h1[c] * w2[128 + c]; }
        float mx = fmaxf(l0, l1);
        float e0 = expf(l0 - mx), e1 = expf(l1 - mx);
        float inv = 1.f / (e0 + e1);
        d_lam[b * 2 + 0] = e0 * inv;
        d_lam[b * 2 + 1] = e1 * inv;
    }
}

// ================= chunked parallel scan =================
__device__ __forceinline__ size_t hf_off(int s, int dir, int b, int c, int i) {
    return (((((size_t)s * 2 + dir) * 4 + b) * NCH + c) * DS) * 1024 + i;
}

__global__ void __launch_bounds__(256)
scan_pass1(const float* __restrict__ VA, const float* __restrict__ VB,
           const float* __restrict__ IA, const float* __restrict__ IB) {
    int idx = blockIdx.x * 256 + threadIdx.x;
    int i   = idx & 1023;
    int r   = idx >> 10;
    int c   = r % 7;
    int r2  = r / 7;
    int b   = r2 & 3;
    int dir = (r2 >> 2) & 1;
    int s   = (r2 >> 3) & 1;

    const float* Alog = s ? IA : VA;
    const float* Bown = s ? IB : VB;
    const float* Both = s ? VB : IB;
    float w0 = 0.5f * d_lam[b * 2 + 0];
    float w1 = 0.5f * d_lam[b * 2 + 1];

    u64 A2[8], Be2[8], h2[8];
#pragma unroll
    for (int k = 0; k < 8; k++) {
        float a0 = fminf(fmaxf(-expf(Alog[i * DS + 2 * k]),     -10.f), -0.01f);
        float a1 = fminf(fmaxf(-expf(Alog[i * DS + 2 * k + 1]), -10.f), -0.01f);
        A2[k]  = pack2(a0, a1);
        Be2[k] = pack2(w0 * Bown[i * DS + 2 * k]     + w1 * Both[i * DS + 2 * k],
                       w0 * Bown[i * DS + 2 * k + 1] + w1 * Both[i * DS + 2 * k + 1]);
        h2[k] = 0ull;
    }

    const bf16* xs = d_xp[s] + (size_t)b * LSEQ * (2 * DI) + i;
    int t  = dir ? (LSEQ - 1 - c * CHL) : c * CHL;
    int dt = dir ? -1 : 1;

    for (int step = 0; step < CHL; step++, t += dt) {
        float x = __bfloat162float(xs[(size_t)t * (2 * DI)]);
        u64 xd = pack2(x, x);
#pragma unroll
        for (int k = 0; k < 8; k++)
            h2[k] = fma2_(h2[k], A2[k], fma2_(Be2[k], xd, 0ull));
    }

    size_t o0 = hf_off(s, dir, b, c, i);
#pragma unroll
    for (int k = 0; k < 8; k++) {
        float2 f = unpack2(h2[k]);
        d_hfin[o0 + (size_t)(2 * k) * 1024]     = f.x;
        d_hfin[o0 + (size_t)(2 * k + 1) * 1024] = f.y;
    }
}

__global__ void __launch_bounds__(256, 2)
scan_pass3m(const float* __restrict__ VA, const float* __restrict__ VB,
            const float* __restrict__ VC, const float* __restrict__ IA,
            const float* __restrict__ IB, const float* __restrict__ IC) {
    extern __shared__ bf16 yfs[];
    int tid = threadIdx.x;
    int idx = blockIdx.x * 256 + tid;
    int i   = idx & 1023;
    int c   = (idx >> 10) & 7;
    int b   = (idx >> 13) & 3;
    int s   = (idx >> 14) & 1;

    const float* Alog = s ? IA : VA;
    const float* Bown = s ? IB : VB;
    const float* Both = s ? VB : IB;
    const float* Cp   = s ? IC : VC;
    float w0 = 0.5f * d_lam[b * 2 + 0];
    float w1 = 0.5f * d_lam[b * 2 + 1];

    u64 A2[8], Be2[8], C2[8], h2[8];
#pragma unroll
    for (int k = 0; k < 8; k++) {
        float a0 = fminf(fmaxf(-expf(Alog[i * DS + 2 * k]),     -10.f), -0.01f);
        float a1 = fminf(fmaxf(-expf(Alog[i * DS + 2 * k + 1]), -10.f), -0.01f);
        A2[k]  = pack2(a0, a1);
        Be2[k] = pack2(w0 * Bown[i * DS + 2 * k]     + w1 * Both[i * DS + 2 * k],
                       w0 * Bown[i * DS + 2 * k + 1] + w1 * Both[i * DS + 2 * k + 1]);
        C2[k]  = pack2(Cp[i * DS + 2 * k], Cp[i * DS + 2 * k + 1]);
    }

    u64 a128[8];
#pragma unroll
    for (int k = 0; k < 8; k++) {
        u64 a = A2[k];
#pragma unroll
        for (int q = 0; q < 7; q++) a = fma2_(a, a, 0ull);
        a128[k] = a;
    }

    const bf16* xs = d_xp[s] + (size_t)b * LSEQ * (2 * DI) + i;
    const bf16* gs = xs + DI;
    bf16* uo = d_u[s] + (size_t)b * LSEQ * DI + i;
    const int t0 = c * CHL;
    const int cb = NCH - 1 - c;

    {
#pragma unroll
        for (int k = 0; k < 8; k++) h2[k] = 0ull;
        for (int cc = 0; cc < c; cc++) {
            size_t o = hf_off(s, 0, b, cc, i);
#pragma unroll
            for (int k = 0; k < 8; k++) {
                u64 fin = pack2(d_hfin[o + (size_t)(2 * k) * 1024],
                                d_hfin[o + (size_t)(2 * k + 1) * 1024]);
                h2[k] = fma2_(h2[k], a128[k], fin);
            }
        }
        for (int step = 0; step < CHL; step++) {
            float x = __bfloat162float(xs[(size_t)(t0 + step) * (2 * DI)]);
            u64 xd = pack2(x, x);
            u64 yp = 0ull;
#pragma unroll
            for (int k = 0; k < 8; k++) {
                h2[k] = fma2_(h2[k], A2[k], fma2_(Be2[k], xd, 0ull));
                yp = fma2_(h2[k], C2[k], yp);
            }
            float2 f = unpack2(yp);
            yfs[step * 256 + tid] = __float2bfloat16(f.x + f.y);
        }
    }
    {
#pragma unroll
        for (int k = 0; k < 8; k++) h2[k] = 0ull;
        for (int cc = 0; cc < cb; cc++) {
            size_t o = hf_off(s, 1, b, cc, i);
#pragma unroll
            for (int k = 0; k < 8; k++) {
                u64 fin = pack2(d_hfin[o + (size_t)(2 * k) * 1024],
                                d_hfin[o + (size_t)(2 * k + 1) * 1024]);
                h2[k] = fma2_(h2[k], a128[k], fin);
            }
        }
        for (int step = 0; step < CHL; step++) {
            int ls = CHL - 1 - step;
            int t = t0 + ls;
            float x = __bfloat162float(xs[(size_t)t * (2 * DI)]);
            u64 xd = pack2(x, x);
            u64 yp = 0ull;
#pragma unroll
            for (int k = 0; k < 8; k++) {
                h2[k] = fma2_(h2[k], A2[k], fma2_(Be2[k], xd, 0ull));
                yp = fma2_(h2[k], C2[k], yp);
            }
            float2 f = unpack2(yp);
            float yb = f.x + f.y;
            float yf = __bfloat162float(yfs[ls * 256 + tid]);
            float g = __bfloat162float(gs[(size_t)t * (2 * DI)]);
            float sig = 1.f / (1.f + expf(-g));
            uo[(size_t)t * DI] = __float2bfloat16((yf + yb) * g * sig);
        }
    }
}

// ---------------- launch ----------------
extern "C" void kernel_launch(void* const* d_in, const int* in_sizes, int n_in,
                              void* d_out, int out_size) {
    const float* x_V        = (const float*)d_in[0];
    const float* x_I        = (const float*)d_in[1];
    const float* conv_red_w = (const float*)d_in[2];
    const float* bn_red_g   = (const float*)d_in[3];
    const float* bn_red_b   = (const float*)d_in[4];
    const float* bn_red_m   = (const float*)d_in[5];
    const float* bn_red_v   = (const float*)d_in[6];
    const float* conv_res_w = (const float*)d_in[7];
    const float* bn_res_g   = (const float*)d_in[8];
    const float* bn_res_b   = (const float*)d_in[9];
    const float* bn_res_m   = (const float*)d_in[10];
    const float* bn_res_v   = (const float*)d_in[11];
    const float* lam_w1     = (const float*)d_in[12];
    const float* lam_b1     = (const float*)d_in[13];
    const float* lam_w2     = (const float*)d_in[14];
    const float* lam_b2     = (const float*)d_in[15];
    const float* in_w[2]    = {(const float*)d_in[16], (const float*)d_in[23]};
    const float* out_w[2]   = {(const float*)d_in[17], (const float*)d_in[24]};
    const float* A_log[2]   = {(const float*)d_in[18], (const float*)d_in[25]};
    const float* Bmat[2]    = {(const float*)d_in[19], (const float*)d_in[26]};
    const float* Cmat[2]    = {(const float*)d_in[20], (const float*)d_in[27]};
    const float* ln_g[2]    = {(const float*)d_in[21], (const float*)d_in[28]};
    const float* ln_b[2]    = {(const float*)d_in[22], (const float*)d_in[29]};
    const float* gate       = (const float*)d_in[30];

    bf16 *XT, *SEQ, *XN, *XP, *U, *WT, *WC, *CRW, *CRSW, *INW;
    float *WCP;
    cudaGetSymbolAddress((void**)&XT,   d_xt);
    cudaGetSymbolAddress((void**)&SEQ,  d_seq);
    cudaGetSymbolAddress((void**)&XN,   d_xn);
    cudaGetSymbolAddress((void**)&XP,   d_xp);
    cudaGetSymbolAddress((void**)&U,    d_u);
    cudaGetSymbolAddress((void**)&WT,   d_wt);
    cudaGetSymbolAddress((void**)&WC,   d_wc);
    cudaGetSymbolAddress((void**)&WCP,  d_wcp);
    cudaGetSymbolAddress((void**)&CRW,  d_crw);
    cudaGetSymbolAddress((void**)&CRSW, d_crsw);
    cudaGetSymbolAddress((void**)&INW,  d_inw);

    cudaFuncSetAttribute(tgemm<0>, cudaFuncAttributeMaxDynamicSharedMemorySize, TG_SMEM);
    cudaFuncSetAttribute(tgemm<1>, cudaFuncAttributeMaxDynamicSharedMemorySize, TG_SMEM);
    cudaFuncSetAttribute(tgemm<2>, cudaFuncAttributeMaxDynamicSharedMemorySize, TG_SMEM);
    cudaFuncSetAttribute(tgemm<3>, cudaFuncAttributeMaxDynamicSharedMemorySize, TG_SMEM);
    cudaFuncSetAttribute(scan_pass3m, cudaFuncAttributeMaxDynamicSharedMemorySize, 65536);

    // 0. mega prep
    mega_prep<<<NB_PREP + NB_TIN + NB_TW, 256>>>(
        conv_red_w, conv_res_w, in_w[0], in_w[1], x_V, x_I, out_w[0], out_w[1]);

    // 1. Wc split-K x4 (reduce folded into poolln)
    tgemm<0><<<dim3(DI / 128, CIN / 128, 8), 128, TG_SMEM>>>(
        CRSW, CRSW, WT, WT + (size_t)DI * DM, WCP, CIN, DI, DM / 4, DM, DM, 4,
        (long long)CIN * DI, nullptr, nullptr, nullptr, nullptr,
        nullptr, nullptr, nullptr);

    // 2. conv_red + BN + ReLU -> bf16 d_seq
    tgemm<1><<<dim3(DM / 128, NTOK / 128, 2), 128, TG_SMEM>>>(
        XT, XT + (size_t)NTOK * CIN, CRW, CRW, SEQ, NTOK, DM, CIN, CIN, CIN, 1,
        (long long)NTOK * DM, bn_red_g, bn_red_b, bn_red_m, bn_red_v,
        nullptr, nullptr, nullptr);

    // 3. pool + layernorm + wc_reduce, then lambda
    poolln<<<2 * NTOK + 128 + NB_WCR, 128>>>(ln_g[0], ln_b[0], ln_g[1], ln_b[1]);
    lambda_kernel<<<4, 128>>>(lam_w1, lam_b1, lam_w2, lam_b2);

    // 4. in_proj (bf16 out)
    tgemm<2><<<dim3(2 * DI / 128, NTOK / 128, 2), 128, TG_SMEM>>>(
        XN, XN + (size_t)NTOK * DM, INW, INW + (size_t)2 * DI * DM, XP, NTOK, 2 * DI,
        DM, DM, DM, 1, (long long)NTOK * 2 * DI, nullptr, nullptr, nullptr, nullptr,
        nullptr, nullptr, nullptr);

    // 5. scan
    scan_pass1<<<448, 256>>>(A_log[0], Bmat[0], A_log[1], Bmat[1]);
    scan_pass3m<<<256, 256, 65536>>>(A_log[0], Bmat[0], Cmat[0],
                                     A_log[1], Bmat[1], Cmat[1]);

    // 6. fused out_proj + conv_res + BN + residual + gate -> output
    tgemm<3><<<dim3(CIN / 128, NTOK / 128, 2), 128, TG_SMEM>>>(
        U, U + (size_t)NTOK * DI, WC, WC + (size_t)CIN * DI, (float*)d_out, NTOK, CIN,
        DI, DI, DI, 1, 0LL, bn_res_g, bn_res_b, bn_res_m, bn_res_v,
        x_V, x_I, gate);
}

// round 14
// speedup vs baseline: 4.9157x; 1.0149x over previous
#include <cuda_runtime.h>
#include <cuda_bf16.h>
#include <math.h>
#include <stdint.h>

#define NS   2
#define BSZ  4
#define LSEQ 1024
#define NTOK 4096
#define DM   512
#define DI   1024
#define DS   16
#define CIN  256
#define NCH  8
#define CHL  128

typedef __nv_bfloat16 bf16;
typedef unsigned long long u64;

// ---------------- scratch ----------------
__device__ bf16  d_xt[NS][NTOK * CIN];
__device__ bf16  d_seq[NS][NTOK * DM];
__device__ float d_ppart[NS][32][DM];          // per-128-token-chunk column sums
__device__ float d_lam[BSZ * 2];
__device__ bf16  d_xn[NS][NTOK * DM];
__device__ bf16  d_xp[NS][NTOK * 2 * DI];
__device__ bf16  d_u[NS][NTOK * DI];
__device__ bf16  d_wt[NS][DI * DM];
__device__ bf16  d_wc[NS][CIN * DI];
__device__ float d_wcp[8][CIN * DI];
__device__ bf16  d_crw[DM * CIN];
__device__ bf16  d_crsw[CIN * DM];
__device__ bf16  d_inw[NS][2 * DI * DM];
__device__ float d_hfin[NS * 2 * BSZ * NCH * DS * 1024];

// ---------------- PTX helpers ----------------
__device__ __forceinline__ uint32_t smem_u32(const void* p) {
    uint32_t a;
    asm("{ .reg .u64 t; cvta.to.shared.u64 t, %1; cvt.u32.u64 %0, t; }" : "=r"(a) : "l"(p));
    return a;
}
#define CP_ASYNC16(sp, gp) \
    asm volatile("cp.async.cg.shared.global [%0], [%1], 16;" :: "r"(sp), "l"(gp) : "memory")
#define CP_COMMIT() asm volatile("cp.async.commit_group;" ::: "memory")
#define CP_WAIT2()  asm volatile("cp.async.wait_group 2;" ::: "memory")

#define LDSM_X4(r0, r1, r2, r3, addr) \
    asm volatile("ldmatrix.sync.aligned.m8n8.x4.shared.b16 {%0,%1,%2,%3}, [%4];" \
                 : "=r"(r0), "=r"(r1), "=r"(r2), "=r"(r3) : "r"(addr))

#define MMA_BF16(d, a, b) \
    asm volatile("mma.sync.aligned.m16n8k16.row.col.f32.bf16.bf16.f32 " \
                 "{%0,%1,%2,%3}, {%4,%5,%6,%7}, {%8,%9}, {%0,%1,%2,%3};" \
                 : "+f"((d)[0]), "+f"((d)[1]), "+f"((d)[2]), "+f"((d)[3]) \
                 : "r"((a)[0]), "r"((a)[1]), "r"((a)[2]), "r"((a)[3]), \
                   "r"((b)[0]), "r"((b)[1]))

__device__ __forceinline__ u64 fma2_(u64 a, u64 b, u64 c) {
    u64 d;
    asm("fma.rn.f32x2 %0, %1, %2, %3;" : "=l"(d) : "l"(a), "l"(b), "l"(c));
    return d;
}
__device__ __forceinline__ u64 pack2(float lo, float hi) {
    u64 r;
    asm("mov.b64 %0, {%1, %2};" : "=l"(r) : "f"(lo), "f"(hi));
    return r;
}
__device__ __forceinline__ float2 unpack2(u64 v) {
    float2 f;
    asm("mov.b64 {%0, %1}, %2;" : "=f"(f.x), "=f"(f.y) : "l"(v));
    return f;
}

// ---------------- bf16 mma.sync GEMM: CTA 128x128, 128 threads, 2 CTAs/SM ----------------
#define TG_PITCH   80
#define TG_MATA    (128 * TG_PITCH)
#define TG_STAGE_B (2 * TG_MATA)
#define TG_NST     4
#define TG_SMEM    (TG_NST * TG_STAGE_B)

// EPI: 0 plain fp32, 1 BN+ReLU bf16 out + fused column pool, 2 bf16 out,
//      3 fused BN+residual+gate transposed out
template <int EPI>
__global__ void __launch_bounds__(128, 2)
tgemm(const bf16* __restrict__ A0, const bf16* __restrict__ A1,
      const bf16* __restrict__ B0, const bf16* __restrict__ B1,
      void* __restrict__ Cv, int M, int N, int K, int lda, int ldb, int zdiv,
      long long sCz,
      const float* __restrict__ eg, const float* __restrict__ eb,
      const float* __restrict__ em, const float* __restrict__ ev,
      const float* __restrict__ RX0, const float* __restrict__ RX1,
      const float* __restrict__ gp) {
    extern __shared__ float smf[];
    const uint32_t sbase = smem_u32(smf);

    const int tid  = threadIdx.x;
    const int lane = tid & 31;
    const int wid  = tid >> 5;
    const int z = blockIdx.z;
    const int zs = z / zdiv, kc = z % zdiv;
    const bf16* __restrict__ A = (zs ? A1 : A0) + (size_t)kc * K;
    const bf16* __restrict__ B = (zs ? B1 : B0) + (size_t)kc * K;
    const int m0 = blockIdx.y * 128, n0 = blockIdx.x * 128;
    const int wm = (wid >> 1) * 64;
    const int wn = (wid & 1) * 64;

    const int lr = tid >> 2;
    const int lc = tid & 3;
    const int T = K / 32;

    auto load_stage = [&](int t) {
        if (t < T) {
            const int k0 = t * 32;
            uint32_t dst = sbase + (t & 3) * TG_STAGE_B;
#pragma unroll
            for (int i = 0; i < 4; i++) {
                int m = lr + i * 32;
                CP_ASYNC16(dst + m * TG_PITCH + lc * 16,
                           A + (size_t)(m0 + m) * lda + k0 + lc * 8);
            }
            dst += TG_MATA;
#pragma unroll
            for (int i = 0; i < 4; i++) {
                int n = lr + i * 32;
                CP_ASYNC16(dst + n * TG_PITCH + lc * 16,
                           B + (size_t)(n0 + n) * ldb + k0 + lc * 8);
            }
        }
        CP_COMMIT();
    };

    float c[4][8][4];
#pragma unroll
    for (int mt = 0; mt < 4; mt++)
#pragma unroll
        for (int nt = 0; nt < 8; nt++)
#pragma unroll
            for (int q = 0; q < 4; q++) c[mt][nt][q] = 0.f;

    load_stage(0);
    load_stage(1);
    load_stage(2);

    const int l15   = lane & 15;
    const int lhiA  = (lane >> 4) * 16;
    const int bnrow = (lane & 7) + ((lane >> 4) << 3);
    const int bkoff = ((lane >> 3) & 1) * 16;

    for (int t = 0; t < T; t++) {
        CP_WAIT2();
        __syncthreads();
        load_stage(t + 3);
        const uint32_t aB = sbase + (t & 3) * TG_STAGE_B;
        const uint32_t bB = aB + TG_MATA;
#pragma unroll
        for (int kk = 0; kk < 2; kk++) {
            uint32_t a[4][4], b[8][2];
#pragma unroll
            for (int mt = 0; mt < 4; mt++) {
                uint32_t addr = aB + (wm + mt * 16 + l15) * TG_PITCH + kk * 32 + lhiA;
                LDSM_X4(a[mt][0], a[mt][1], a[mt][2], a[mt][3], addr);
            }
#pragma unroll
            for (int nh = 0; nh < 4; nh++) {
                uint32_t addr = bB + (wn + nh * 16 + bnrow) * TG_PITCH + kk * 32 + bkoff;
                uint32_t r0, r1, r2, r3;
                LDSM_X4(r0, r1, r2, r3, addr);
                b[nh * 2][0] = r0; b[nh * 2][1] = r1;
                b[nh * 2 + 1][0] = r2; b[nh * 2 + 1][1] = r3;
            }
#pragma unroll
            for (int mt = 0; mt < 4; mt++)
#pragma unroll
                for (int nt = 0; nt < 8; nt++)
                    MMA_BF16(c[mt][nt], a[mt], b[nt]);
        }
    }

    const int gid = lane >> 2;
    const int tig = lane & 3;
    float sg = 0.f;
    if (EPI == 3) sg = 1.f / (1.f + expf(-gp[0]));
    float cs[16];
    if (EPI == 1) {
#pragma unroll
        for (int i = 0; i < 16; i++) cs[i] = 0.f;
    }
#pragma unroll
    for (int mt = 0; mt < 4; mt++) {
        const int r0 = m0 + wm + mt * 16 + gid;
#pragma unroll
        for (int nt = 0; nt < 8; nt++) {
            const int col = n0 + wn + nt * 8 + tig * 2;
            float v0 = c[mt][nt][0], v1 = c[mt][nt][1];
            float v2 = c[mt][nt][2], v3 = c[mt][nt][3];
            if (EPI == 1) {
                float s0 = eg[col] * rsqrtf(ev[col] + 1e-5f);
                float h0 = eb[col] - em[col] * s0;
                float s1 = eg[col + 1] * rsqrtf(ev[col + 1] + 1e-5f);
                float h1 = eb[col + 1] - em[col + 1] * s1;
                v0 = fmaxf(v0 * s0 + h0, 0.f);
                v1 = fmaxf(v1 * s1 + h1, 0.f);
                v2 = fmaxf(v2 * s0 + h0, 0.f);
                v3 = fmaxf(v3 * s1 + h1, 0.f);
                cs[nt * 2]     += v0 + v2;
                cs[nt * 2 + 1] += v1 + v3;
                bf16* Cb = (bf16*)Cv + (size_t)z * sCz;
                *(__nv_bfloat162*)&Cb[(size_t)r0 * N + col] =
                    __floats2bfloat162_rn(v0, v1);
                *(__nv_bfloat162*)&Cb[(size_t)(r0 + 8) * N + col] =
                    __floats2bfloat162_rn(v2, v3);
            } else if (EPI == 2) {
                bf16* Cb = (bf16*)Cv + (size_t)z * sCz;
                *(__nv_bfloat162*)&Cb[(size_t)r0 * N + col] =
                    __floats2bfloat162_rn(v0, v1);
                *(__nv_bfloat162*)&Cb[(size_t)(r0 + 8) * N + col] =
                    __floats2bfloat162_rn(v2, v3);
            } else if (EPI == 3) {
                float s0 = eg[col] * rsqrtf(ev[col] + 1e-5f);
                float h0 = eb[col] - em[col] * s0;
                float s1 = eg[col + 1] * rsqrtf(ev[col + 1] + 1e-5f);
                float h1 = eb[col + 1] - em[col + 1] * s1;
                const float* xin = zs ? RX1 : RX0;
                float* outp = (float*)Cv + (size_t)zs * BSZ * CIN * LSEQ;
                int b = r0 >> 10, hw = r0 & 1023;
                size_t p0 = ((size_t)b * CIN + col) * LSEQ + hw;
                size_t p1 = p0 + LSEQ;
                outp[p0]     = xin[p0]     + sg * (v0 * s0 + h0);
                outp[p1]     = xin[p1]     + sg * (v1 * s1 + h1);
                outp[p0 + 8] = xin[p0 + 8] + sg * (v2 * s0 + h0);
                outp[p1 + 8] = xin[p1 + 8] + sg * (v3 * s1 + h1);
            } else {
                float* Cf = (float*)Cv + (size_t)z * sCz;
                *(float2*)&Cf[(size_t)r0 * N + col]       = make_float2(v0, v1);
                *(float2*)&Cf[(size_t)(r0 + 8) * N + col] = make_float2(v2, v3);
            }
        }
    }

    if (EPI == 1) {
        // reduce column sums over gid lanes (stride-4 butterfly)
#pragma unroll
        for (int off = 4; off <= 16; off <<= 1)
#pragma unroll
            for (int i = 0; i < 16; i++)
                cs[i] += __shfl_xor_sync(0xffffffffu, cs[i], off);
        __syncthreads();                 // stage smem dead; reuse for column exchange
        float* scol = smf;               // 128 floats
        if (wid < 2 && lane < 4) {
#pragma unroll
            for (int nt = 0; nt < 8; nt++) {
                scol[wn + nt * 8 + lane * 2]     = cs[nt * 2];
                scol[wn + nt * 8 + lane * 2 + 1] = cs[nt * 2 + 1];
            }
        }
        __syncthreads();
        if (wid >= 2 && lane < 4) {
#pragma unroll
            for (int nt = 0; nt < 8; nt++) {
                scol[wn + nt * 8 + lane * 2]     += cs[nt * 2];
                scol[wn + nt * 8 + lane * 2 + 1] += cs[nt * 2 + 1];
            }
        }
        __syncthreads();
        d_ppart[zs][m0 >> 7][n0 + tid] = scol[tid];
    }
}

// ---------------- mega prep ----------------
#define PREP_N (DM * CIN + CIN * DM + 2 * (2 * DI * DM))
#define NB_PREP (PREP_N / 256)
#define NB_TIN  (32 * 8 * 8)
#define NB_TW   (32 * 16 * 2)
__global__ void __launch_bounds__(256)
mega_prep(const float* __restrict__ crw, const float* __restrict__ crsw,
          const float* __restrict__ iw0, const float* __restrict__ iw1,
          const float* __restrict__ x0, const float* __restrict__ x1,
          const float* __restrict__ ow0, const float* __restrict__ ow1) {
    int bid = blockIdx.x;
    int tid = threadIdx.x;
    if (bid < NB_PREP) {
        int i = bid * 256 + tid;
        const int n1 = DM * CIN, n2 = n1 + CIN * DM, n3 = n2 + 2 * DI * DM;
        if (i < n1)       d_crw[i]           = __float2bfloat16(crw[i]);
        else if (i < n2)  d_crsw[i - n1]     = __float2bfloat16(crsw[i - n1]);
        else if (i < n3)  d_inw[0][i - n2]   = __float2bfloat16(iw0[i - n2]);
        else              d_inw[1][i - n3]   = __float2bfloat16(iw1[i - n3]);
    } else if (bid < NB_PREP + NB_TIN) {
        __shared__ float tile[32][33];
        int q = bid - NB_PREP;
        int zc = q >> 8;
        int s = zc >> 2, b = zc & 3;
        int rem = q & 255;
        int c0 = (rem >> 5) * 32, hw0 = (rem & 31) * 32;
        const float* x = s ? x1 : x0;
        int tx = tid & 31, ty = tid >> 5;
#pragma unroll
        for (int r = 0; r < 4; r++) {
            int row = ty + r * 8;
            tile[row][tx] = x[((size_t)b * CIN + (c0 + row)) * LSEQ + hw0 + tx];
        }
        __syncthreads();
#pragma unroll
        for (int r = 0; r < 4; r++) {
            int row = ty + r * 8;
            d_xt[s][((size_t)b * LSEQ + hw0 + row) * CIN + c0 + tx] =
                __float2bfloat16(tile[tx][row]);
        }
    } else {
        __shared__ float tile[32][33];
        int q = bid - NB_PREP - NB_TIN;
        int s = q >> 9;
        int rem = q & 511;
        int r0 = (rem >> 5) * 32, c0 = (rem & 31) * 32;
        const float* w = s ? ow1 : ow0;
        int tx = tid & 31, ty = tid >> 5;
#pragma unroll
        for (int r = 0; r < 4; r++) {
            int row = ty + r * 8;
            tile[row][tx] = w[(size_t)(r0 + row) * DI + c0 + tx];
        }
        __syncthreads();
#pragma unroll
        for (int r = 0; r < 4; r++) {
            int row = ty + r * 8;
            d_wt[s][(size_t)(c0 + row) * DM + r0 + tx] = __float2bfloat16(tile[tx][row]);
        }
    }
}

// ---------------- layernorm + wc_reduce (pool now fused in conv_red) ----------------
#define NB_WCR (2 * CIN * DI / 128)
__global__ void __launch_bounds__(128)
poolln(const float* __restrict__ g0, const float* __restrict__ b0,
       const float* __restrict__ g1, const float* __restrict__ b1) {
    int bid = blockIdx.x;
    int t = threadIdx.x;
    if (bid < 2 * NTOK) {
        int s = bid >> 12;
        int n = bid & (NTOK - 1);
        const float* g = s ? g1 : g0;
        const float* b = s ? b1 : b0;
        const __nv_bfloat162* src = (const __nv_bfloat162*)(d_seq[s] + (size_t)n * DM);
        float2 p0 = __bfloat1622float2(src[2 * t]);
        float2 p1 = __bfloat1622float2(src[2 * t + 1]);
        float4 v = make_float4(p0.x, p0.y, p1.x, p1.y);
        float sm = v.x + v.y + v.z + v.w;
        float sq = v.x * v.x + v.y * v.y + v.z * v.z + v.w * v.w;
#pragma unroll
        for (int o = 16; o; o >>= 1) {
            sm += __shfl_xor_sync(0xffffffffu, sm, o);
            sq += __shfl_xor_sync(0xffffffffu, sq, o);
        }
        __shared__ float ss[4], sqs[4];
        int w = t >> 5, ln = t & 31;
        if (ln == 0) { ss[w] = sm; sqs[w] = sq; }
        __syncthreads();
        sm = ss[0] + ss[1] + ss[2] + ss[3];
        sq = sqs[0] + sqs[1] + sqs[2] + sqs[3];
        float mu = sm * (1.f / DM);
        float var = sq * (1.f / DM) - mu * mu;
        float inv = rsqrtf(var + 1e-5f);
        float4 gg = ((const float4*)g)[t];
        float4 bb = ((const float4*)b)[t];
        __nv_bfloat162* dst = (__nv_bfloat162*)(d_xn[s] + (size_t)n * DM);
        dst[2 * t]     = __floats2bfloat162_rn((v.x - mu) * inv * gg.x + bb.x,
                                               (v.y - mu) * inv * gg.y + bb.y);
        dst[2 * t + 1] = __floats2bfloat162_rn((v.z - mu) * inv * gg.z + bb.z,
                                               (v.w - mu) * inv * gg.w + bb.w);
    } else {
        int idx = (bid - 2 * NTOK) * 128 + t;
        int s = idx >> 18;
        int j = idx & (CIN * DI - 1);
        float v = d_wcp[s * 4 + 0][j] + d_wcp[s * 4 + 1][j] +
                  d_wcp[s * 4 + 2][j] + d_wcp[s * 4 + 3][j];
        d_wc[s][j] = __float2bfloat16(v);
    }
}

// ---------------- lambda predictor ----------------
__global__ void lambda_kernel(const float* __restrict__ w1, const float* __restrict__ b1,
                              const float* __restrict__ w2, const float* __restrict__ b2) {
    int b = blockIdx.x, j = threadIdx.x;
    __shared__ float pooled[2 * DM];
    for (int idx = j; idx < 2 * DM; idx += 128) {
        int s = idx >> 9, d = idx & (DM - 1);
        float acc = 0.f;
#pragma unroll
        for (int c = 0; c < 8; c++) acc += d_ppart[s][b * 8 + c][d];
        pooled[idx] = acc * (1.0f / LSEQ);
    }
    __syncthreads();
    const float* w = w1 + (size_t)j * (2 * DM);
    float acc = b1[j];
    for (int c = 0; c < DM; c++) acc += pooled[c] * w[c];
    for (int c = 0; c < DM; c++) acc += pooled[DM + c] * w[DM + c];
    __shared__ float h1[128];
    h1[j] = fmaxf(acc, 0.f);
    __syncthreads();
    if (j == 0) {
        float l0 = b2[0], l1 = b2[1];
        for (int c = 0; c < 128; c++) { l0 += h1[c] * w2[c]; l1 += h1[c] * w2[128 + c]; }
        float mx = fmaxf(l0, l1);
        float e0 = expf(l0 - mx), e1 = expf(l1 - mx);
        float inv = 1.f / (e0 + e1);
        d_lam[b * 2 + 0] = e0 * inv;
        d_lam[b * 2 + 1] = e1 * inv;
    }
}

// ================= chunked parallel scan =================
__device__ __forceinline__ size_t hf_off(int s, int dir, int b, int c, int i) {
    return (((((size_t)s * 2 + dir) * 4 + b) * NCH + c) * DS) * 1024 + i;
}

__global__ void __launch_bounds__(256)
scan_pass1(const float* __restrict__ VA, const float* __restrict__ VB,
           const float* __restrict__ IA, const float* __restrict__ IB) {
    int idx = blockIdx.x * 256 + threadIdx.x;
    int i   = idx & 1023;
    int r   = idx >> 10;
    int c   = r % 7;
    int r2  = r / 7;
    int b   = r2 & 3;
    int dir = (r2 >> 2) & 1;
    int s   = (r2 >> 3) & 1;

    const float* Alog = s ? IA : VA;
    const float* Bown = s ? IB : VB;
    const float* Both = s ? VB : IB;
    float w0 = 0.5f * d_lam[b * 2 + 0];
    float w1 = 0.5f * d_lam[b * 2 + 1];

    u64 A2[8], Be2[8], h2[8];
#pragma unroll
    for (int k = 0; k < 8; k++) {
        float a0 = fminf(fmaxf(-expf(Alog[i * DS + 2 * k]),     -10.f), -0.01f);
        float a1 = fminf(fmaxf(-expf(Alog[i * DS + 2 * k + 1]), -10.f), -0.01f);
        A2[k]  = pack2(a0, a1);
        Be2[k] = pack2(w0 * Bown[i * DS + 2 * k]     + w1 * Both[i * DS + 2 * k],
                       w0 * Bown[i * DS + 2 * k + 1] + w1 * Both[i * DS + 2 * k + 1]);
        h2[k] = 0ull;
    }

    const bf16* xs = d_xp[s] + (size_t)b * LSEQ * (2 * DI) + i;
    int t  = dir ? (LSEQ - 1 - c * CHL) : c * CHL;
    int dt = dir ? -1 : 1;

    for (int step = 0; step < CHL; step++, t += dt) {
        float x = __bfloat162float(xs[(size_t)t * (2 * DI)]);
        u64 xd = pack2(x, x);
#pragma unroll
        for (int k = 0; k < 8; k++)
            h2[k] = fma2_(h2[k], A2[k], fma2_(Be2[k], xd, 0ull));
    }

    size_t o0 = hf_off(s, dir, b, c, i);
#pragma unroll
    for (int k = 0; k < 8; k++) {
        float2 f = unpack2(h2[k]);
        d_hfin[o0 + (size_t)(2 * k) * 1024]     = f.x;
        d_hfin[o0 + (size_t)(2 * k + 1) * 1024] = f.y;
    }
}

__global__ void __launch_bounds__(256, 2)
scan_pass3m(const float* __restrict__ VA, const float* __restrict__ VB,
            const float* __restrict__ VC, const float* __restrict__ IA,
            const float* __restrict__ IB, const float* __restrict__ IC) {
    extern __shared__ bf16 yfs[];
    int tid = threadIdx.x;
    int idx = blockIdx.x * 256 + tid;
    int i   = idx & 1023;
    int c   = (idx >> 10) & 7;
    int b   = (idx >> 13) & 3;
    int s   = (idx >> 14) & 1;

    const float* Alog = s ? IA : VA;
    const float* Bown = s ? IB : VB;
    const float* Both = s ? VB : IB;
    const float* Cp   = s ? IC : VC;
    float w0 = 0.5f * d_lam[b * 2 + 0];
    float w1 = 0.5f * d_lam[b * 2 + 1];

    u64 A2[8], Be2[8], C2[8], h2[8];
#pragma unroll
    for (int k = 0; k < 8; k++) {
        float a0 = fminf(fmaxf(-expf(Alog[i * DS + 2 * k]),     -10.f), -0.01f);
        float a1 = fminf(fmaxf(-expf(Alog[i * DS + 2 * k + 1]), -10.f), -0.01f);
        A2[k]  = pack2(a0, a1);
        Be2[k] = pack2(w0 * Bown[i * DS + 2 * k]     + w1 * Both[i * DS + 2 * k],
                       w0 * Bown[i * DS + 2 * k + 1] + w1 * Both[i * DS + 2 * k + 1]);
        C2[k]  = pack2(Cp[i * DS + 2 * k], Cp[i * DS + 2 * k + 1]);
    }

    u64 a128[8];
#pragma unroll
    for (int k = 0; k < 8; k++) {
        u64 a = A2[k];
#pragma unroll
        for (int q = 0; q < 7; q++) a = fma2_(a, a, 0ull);
        a128[k] = a;
    }

    const bf16* xs = d_xp[s] + (size_t)b * LSEQ * (2 * DI) + i;
    const bf16* gs = xs + DI;
    bf16* uo = d_u[s] + (size_t)b * LSEQ * DI + i;
    const int t0 = c * CHL;
    const int cb = NCH - 1 - c;

    {
#pragma unroll
        for (int k = 0; k < 8; k++) h2[k] = 0ull;
        for (int cc = 0; cc < c; cc++) {
            size_t o = hf_off(s, 0, b, cc, i);
#pragma unroll
            for (int k = 0; k < 8; k++) {
                u64 fin = pack2(d_hfin[o + (size_t)(2 * k) * 1024],
                                d_hfin[o + (size_t)(2 * k + 1) * 1024]);
                h2[k] = fma2_(h2[k], a128[k], fin);
            }
        }
        for (int step = 0; step < CHL; step++) {
            float x = __bfloat162float(xs[(size_t)(t0 + step) * (2 * DI)]);
            u64 xd = pack2(x, x);
            u64 yp = 0ull;
#pragma unroll
            for (int k = 0; k < 8; k++) {
                h2[k] = fma2_(h2[k], A2[k], fma2_(Be2[k], xd, 0ull));
                yp = fma2_(h2[k], C2[k], yp);
            }
            float2 f = unpack2(yp);
            yfs[step * 256 + tid] = __float2bfloat16(f.x + f.y);
        }
    }
    {
#pragma unroll
        for (int k = 0; k < 8; k++) h2[k] = 0ull;
        for (int cc = 0; cc < cb; cc++) {
            size_t o = hf_off(s, 1, b, cc, i);
#pragma unroll
            for (int k = 0; k < 8; k++) {
                u64 fin = pack2(d_hfin[o + (size_t)(2 * k) * 1024],
                                d_hfin[o + (size_t)(2 * k + 1) * 1024]);
                h2[k] = fma2_(h2[k], a128[k], fin);
            }
        }
        for (int step = 0; step < CHL; step++) {
            int ls = CHL - 1 - step;
            int t = t0 + ls;
            float x = __bfloat162float(xs[(size_t)t * (2 * DI)]);
            u64 xd = pack2(x, x);
            u64 yp = 0ull;
#pragma unroll
            for (int k = 0; k < 8; k++) {
                h2[k] = fma2_(h2[k], A2[k], fma2_(Be2[k], xd, 0ull));
                yp = fma2_(h2[k], C2[k], yp);
            }
            float2 f = unpack2(yp);
            float yb = f.x + f.y;
            float yf = __bfloat162float(yfs[ls * 256 + tid]);
            float g = __bfloat162float(gs[(size_t)t * (2 * DI)]);
            float sig = 1.f / (1.f + expf(-g));
            uo[(size_t)t * DI] = __float2bfloat16((yf + yb) * g * sig);
        }
    }
}

// ---------------- launch ----------------
extern "C" void kernel_launch(void* const* d_in, const int* in_sizes, int n_in,
                              void* d_out, int out_size) {
    const float* x_V        = (const float*)d_in[0];
    const float* x_I        = (const float*)d_in[1];
    const float* conv_red_w = (const float*)d_in[2];
    const float* bn_red_g   = (const float*)d_in[3];
    const float* bn_red_b   = (const float*)d_in[4];
    const float* bn_red_m   = (const float*)d_in[5];
    const float* bn_red_v   = (const float*)d_in[6];
    const float* conv_res_w = (const float*)d_in[7];
    const float* bn_res_g   = (const float*)d_in[8];
    const float* bn_res_b   = (const float*)d_in[9];
    const float* bn_res_m   = (const float*)d_in[10];
    const float* bn_res_v   = (const float*)d_in[11];
    const float* lam_w1     = (const float*)d_in[12];
    const float* lam_b1     = (const float*)d_in[13];
    const float* lam_w2     = (const float*)d_in[14];
    const float* lam_b2     = (const float*)d_in[15];
    const float* in_w[2]    = {(const float*)d_in[16], (const float*)d_in[23]};
    const float* out_w[2]   = {(const float*)d_in[17], (const float*)d_in[24]};
    const float* A_log[2]   = {(const float*)d_in[18], (const float*)d_in[25]};
    const float* Bmat[2]    = {(const float*)d_in[19], (const float*)d_in[26]};
    const float* Cmat[2]    = {(const float*)d_in[20], (const float*)d_in[27]};
    const float* ln_g[2]    = {(const float*)d_in[21], (const float*)d_in[28]};
    const float* ln_b[2]    = {(const float*)d_in[22], (const float*)d_in[29]};
    const float* gate       = (const float*)d_in[30];

    bf16 *XT, *SEQ, *XN, *XP, *U, *WT, *WC, *CRW, *CRSW, *INW;
    float *WCP;
    cudaGetSymbolAddress((void**)&XT,   d_xt);
    cudaGetSymbolAddress((void**)&SEQ,  d_seq);
    cudaGetSymbolAddress((void**)&XN,   d_xn);
    cudaGetSymbolAddress((void**)&XP,   d_xp);
    cudaGetSymbolAddress((void**)&U,    d_u);
    cudaGetSymbolAddress((void**)&WT,   d_wt);
    cudaGetSymbolAddress((void**)&WC,   d_wc);
    cudaGetSymbolAddress((void**)&WCP,  d_wcp);
    cudaGetSymbolAddress((void**)&CRW,  d_crw);
    cudaGetSymbolAddress((void**)&CRSW, d_crsw);
    cudaGetSymbolAddress((void**)&INW,  d_inw);

    cudaFuncSetAttribute(tgemm<0>, cudaFuncAttributeMaxDynamicSharedMemorySize, TG_SMEM);
    cudaFuncSetAttribute(tgemm<1>, cudaFuncAttributeMaxDynamicSharedMemorySize, TG_SMEM);
    cudaFuncSetAttribute(tgemm<2>, cudaFuncAttributeMaxDynamicSharedMemorySize, TG_SMEM);
    cudaFuncSetAttribute(tgemm<3>, cudaFuncAttributeMaxDynamicSharedMemorySize, TG_SMEM);
    cudaFuncSetAttribute(scan_pass3m, cudaFuncAttributeMaxDynamicSharedMemorySize, 65536);

    // 0. mega prep
    mega_prep<<<NB_PREP + NB_TIN + NB_TW, 256>>>(
        conv_red_w, conv_res_w, in_w[0], in_w[1], x_V, x_I, out_w[0], out_w[1]);

    // 1. Wc split-K x4 (reduce folded into poolln)
    tgemm<0><<<dim3(DI / 128, CIN / 128, 8), 128, TG_SMEM>>>(
        CRSW, CRSW, WT, WT + (size_t)DI * DM, WCP, CIN, DI, DM / 4, DM, DM, 4,
        (long long)CIN * DI, nullptr, nullptr, nullptr, nullptr,
        nullptr, nullptr, nullptr);

    // 2. conv_red + BN + ReLU -> bf16 d_seq (+ fused column pool partials)
    tgemm<1><<<dim3(DM / 128, NTOK / 128, 2), 128, TG_SMEM>>>(
        XT, XT + (size_t)NTOK * CIN, CRW, CRW, SEQ, NTOK, DM, CIN, CIN, CIN, 1,
        (long long)NTOK * DM, bn_red_g, bn_red_b, bn_red_m, bn_red_v,
        nullptr, nullptr, nullptr);

    // 3. layernorm + wc_reduce, then lambda
    poolln<<<2 * NTOK + NB_WCR, 128>>>(ln_g[0], ln_b[0], ln_g[1], ln_b[1]);
    lambda_kernel<<<4, 128>>>(lam_w1, lam_b1, lam_w2, lam_b2);

    // 4. in_proj (bf16 out)
    tgemm<2><<<dim3(2 * DI / 128, NTOK / 128, 2), 128, TG_SMEM>>>(
        XN, XN + (size_t)NTOK * DM, INW, INW + (size_t)2 * DI * DM, XP, NTOK, 2 * DI,
        DM, DM, DM, 1, (long long)NTOK * 2 * DI, nullptr, nullptr, nullptr, nullptr,
        nullptr, nullptr, nullptr);

    // 5. scan
    scan_pass1<<<448, 256>>>(A_log[0], Bmat[0], A_log[1], Bmat[1]);
    scan_pass3m<<<256, 256, 65536>>>(A_log[0], Bmat[0], Cmat[0],
                                     A_log[1], Bmat[1], Cmat[1]);

    // 6. fused out_proj + conv_res + BN + residual + gate -> output
    tgemm<3><<<dim3(CIN / 128, NTOK / 128, 2), 128, TG_SMEM>>>(
        U, U + (size_t)NTOK * DI, WC, WC + (size_t)CIN * DI, (float*)d_out, NTOK, CIN,
        DI, DI, DI, 1, 0LL, bn_res_g, bn_res_b, bn_res_m, bn_res_v,
        x_V, x_I, gate);
}